// round 9
// baseline (speedup 1.0000x reference)
#include <cuda_runtime.h>
#include <cstdint>

// ---------------------------------------------------------------------------
// DGCNN: 2x EdgeConv (dynamic kNN) + final MLP, training-mode BatchNorm.
// R9 = R8 + (a) XOR-swizzled B-fragment reads in dist/gemm (kills the 2-way
// LDS bank conflict at 32B stride), (b) conv2 max-agg fused into the stats
// gather via the max/min monotone-affine trick (one L2 pass instead of two).
// ---------------------------------------------------------------------------

typedef unsigned long long ull;

namespace cfg {
constexpr int BB   = 8;
constexpr int NN_  = 1024;
constexpr int KNN  = 20;
constexpr int NROW  = BB * NN_;        // 8192
constexpr int NEDGE = NROW * KNN;      // 163840

constexpr size_t OFF_D    = 0;
constexpr size_t SZ_D     = (size_t)BB * NN_ * NN_;
constexpr size_t OFF_PQ   = OFF_D + SZ_D;
constexpr size_t SZ_PQ    = (size_t)NROW * 128;
constexpr size_t OFF_PQ2  = OFF_PQ + SZ_PQ;
constexpr size_t SZ_PQ2   = (size_t)NROW * 256;
constexpr size_t OFF_H1   = OFF_PQ2 + SZ_PQ2;
constexpr size_t SZ_H64   = (size_t)NEDGE * 64;
constexpr size_t OFF_H2   = OFF_H1 + SZ_H64;
constexpr size_t OFF_HCAT = OFF_H2 + SZ_H64;
constexpr size_t SZ_HCAT  = (size_t)NROW * 192;
constexpr size_t OFF_X1   = OFF_HCAT + SZ_HCAT;
constexpr size_t SZ_X1    = (size_t)NROW * 64;
constexpr size_t OFF_Y0   = OFF_X1 + SZ_X1;
constexpr size_t SZ_Y0    = (size_t)NROW * 128;
constexpr size_t OFF_SQ   = OFF_Y0 + SZ_Y0;
constexpr size_t SZ_SQ    = (size_t)NROW;
constexpr size_t OFF_WCAT = OFF_SQ + SZ_SQ;
constexpr size_t SZ_WCAT  = 256 * 128;
constexpr size_t OFF_WCAT2= OFF_WCAT + SZ_WCAT;
constexpr size_t SZ_WCAT2 = 64 * 256;
constexpr size_t OFF_WF   = OFF_WCAT2 + SZ_WCAT2;
constexpr size_t SZ_WF    = 64 * 64;
constexpr size_t OFF_BF   = OFF_WF + SZ_WF;
constexpr size_t SZ_BF    = 128;
constexpr size_t SCRATCH_TOTAL = OFF_BF + SZ_BF;
}  // namespace cfg
using namespace cfg;

__device__ float  g_scratch[SCRATCH_TOTAL];
__device__ int    g_knn_idx[NEDGE];
__device__ double g_sum[128];
__device__ double g_sumsq[128];
__device__ float  g_sc[128];
__device__ float  g_cc[128];

// ---------------------------------------------------------------------------
__device__ __forceinline__ ull pack2(float x, float y) {
    ull r; asm("mov.b64 %0, {%1, %2};" : "=l"(r) : "f"(x), "f"(y)); return r;
}
__device__ __forceinline__ void fma2(ull& d, ull a, ull b) {
    asm("fma.rn.f32x2 %0, %1, %2, %0;" : "+l"(d) : "l"(a), "l"(b));
}
__device__ __forceinline__ float2 unpack2(ull v) {
    float2 f; asm("mov.b64 {%0, %1}, %2;" : "=f"(f.x), "=f"(f.y) : "l"(v)); return f;
}

// ---------------------------------------------------------------------------
__global__ void build_wcat1(const float* __restrict__ W0, float* __restrict__ Wcat) {
    int e = blockIdx.x * 256 + threadIdx.x;    // 256*128
    int kk = e >> 7, n = e & 127;
    float v;
    if (n < 64) v = W0[kk * 64 + n] - W0[(kk + 256) * 64 + n];
    else        v = W0[(kk + 256) * 64 + (n - 64)];
    Wcat[e] = v;
}
__global__ void build_wcat2(const float* __restrict__ W0, float* __restrict__ Wcat) {
    int e = blockIdx.x * 256 + threadIdx.x;    // 64*256
    int kk = e >> 8, n = e & 255;
    float v;
    if (n < 128) v = W0[kk * 128 + n] - W0[(kk + 64) * 128 + n];
    else         v = W0[(kk + 64) * 128 + (n - 128)];
    Wcat[e] = v;
}

// ---------------------------------------------------------------------------
template <int C>
__global__ void rowsq_kernel(const float* __restrict__ X, float* __restrict__ sq) {
    int row = blockIdx.x;
    const float* x = X + (size_t)row * C;
    float a = 0.f;
    #pragma unroll
    for (int c = threadIdx.x; c < C; c += 32) { float v = x[c]; a = fmaf(v, v, a); }
    #pragma unroll
    for (int o = 16; o; o >>= 1) a += __shfl_xor_sync(0xffffffffu, a, o);
    if (threadIdx.x == 0) sq[row] = a;
}

// ---------------------------------------------------------------------------
// Distance matrix, symmetric triangular tiles, swizzled B-fragment reads.
// ---------------------------------------------------------------------------
template <int C>
__global__ void __launch_bounds__(256)
dist_kernel(const float* __restrict__ X, const float* __restrict__ sq,
            float* __restrict__ D) {
    __shared__ float As[16][128];
    __shared__ float Bs[16][128];
    int b  = blockIdx.z;
    const float* Xb  = X  + (size_t)b * NN_ * C;
    const float* sqb = sq + (size_t)b * NN_;
    float* Db = D + (size_t)b * NN_ * NN_;

    int rem = blockIdx.x, bi = 0;
    while (rem >= 8 - bi) { rem -= 8 - bi; bi++; }
    int bj = bi + rem;
    int i0 = bi * 128, j0 = bj * 128;

    int t  = threadIdx.x;
    int tx = t & 15, ty = t >> 4;
    int sw4 = ((tx >> 2) & 1) * 4;          // phase swizzle: 0 or 4 floats
    int cb0 = tx * 8 + sw4;                 // first 4 owned cols
    int cb1 = tx * 8 + 4 - sw4;             // other 4 owned cols

    ull acc[8][4];
    #pragma unroll
    for (int i = 0; i < 8; i++)
        #pragma unroll
        for (int j = 0; j < 4; j++) acc[i][j] = 0ull;

    for (int k0 = 0; k0 < C; k0 += 16) {
        #pragma unroll
        for (int it = 0; it < 2; it++) {
            int r  = (t >> 2) + it * 64;
            int kk = (t & 3) * 4;
            float4 va = *reinterpret_cast<const float4*>(&Xb[(size_t)(i0 + r) * C + k0 + kk]);
            As[kk + 0][r] = va.x; As[kk + 1][r] = va.y;
            As[kk + 2][r] = va.z; As[kk + 3][r] = va.w;
            float4 vb = *reinterpret_cast<const float4*>(&Xb[(size_t)(j0 + r) * C + k0 + kk]);
            Bs[kk + 0][r] = vb.x; Bs[kk + 1][r] = vb.y;
            Bs[kk + 2][r] = vb.z; Bs[kk + 3][r] = vb.w;
        }
        __syncthreads();
        #pragma unroll
        for (int kk = 0; kk < 16; kk++) {
            float4 a0 = *reinterpret_cast<const float4*>(&As[kk][ty * 8]);
            float4 a1 = *reinterpret_cast<const float4*>(&As[kk][ty * 8 + 4]);
            float4 b0 = *reinterpret_cast<const float4*>(&Bs[kk][cb0]);   // conflict-free
            float4 b1 = *reinterpret_cast<const float4*>(&Bs[kk][cb1]);   // conflict-free
            ull rb[4] = {pack2(b0.x, b0.y), pack2(b0.z, b0.w),
                         pack2(b1.x, b1.y), pack2(b1.z, b1.w)};
            float ra[8] = {a0.x, a0.y, a0.z, a0.w, a1.x, a1.y, a1.z, a1.w};
            #pragma unroll
            for (int i = 0; i < 8; i++) {
                ull ai = pack2(ra[i], ra[i]);
                #pragma unroll
                for (int j = 0; j < 4; j++) fma2(acc[i][j], ai, rb[j]);
            }
        }
        __syncthreads();
    }
    int cols[8];
    #pragma unroll
    for (int j = 0; j < 8; j++) cols[j] = (j < 4) ? (cb0 + j) : (cb1 + j - 4);
    float sj[8];
    #pragma unroll
    for (int j = 0; j < 8; j++) sj[j] = sqb[j0 + cols[j]];

    float o[8][8];
    #pragma unroll
    for (int i = 0; i < 8; i++) {
        float si = sqb[i0 + ty * 8 + i];
        #pragma unroll
        for (int j = 0; j < 4; j++) {
            float2 u = unpack2(acc[i][j]);
            o[i][j * 2]     = si + sj[j * 2]     - 2.f * u.x;
            o[i][j * 2 + 1] = si + sj[j * 2 + 1] - 2.f * u.y;
        }
    }
    // normal tile write
    #pragma unroll
    for (int i = 0; i < 8; i++) {
        int gi = i0 + ty * 8 + i;
        *reinterpret_cast<float4*>(&Db[(size_t)gi * NN_ + j0 + cb0]) =
            make_float4(o[i][0], o[i][1], o[i][2], o[i][3]);
        *reinterpret_cast<float4*>(&Db[(size_t)gi * NN_ + j0 + cb1]) =
            make_float4(o[i][4], o[i][5], o[i][6], o[i][7]);
    }
    // mirror tile write (transposed)
    if (bi != bj) {
        #pragma unroll
        for (int j = 0; j < 8; j++) {
            int gj = j0 + cols[j];
            float4* dst = reinterpret_cast<float4*>(&Db[(size_t)gj * NN_ + i0 + ty * 8]);
            dst[0] = make_float4(o[0][j], o[1][j], o[2][j], o[3][j]);
            dst[1] = make_float4(o[4][j], o[5][j], o[6][j], o[7][j]);
        }
    }
}

// ---------------------------------------------------------------------------
// Top-20 smallest per row; one warp per row, coalesced float4 loads.
// ---------------------------------------------------------------------------
__global__ void topk_kernel(const float* __restrict__ D, int* __restrict__ idx) {
    int row  = blockIdx.x * 8 + (threadIdx.x >> 5);
    int lane = threadIdx.x & 31;
    const float4* d4 = reinterpret_cast<const float4*>(D + (size_t)row * NN_);
    float v[32];
    #pragma unroll
    for (int q = 0; q < 8; q++) {
        float4 x = d4[lane + 32 * q];
        v[4 * q + 0] = x.x; v[4 * q + 1] = x.y;
        v[4 * q + 2] = x.z; v[4 * q + 3] = x.w;
    }

    for (int s = 0; s < KNN; s++) {
        float m = v[0]; int mq = 0;
        #pragma unroll
        for (int q = 1; q < 32; q++) { if (v[q] < m) { m = v[q]; mq = q; } }
        int gidx = 4 * lane + 128 * (mq >> 2) + (mq & 3);
        float bm = m; int bidx = gidx;
        #pragma unroll
        for (int o = 16; o; o >>= 1) {
            float om = __shfl_xor_sync(0xffffffffu, bm, o);
            int   oi = __shfl_xor_sync(0xffffffffu, bidx, o);
            if (om < bm || (om == bm && oi < bidx)) { bm = om; bidx = oi; }
        }
        if (lane == 0) idx[row * KNN + s] = bidx;
        int wl = (bidx >> 2) & 31;
        if (lane == wl) {
            int slot = 4 * (bidx >> 7) + (bidx & 3);
            #pragma unroll
            for (int q = 0; q < 32; q++) if (q == slot) v[q] = 3.4e38f;
        }
    }
}

// ---------------------------------------------------------------------------
// Generic fp32 GEMM (f32x2, swizzled B when TN==8): C = A@B (+bias,relu)(+stats)
// ---------------------------------------------------------------------------
template <int BM, int BN, int TM, int TN, bool BIAS_RELU, bool STATS>
__global__ void __launch_bounds__(256)
gemm_nodes(const float* __restrict__ A, const float* __restrict__ Bm,
           const float* __restrict__ bias, float* __restrict__ Cmat,
           int M, int N, int K) {
    constexpr int BK = 16;
    constexpr int TX = BN / TN;
    static_assert(TX == 16 && (256 / TX) * TM == BM, "layout");
    __shared__ float smem[BK * (BM + BN)];
    float* As = smem;
    float* Bs = smem + BK * BM;
    int block_m = blockIdx.y * BM, block_n = blockIdx.x * BN;
    int t  = threadIdx.x;
    int tx = t % TX, ty = t / TX;

    int sw4 = (TN == 8) ? ((tx >> 2) & 1) * 4 : 0;
    int cb0 = tx * TN + sw4;
    int cb1 = tx * TN + 4 - sw4;     // only used when TN==8
    int lcol[TN];
    #pragma unroll
    for (int j = 0; j < TN; j++) lcol[j] = (j < 4) ? (cb0 + j) : (cb1 + j - 4);

    ull acc[TM][TN / 2];
    #pragma unroll
    for (int i = 0; i < TM; i++)
        #pragma unroll
        for (int j = 0; j < TN / 2; j++) acc[i][j] = 0ull;

    for (int k0 = 0; k0 < K; k0 += BK) {
        #pragma unroll
        for (int it = 0; it < BM / 64; it++) {
            int r  = (t >> 2) + it * 64;
            int kk = (t & 3) * 4;
            float4 v = *reinterpret_cast<const float4*>(&A[(size_t)(block_m + r) * K + k0 + kk]);
            As[(kk + 0) * BM + r] = v.x; As[(kk + 1) * BM + r] = v.y;
            As[(kk + 2) * BM + r] = v.z; As[(kk + 3) * BM + r] = v.w;
        }
        #pragma unroll
        for (int it = 0; it < BN / 64; it++) {
            int kk = t >> 4;
            int cc = (t & 15) * 4 + it * 64;
            *reinterpret_cast<float4*>(&Bs[kk * BN + cc]) =
                *reinterpret_cast<const float4*>(&Bm[(size_t)(k0 + kk) * N + block_n + cc]);
        }
        __syncthreads();
        #pragma unroll
        for (int kk = 0; kk < BK; kk++) {
            float ra[TM];
            #pragma unroll
            for (int i4 = 0; i4 < TM / 4; i4++) {
                float4 a = *reinterpret_cast<const float4*>(&As[kk * BM + ty * TM + i4 * 4]);
                ra[i4 * 4 + 0] = a.x; ra[i4 * 4 + 1] = a.y;
                ra[i4 * 4 + 2] = a.z; ra[i4 * 4 + 3] = a.w;
            }
            ull rb[TN / 2];
            {
                float4 bq0 = *reinterpret_cast<const float4*>(&Bs[kk * BN + cb0]);
                rb[0] = pack2(bq0.x, bq0.y);
                rb[1] = pack2(bq0.z, bq0.w);
                if (TN == 8) {
                    float4 bq1 = *reinterpret_cast<const float4*>(&Bs[kk * BN + cb1]);
                    rb[2] = pack2(bq1.x, bq1.y);
                    rb[3] = pack2(bq1.z, bq1.w);
                }
            }
            #pragma unroll
            for (int i = 0; i < TM; i++) {
                ull ai = pack2(ra[i], ra[i]);
                #pragma unroll
                for (int j = 0; j < TN / 2; j++) fma2(acc[i][j], ai, rb[j]);
            }
        }
        __syncthreads();
    }

    float bb[TN];
    if (BIAS_RELU) {
        #pragma unroll
        for (int j = 0; j < TN; j++) bb[j] = bias[block_n + lcol[j]];
    }
    float ps[TN], ps2[TN];
    #pragma unroll
    for (int j = 0; j < TN; j++) { ps[j] = 0.f; ps2[j] = 0.f; }

    #pragma unroll
    for (int i = 0; i < TM; i++) {
        float v[TN];
        #pragma unroll
        for (int j = 0; j < TN / 2; j++) {
            float2 u = unpack2(acc[i][j]);
            v[j * 2] = u.x; v[j * 2 + 1] = u.y;
        }
        #pragma unroll
        for (int j = 0; j < TN; j++) {
            if (BIAS_RELU) v[j] = fmaxf(v[j] + bb[j], 0.f);
            if (STATS) { ps[j] += v[j]; ps2[j] = fmaf(v[j], v[j], ps2[j]); }
        }
        int r = block_m + ty * TM + i;
        *reinterpret_cast<float4*>(&Cmat[(size_t)r * N + block_n + cb0]) =
            make_float4(v[0], v[1], v[2], v[3]);
        if (TN == 8)
            *reinterpret_cast<float4*>(&Cmat[(size_t)r * N + block_n + cb1]) =
                make_float4(v[4], v[5], v[6], v[7]);
    }

    if (STATS) {
        #pragma unroll
        for (int j = 0; j < TN; j++) {
            smem[ty * BN + lcol[j]]           = ps[j];
            smem[16 * BN + ty * BN + lcol[j]] = ps2[j];
        }
        __syncthreads();
        if (t < BN) {
            float s = 0.f, s2 = 0.f;
            #pragma unroll
            for (int g = 0; g < 16; g++) { s += smem[g * BN + t]; s2 += smem[16 * BN + g * BN + t]; }
            atomicAdd(&g_sum[t],   (double)s);
            atomicAdd(&g_sumsq[t], (double)s2);
        }
    }
}

// ---------------------------------------------------------------------------
// Layer-1 edge GEMM: A recomputed on the fly (B reads already conflict-free).
// ---------------------------------------------------------------------------
__global__ void __launch_bounds__(256)
gemm_edge1(const float* __restrict__ PQ, const int* __restrict__ IDXp,
           const float* __restrict__ abias, const float* __restrict__ W,
           const float* __restrict__ obias, float* __restrict__ H) {
    __shared__ float As[16 * 128];
    __shared__ float Bs[16 * 64];
    __shared__ int   s_bi[128], s_qo[128];
    __shared__ float s_ab[64];
    int t = threadIdx.x;
    int block_m = blockIdx.x * 128;
    if (t < 128) {
        int e = block_m + t;
        int bi = e / KNN;
        s_bi[t] = bi;
        s_qo[t] = ((bi >> 10) << 10) + IDXp[e];
    }
    if (t < 64) s_ab[t] = abias[t];
    __syncthreads();

    int tx = t & 15, ty = t >> 4;
    ull acc[8][2];
    #pragma unroll
    for (int i = 0; i < 8; i++) { acc[i][0] = 0ull; acc[i][1] = 0ull; }

    for (int k0 = 0; k0 < 64; k0 += 16) {
        {
            int r  = t >> 1;
            int co = (t & 1) * 8;
            int bi = s_bi[r], qo = s_qo[r];
            const float* Pp = PQ + (size_t)bi * 128 + k0 + co;
            const float* Qp = PQ + (size_t)qo * 128 + 64 + k0 + co;
            float4 p0 = *reinterpret_cast<const float4*>(Pp);
            float4 p1 = *reinterpret_cast<const float4*>(Pp + 4);
            float4 q0 = *reinterpret_cast<const float4*>(Qp);
            float4 q1 = *reinterpret_cast<const float4*>(Qp + 4);
            As[(co + 0) * 128 + r] = fmaxf(p0.x + q0.x + s_ab[k0 + co + 0], 0.f);
            As[(co + 1) * 128 + r] = fmaxf(p0.y + q0.y + s_ab[k0 + co + 1], 0.f);
            As[(co + 2) * 128 + r] = fmaxf(p0.z + q0.z + s_ab[k0 + co + 2], 0.f);
            As[(co + 3) * 128 + r] = fmaxf(p0.w + q0.w + s_ab[k0 + co + 3], 0.f);
            As[(co + 4) * 128 + r] = fmaxf(p1.x + q1.x + s_ab[k0 + co + 4], 0.f);
            As[(co + 5) * 128 + r] = fmaxf(p1.y + q1.y + s_ab[k0 + co + 5], 0.f);
            As[(co + 6) * 128 + r] = fmaxf(p1.z + q1.z + s_ab[k0 + co + 6], 0.f);
            As[(co + 7) * 128 + r] = fmaxf(p1.w + q1.w + s_ab[k0 + co + 7], 0.f);
        }
        {
            int kk = t >> 4, cc = (t & 15) * 4;
            *reinterpret_cast<float4*>(&Bs[kk * 64 + cc]) =
                *reinterpret_cast<const float4*>(&W[(size_t)(k0 + kk) * 64 + cc]);
        }
        __syncthreads();
        #pragma unroll
        for (int kk = 0; kk < 16; kk++) {
            float4 a0 = *reinterpret_cast<const float4*>(&As[kk * 128 + ty * 8]);
            float4 a1 = *reinterpret_cast<const float4*>(&As[kk * 128 + ty * 8 + 4]);
            float4 b0 = *reinterpret_cast<const float4*>(&Bs[kk * 64 + tx * 4]);
            ull rb0 = pack2(b0.x, b0.y), rb1 = pack2(b0.z, b0.w);
            float ra[8] = {a0.x, a0.y, a0.z, a0.w, a1.x, a1.y, a1.z, a1.w};
            #pragma unroll
            for (int i = 0; i < 8; i++) {
                ull ai = pack2(ra[i], ra[i]);
                fma2(acc[i][0], ai, rb0);
                fma2(acc[i][1], ai, rb1);
            }
        }
        __syncthreads();
    }
    float ob[4];
    #pragma unroll
    for (int j = 0; j < 4; j++) ob[j] = obias[tx * 4 + j];
    float ps[4] = {0, 0, 0, 0}, ps2[4] = {0, 0, 0, 0};
    #pragma unroll
    for (int i = 0; i < 8; i++) {
        float2 u0 = unpack2(acc[i][0]), u1 = unpack2(acc[i][1]);
        float v[4] = {u0.x, u0.y, u1.x, u1.y};
        #pragma unroll
        for (int j = 0; j < 4; j++) {
            v[j] = fmaxf(v[j] + ob[j], 0.f);
            ps[j] += v[j]; ps2[j] = fmaf(v[j], v[j], ps2[j]);
        }
        int r = block_m + ty * 8 + i;
        *reinterpret_cast<float4*>(&H[(size_t)r * 64 + tx * 4]) =
            make_float4(v[0], v[1], v[2], v[3]);
    }
    #pragma unroll
    for (int j = 0; j < 4; j++) {
        As[ty * 64 + tx * 4 + j]        = ps[j];
        As[1024 + ty * 64 + tx * 4 + j] = ps2[j];
    }
    __syncthreads();
    if (t < 64) {
        float s = 0.f, s2 = 0.f;
        #pragma unroll
        for (int g = 0; g < 16; g++) { s += As[g * 64 + t]; s2 += As[1024 + g * 64 + t]; }
        atomicAdd(&g_sum[t],   (double)s);
        atomicAdd(&g_sumsq[t], (double)s2);
    }
}

// ---------------------------------------------------------------------------
// Conv1: stats of recomputed edge features relu(P+Q+b)
// ---------------------------------------------------------------------------
template <int CH>
__global__ void stats_edges_kernel(const float* __restrict__ PQ,
                                   const int* __restrict__ IDXp,
                                   const float* __restrict__ bias) {
    constexpr int G = 256 / CH;
    int c = threadIdx.x % CH;
    int g = threadIdx.x / CH;
    float bb = bias[c];
    float s = 0.f, s2 = 0.f;
    for (int node = blockIdx.x * G + g; node < NROW; node += 128 * G) {
        float p = PQ[(size_t)node * (2 * CH) + c] + bb;
        int base = (node >> 10) << 10;
        const int* ix = IDXp + node * KNN;
        #pragma unroll 5
        for (int kk = 0; kk < KNN; kk++) {
            int j = base + ix[kk];
            float v = fmaxf(p + PQ[(size_t)j * (2 * CH) + CH + c], 0.f);
            s += v; s2 = fmaf(v, v, s2);
        }
    }
    __shared__ float sh[2][256];
    sh[0][threadIdx.x] = s; sh[1][threadIdx.x] = s2;
    __syncthreads();
    if (g == 0) {
        #pragma unroll
        for (int gg = 1; gg < G; gg++) { s += sh[0][gg * CH + c]; s2 += sh[1][gg * CH + c]; }
        atomicAdd(&g_sum[c],   (double)s);
        atomicAdd(&g_sumsq[c], (double)s2);
    }
}

// ---------------------------------------------------------------------------
// Conv2: fused stats + per-node max/min of recomputed edge features (1 pass)
// ---------------------------------------------------------------------------
__global__ void stats_minmax_edges_kernel(const float* __restrict__ PQ2,
                                          const int* __restrict__ IDXp,
                                          const float* __restrict__ bias,
                                          float* __restrict__ vmax,
                                          float* __restrict__ vmin) {
    int c = threadIdx.x & 127;
    int g = threadIdx.x >> 7;          // 0..1
    float bb = bias[c];
    float s = 0.f, s2 = 0.f;
    for (int node = blockIdx.x * 2 + g; node < NROW; node += 256) {
        float p = PQ2[(size_t)node * 256 + c] + bb;
        int base = (node >> 10) << 10;
        const int* ix = IDXp + node * KNN;
        float mx = -3.4e38f, mn = 3.4e38f;
        #pragma unroll 5
        for (int kk = 0; kk < KNN; kk++) {
            int j = base + ix[kk];
            float v = fmaxf(p + PQ2[(size_t)j * 256 + 128 + c], 0.f);
            s += v; s2 = fmaf(v, v, s2);
            mx = fmaxf(mx, v); mn = fminf(mn, v);
        }
        vmax[(size_t)node * 128 + c] = mx;
        vmin[(size_t)node * 128 + c] = mn;
    }
    __shared__ float sh[2][256];
    sh[0][threadIdx.x] = s; sh[1][threadIdx.x] = s2;
    __syncthreads();
    if (g == 0) {
        s  += sh[0][128 + c];
        s2 += sh[1][128 + c];
        atomicAdd(&g_sum[c],   (double)s);
        atomicAdd(&g_sumsq[c], (double)s2);
    }
}

// hcat[bi,64+c] = s>=0 ? s*vmax+cc : s*vmin+cc
__global__ void apply_minmax_kernel(const float* __restrict__ vmax,
                                    const float* __restrict__ vmin,
                                    float* __restrict__ hcat) {
    int i = blockIdx.x * 256 + threadIdx.x;   // NROW*128
    int c = i & 127, bi = i >> 7;
    float s = g_sc[c], cc = g_cc[c];
    float v = (s >= 0.f) ? vmax[i] : vmin[i];
    hcat[(size_t)bi * 192 + 64 + c] = fmaf(s, v, cc);
}

// ---------------------------------------------------------------------------
template <int CH>
__global__ void finalize_kernel(const float* __restrict__ gam,
                                const float* __restrict__ bet, int E) {
    int c = threadIdx.x;   // 128
    if (c < CH) {
        double mu  = g_sum[c] / (double)E;
        double var = g_sumsq[c] / (double)E - mu * mu;
        float s = gam[c] * rsqrtf((float)var + 1e-5f);
        g_sc[c] = s;
        g_cc[c] = bet[c] - (float)mu * s;
    }
    g_sum[c] = 0.0; g_sumsq[c] = 0.0;
}

__global__ void fold_kernel(const float* __restrict__ gam, const float* __restrict__ bet,
                            const float* __restrict__ W, const float* __restrict__ bias,
                            int E, float* __restrict__ Wf, float* __restrict__ bf) {
    __shared__ float s_s[64], s_c[64];
    int t = threadIdx.x;   // 256
    if (t < 64) {
        double mu  = g_sum[t] / (double)E;
        double var = g_sumsq[t] / (double)E - mu * mu;
        float s = gam[t] * rsqrtf((float)var + 1e-5f);
        s_s[t] = s;
        s_c[t] = bet[t] - (float)mu * s;
        g_sum[t] = 0.0; g_sumsq[t] = 0.0;
    } else if (t < 128) {
        g_sum[t] = 0.0; g_sumsq[t] = 0.0;
    }
    __syncthreads();
    for (int e = t; e < 64 * 64; e += 256) Wf[e] = s_s[e >> 6] * W[e];
    if (t < 64) {
        float acc = bias[t];
        #pragma unroll 4
        for (int kk = 0; kk < 64; kk++) acc = fmaf(s_c[kk], W[kk * 64 + t], acc);
        bf[t] = acc;
    }
}

// ---------------------------------------------------------------------------
__global__ void maxagg1_kernel(const float* __restrict__ H, float* __restrict__ hcat,
                               float* __restrict__ x1, float* __restrict__ sq) {
    int bi = blockIdx.x;
    int c  = threadIdx.x;   // 64
    const float* h = H + (size_t)bi * (KNN * 64) + c;
    float s = g_sc[c], cc = g_cc[c];
    float m = -3.4e38f;
    #pragma unroll
    for (int kk = 0; kk < KNN; kk++) m = fmaxf(m, fmaf(s, h[kk * 64], cc));
    hcat[(size_t)bi * 192 + c] = m;
    x1[(size_t)bi * 64 + c]    = m;
    float q = m * m;
    #pragma unroll
    for (int o = 16; o; o >>= 1) q += __shfl_xor_sync(0xffffffffu, q, o);
    __shared__ float sh[2];
    if ((c & 31) == 0) sh[c >> 5] = q;
    __syncthreads();
    if (c == 0) sq[bi] = sh[0] + sh[1];
}

__global__ void apply_bn_kernel(const float* __restrict__ Y, float* __restrict__ out) {
    int i = blockIdx.x * 256 + threadIdx.x;
    int c = i & 127;
    out[i] = fmaf(g_sc[c], Y[i], g_cc[c]);
}

// ---------------------------------------------------------------------------
extern "C" void kernel_launch(void* const* d_in, const int* in_sizes, int n_in,
                              void* d_out, int out_size) {
    const float* x0    = (const float*)d_in[1];
    const float* c1w0  = (const float*)d_in[2];
    const float* c1b0  = (const float*)d_in[3];
    const float* c1g0  = (const float*)d_in[4];
    const float* c1be0 = (const float*)d_in[5];
    const float* c1w1  = (const float*)d_in[6];
    const float* c1b1  = (const float*)d_in[7];
    const float* c1g1  = (const float*)d_in[8];
    const float* c1be1 = (const float*)d_in[9];
    const float* c1w2  = (const float*)d_in[10];
    const float* c1b2  = (const float*)d_in[11];
    const float* c1g2  = (const float*)d_in[12];
    const float* c1be2 = (const float*)d_in[13];
    const float* c2w0  = (const float*)d_in[14];
    const float* c2b0  = (const float*)d_in[15];
    const float* c2g0  = (const float*)d_in[16];
    const float* c2be0 = (const float*)d_in[17];
    const float* lw    = (const float*)d_in[18];
    const float* lb    = (const float*)d_in[19];
    const float* lg    = (const float*)d_in[20];
    const float* lbe   = (const float*)d_in[21];
    float* out = (float*)d_out;

    void* sp = nullptr; cudaGetSymbolAddress(&sp, g_scratch);
    float* S = (float*)sp;
    void* ip = nullptr; cudaGetSymbolAddress(&ip, g_knn_idx);
    int* IDX = (int*)ip;

    float* D     = S + OFF_D;
    float* PQ    = S + OFF_PQ;
    float* PQ2   = S + OFF_PQ2;
    float* H1    = S + OFF_H1;
    float* H2    = S + OFF_H2;
    float* HCAT  = S + OFF_HCAT;
    float* X1    = S + OFF_X1;
    float* Y0    = S + OFF_Y0;
    float* SQ    = S + OFF_SQ;
    float* WCAT  = S + OFF_WCAT;
    float* WCAT2 = S + OFF_WCAT2;
    float* WF    = S + OFF_WF;
    float* BF    = S + OFF_BF;
    float* VMAX  = S + OFF_H1;                       // H1 dead by conv2
    float* VMIN  = S + OFF_H1 + (size_t)NROW * 128;

    // dependency-free weight prep first => ncu capture slot lands on dist1
    build_wcat1<<<128, 256>>>(c1w0, WCAT);
    build_wcat2<<<64, 256>>>(c2w0, WCAT2);
    rowsq_kernel<256><<<NROW, 32>>>(x0, SQ);

    // ---- EdgeConv 1 ----
    dist_kernel<256><<<dim3(36, 1, 8), 256>>>(x0, SQ, D);
    topk_kernel<<<NROW / 8, 256>>>(D, IDX);
    gemm_nodes<128, 128, 8, 8, false, false><<<dim3(1, NROW / 128), 256>>>(x0, WCAT, nullptr, PQ, NROW, 128, 256);
    stats_edges_kernel<64><<<128, 256>>>(PQ, IDX, c1b0);
    fold_kernel<<<1, 256>>>(c1g0, c1be0, c1w1, c1b1, NEDGE, WF, BF);
    gemm_edge1<<<NEDGE / 128, 256>>>(PQ, IDX, c1b0, WF, BF, H1);
    fold_kernel<<<1, 256>>>(c1g1, c1be1, c1w2, c1b2, NEDGE, WF, BF);
    gemm_nodes<128, 64, 8, 4, true, true><<<dim3(1, NEDGE / 128), 256>>>(H1, WF, BF, H2, NEDGE, 64, 64);
    finalize_kernel<64><<<1, 128>>>(c1g2, c1be2, NEDGE);
    maxagg1_kernel<<<NROW, 64>>>(H2, HCAT, X1, SQ);

    // ---- EdgeConv 2 ----
    dist_kernel<64><<<dim3(36, 1, 8), 256>>>(X1, SQ, D);
    topk_kernel<<<NROW / 8, 256>>>(D, IDX);
    gemm_nodes<128, 128, 8, 8, false, false><<<dim3(2, NROW / 128), 256>>>(X1, WCAT2, nullptr, PQ2, NROW, 256, 64);
    stats_minmax_edges_kernel<<<128, 256>>>(PQ2, IDX, c2b0, VMAX, VMIN);
    finalize_kernel<128><<<1, 128>>>(c2g0, c2be0, NEDGE);
    apply_minmax_kernel<<<NROW * 128 / 256, 256>>>(VMAX, VMIN, HCAT);

    // ---- Final Linear + BN ----
    gemm_nodes<128, 128, 8, 8, true, true><<<dim3(1, NROW / 128), 256>>>(HCAT, lw, lb, Y0, NROW, 128, 192);
    finalize_kernel<128><<<1, 128>>>(lg, lbe, NROW);
    apply_bn_kernel<<<NROW * 128 / 256, 256>>>(Y0, out);
}

// round 10
// speedup vs baseline: 1.0424x; 1.0424x over previous
#include <cuda_runtime.h>
#include <cstdint>

// ---------------------------------------------------------------------------
// DGCNN: 2x EdgeConv (dynamic kNN) + final MLP, training-mode BatchNorm.
// R10 = R8 + split-half B-column ownership (conflict-free LDS at 16B phase
// stride, compile-time offsets -> no register cost, unlike R9's swizzle)
// + conv2 stats/max-agg fusion kept from R9.
// ---------------------------------------------------------------------------

typedef unsigned long long ull;

namespace cfg {
constexpr int BB   = 8;
constexpr int NN_  = 1024;
constexpr int KNN  = 20;
constexpr int NROW  = BB * NN_;        // 8192
constexpr int NEDGE = NROW * KNN;      // 163840

constexpr size_t OFF_D    = 0;
constexpr size_t SZ_D     = (size_t)BB * NN_ * NN_;
constexpr size_t OFF_PQ   = OFF_D + SZ_D;
constexpr size_t SZ_PQ    = (size_t)NROW * 128;
constexpr size_t OFF_PQ2  = OFF_PQ + SZ_PQ;
constexpr size_t SZ_PQ2   = (size_t)NROW * 256;
constexpr size_t OFF_H1   = OFF_PQ2 + SZ_PQ2;
constexpr size_t SZ_H64   = (size_t)NEDGE * 64;
constexpr size_t OFF_H2   = OFF_H1 + SZ_H64;
constexpr size_t OFF_HCAT = OFF_H2 + SZ_H64;
constexpr size_t SZ_HCAT  = (size_t)NROW * 192;
constexpr size_t OFF_X1   = OFF_HCAT + SZ_HCAT;
constexpr size_t SZ_X1    = (size_t)NROW * 64;
constexpr size_t OFF_Y0   = OFF_X1 + SZ_X1;
constexpr size_t SZ_Y0    = (size_t)NROW * 128;
constexpr size_t OFF_SQ   = OFF_Y0 + SZ_Y0;
constexpr size_t SZ_SQ    = (size_t)NROW;
constexpr size_t OFF_WCAT = OFF_SQ + SZ_SQ;
constexpr size_t SZ_WCAT  = 256 * 128;
constexpr size_t OFF_WCAT2= OFF_WCAT + SZ_WCAT;
constexpr size_t SZ_WCAT2 = 64 * 256;
constexpr size_t OFF_WF   = OFF_WCAT2 + SZ_WCAT2;
constexpr size_t SZ_WF    = 64 * 64;
constexpr size_t OFF_BF   = OFF_WF + SZ_WF;
constexpr size_t SZ_BF    = 128;
constexpr size_t SCRATCH_TOTAL = OFF_BF + SZ_BF;
}  // namespace cfg
using namespace cfg;

__device__ float  g_scratch[SCRATCH_TOTAL];
__device__ int    g_knn_idx[NEDGE];
__device__ double g_sum[128];
__device__ double g_sumsq[128];
__device__ float  g_sc[128];
__device__ float  g_cc[128];

// ---------------------------------------------------------------------------
__device__ __forceinline__ ull pack2(float x, float y) {
    ull r; asm("mov.b64 %0, {%1, %2};" : "=l"(r) : "f"(x), "f"(y)); return r;
}
__device__ __forceinline__ void fma2(ull& d, ull a, ull b) {
    asm("fma.rn.f32x2 %0, %1, %2, %0;" : "+l"(d) : "l"(a), "l"(b));
}
__device__ __forceinline__ float2 unpack2(ull v) {
    float2 f; asm("mov.b64 {%0, %1}, %2;" : "=f"(f.x), "=f"(f.y) : "l"(v)); return f;
}

// ---------------------------------------------------------------------------
__global__ void build_wcat1(const float* __restrict__ W0, float* __restrict__ Wcat) {
    int e = blockIdx.x * 256 + threadIdx.x;    // 256*128
    int kk = e >> 7, n = e & 127;
    float v;
    if (n < 64) v = W0[kk * 64 + n] - W0[(kk + 256) * 64 + n];
    else        v = W0[(kk + 256) * 64 + (n - 64)];
    Wcat[e] = v;
}
__global__ void build_wcat2(const float* __restrict__ W0, float* __restrict__ Wcat) {
    int e = blockIdx.x * 256 + threadIdx.x;    // 64*256
    int kk = e >> 8, n = e & 255;
    float v;
    if (n < 128) v = W0[kk * 128 + n] - W0[(kk + 64) * 128 + n];
    else         v = W0[(kk + 64) * 128 + (n - 128)];
    Wcat[e] = v;
}

// ---------------------------------------------------------------------------
template <int C>
__global__ void rowsq_kernel(const float* __restrict__ X, float* __restrict__ sq) {
    int row = blockIdx.x;
    const float* x = X + (size_t)row * C;
    float a = 0.f;
    #pragma unroll
    for (int c = threadIdx.x; c < C; c += 32) { float v = x[c]; a = fmaf(v, v, a); }
    #pragma unroll
    for (int o = 16; o; o >>= 1) a += __shfl_xor_sync(0xffffffffu, a, o);
    if (threadIdx.x == 0) sq[row] = a;
}

// ---------------------------------------------------------------------------
// Distance matrix, symmetric triangular tiles, split-half B ownership:
// thread tx owns cols [tx*4, tx*4+4) and [64+tx*4, 64+tx*4+4).
// ---------------------------------------------------------------------------
template <int C>
__global__ void __launch_bounds__(256)
dist_kernel(const float* __restrict__ X, const float* __restrict__ sq,
            float* __restrict__ D) {
    __shared__ float As[16][128];
    __shared__ float Bs[16][128];
    int b  = blockIdx.z;
    const float* Xb  = X  + (size_t)b * NN_ * C;
    const float* sqb = sq + (size_t)b * NN_;
    float* Db = D + (size_t)b * NN_ * NN_;

    int rem = blockIdx.x, bi = 0;
    while (rem >= 8 - bi) { rem -= 8 - bi; bi++; }
    int bj = bi + rem;
    int i0 = bi * 128, j0 = bj * 128;

    int t  = threadIdx.x;
    int tx = t & 15, ty = t >> 4;
    int c0 = tx * 4;            // first owned 4 cols
    int c1 = 64 + tx * 4;       // second owned 4 cols

    ull acc[8][4];
    #pragma unroll
    for (int i = 0; i < 8; i++)
        #pragma unroll
        for (int j = 0; j < 4; j++) acc[i][j] = 0ull;

    for (int k0 = 0; k0 < C; k0 += 16) {
        #pragma unroll
        for (int it = 0; it < 2; it++) {
            int r  = (t >> 2) + it * 64;
            int kk = (t & 3) * 4;
            float4 va = *reinterpret_cast<const float4*>(&Xb[(size_t)(i0 + r) * C + k0 + kk]);
            As[kk + 0][r] = va.x; As[kk + 1][r] = va.y;
            As[kk + 2][r] = va.z; As[kk + 3][r] = va.w;
            float4 vb = *reinterpret_cast<const float4*>(&Xb[(size_t)(j0 + r) * C + k0 + kk]);
            Bs[kk + 0][r] = vb.x; Bs[kk + 1][r] = vb.y;
            Bs[kk + 2][r] = vb.z; Bs[kk + 3][r] = vb.w;
        }
        __syncthreads();
        #pragma unroll
        for (int kk = 0; kk < 16; kk++) {
            float4 a0 = *reinterpret_cast<const float4*>(&As[kk][ty * 8]);
            float4 a1 = *reinterpret_cast<const float4*>(&As[kk][ty * 8 + 4]);
            float4 b0 = *reinterpret_cast<const float4*>(&Bs[kk][c0]);   // 16B stride: CF
            float4 b1 = *reinterpret_cast<const float4*>(&Bs[kk][c1]);   // 16B stride: CF
            ull rb[4] = {pack2(b0.x, b0.y), pack2(b0.z, b0.w),
                         pack2(b1.x, b1.y), pack2(b1.z, b1.w)};
            float ra[8] = {a0.x, a0.y, a0.z, a0.w, a1.x, a1.y, a1.z, a1.w};
            #pragma unroll
            for (int i = 0; i < 8; i++) {
                ull ai = pack2(ra[i], ra[i]);
                #pragma unroll
                for (int j = 0; j < 4; j++) fma2(acc[i][j], ai, rb[j]);
            }
        }
        __syncthreads();
    }
    float sj[8];
    #pragma unroll
    for (int j = 0; j < 4; j++) { sj[j] = sqb[j0 + c0 + j]; sj[4 + j] = sqb[j0 + c1 + j]; }

    float o[8][8];
    #pragma unroll
    for (int i = 0; i < 8; i++) {
        float si = sqb[i0 + ty * 8 + i];
        #pragma unroll
        for (int j = 0; j < 4; j++) {
            float2 u = unpack2(acc[i][j]);
            o[i][j * 2]     = si + sj[j * 2]     - 2.f * u.x;
            o[i][j * 2 + 1] = si + sj[j * 2 + 1] - 2.f * u.y;
        }
    }
    // normal tile write
    #pragma unroll
    for (int i = 0; i < 8; i++) {
        int gi = i0 + ty * 8 + i;
        *reinterpret_cast<float4*>(&Db[(size_t)gi * NN_ + j0 + c0]) =
            make_float4(o[i][0], o[i][1], o[i][2], o[i][3]);
        *reinterpret_cast<float4*>(&Db[(size_t)gi * NN_ + j0 + c1]) =
            make_float4(o[i][4], o[i][5], o[i][6], o[i][7]);
    }
    // mirror tile write (transposed)
    if (bi != bj) {
        #pragma unroll
        for (int j = 0; j < 8; j++) {
            int gj = j0 + ((j < 4) ? (c0 + j) : (c1 + j - 4));
            float4* dst = reinterpret_cast<float4*>(&Db[(size_t)gj * NN_ + i0 + ty * 8]);
            dst[0] = make_float4(o[0][j], o[1][j], o[2][j], o[3][j]);
            dst[1] = make_float4(o[4][j], o[5][j], o[6][j], o[7][j]);
        }
    }
}

// ---------------------------------------------------------------------------
// Top-20 smallest per row; one warp per row, coalesced float4 loads.
// ---------------------------------------------------------------------------
__global__ void topk_kernel(const float* __restrict__ D, int* __restrict__ idx) {
    int row  = blockIdx.x * 8 + (threadIdx.x >> 5);
    int lane = threadIdx.x & 31;
    const float4* d4 = reinterpret_cast<const float4*>(D + (size_t)row * NN_);
    float v[32];
    #pragma unroll
    for (int q = 0; q < 8; q++) {
        float4 x = d4[lane + 32 * q];
        v[4 * q + 0] = x.x; v[4 * q + 1] = x.y;
        v[4 * q + 2] = x.z; v[4 * q + 3] = x.w;
    }

    for (int s = 0; s < KNN; s++) {
        float m = v[0]; int mq = 0;
        #pragma unroll
        for (int q = 1; q < 32; q++) { if (v[q] < m) { m = v[q]; mq = q; } }
        int gidx = 4 * lane + 128 * (mq >> 2) + (mq & 3);
        float bm = m; int bidx = gidx;
        #pragma unroll
        for (int o = 16; o; o >>= 1) {
            float om = __shfl_xor_sync(0xffffffffu, bm, o);
            int   oi = __shfl_xor_sync(0xffffffffu, bidx, o);
            if (om < bm || (om == bm && oi < bidx)) { bm = om; bidx = oi; }
        }
        if (lane == 0) idx[row * KNN + s] = bidx;
        int wl = (bidx >> 2) & 31;
        if (lane == wl) {
            int slot = 4 * (bidx >> 7) + (bidx & 3);
            #pragma unroll
            for (int q = 0; q < 32; q++) if (q == slot) v[q] = 3.4e38f;
        }
    }
}

// ---------------------------------------------------------------------------
// Generic fp32 GEMM (f32x2, split-half cols for TN==8): C=A@B (+bias,relu)(+stats)
// ---------------------------------------------------------------------------
template <int BM, int BN, int TM, int TN, bool BIAS_RELU, bool STATS>
__global__ void __launch_bounds__(256)
gemm_nodes(const float* __restrict__ A, const float* __restrict__ Bm,
           const float* __restrict__ bias, float* __restrict__ Cmat,
           int M, int N, int K) {
    constexpr int BK = 16;
    constexpr int TX = BN / TN;
    static_assert(TX == 16 && (256 / TX) * TM == BM, "layout");
    __shared__ float smem[BK * (BM + BN)];
    float* As = smem;
    float* Bs = smem + BK * BM;
    int block_m = blockIdx.y * BM, block_n = blockIdx.x * BN;
    int t  = threadIdx.x;
    int tx = t % TX, ty = t / TX;
    int c0 = tx * 4;                 // first owned 4 cols
    int c1 = BN / 2 + tx * 4;        // second owned 4 cols (TN==8 only)

    ull acc[TM][TN / 2];
    #pragma unroll
    for (int i = 0; i < TM; i++)
        #pragma unroll
        for (int j = 0; j < TN / 2; j++) acc[i][j] = 0ull;

    for (int k0 = 0; k0 < K; k0 += BK) {
        #pragma unroll
        for (int it = 0; it < BM / 64; it++) {
            int r  = (t >> 2) + it * 64;
            int kk = (t & 3) * 4;
            float4 v = *reinterpret_cast<const float4*>(&A[(size_t)(block_m + r) * K + k0 + kk]);
            As[(kk + 0) * BM + r] = v.x; As[(kk + 1) * BM + r] = v.y;
            As[(kk + 2) * BM + r] = v.z; As[(kk + 3) * BM + r] = v.w;
        }
        #pragma unroll
        for (int it = 0; it < BN / 64; it++) {
            int kk = t >> 4;
            int cc = (t & 15) * 4 + it * 64;
            *reinterpret_cast<float4*>(&Bs[kk * BN + cc]) =
                *reinterpret_cast<const float4*>(&Bm[(size_t)(k0 + kk) * N + block_n + cc]);
        }
        __syncthreads();
        #pragma unroll
        for (int kk = 0; kk < BK; kk++) {
            float ra[TM];
            #pragma unroll
            for (int i4 = 0; i4 < TM / 4; i4++) {
                float4 a = *reinterpret_cast<const float4*>(&As[kk * BM + ty * TM + i4 * 4]);
                ra[i4 * 4 + 0] = a.x; ra[i4 * 4 + 1] = a.y;
                ra[i4 * 4 + 2] = a.z; ra[i4 * 4 + 3] = a.w;
            }
            ull rb[TN / 2];
            {
                float4 bq0 = *reinterpret_cast<const float4*>(&Bs[kk * BN + c0]);
                rb[0] = pack2(bq0.x, bq0.y);
                rb[1] = pack2(bq0.z, bq0.w);
                if (TN == 8) {
                    float4 bq1 = *reinterpret_cast<const float4*>(&Bs[kk * BN + c1]);
                    rb[2] = pack2(bq1.x, bq1.y);
                    rb[3] = pack2(bq1.z, bq1.w);
                }
            }
            #pragma unroll
            for (int i = 0; i < TM; i++) {
                ull ai = pack2(ra[i], ra[i]);
                #pragma unroll
                for (int j = 0; j < TN / 2; j++) fma2(acc[i][j], ai, rb[j]);
            }
        }
        __syncthreads();
    }

    float bb[TN];
    if (BIAS_RELU) {
        #pragma unroll
        for (int j = 0; j < TN; j++)
            bb[j] = bias[block_n + ((j < 4) ? (c0 + j) : (c1 + j - 4))];
    }
    float ps[TN], ps2[TN];
    #pragma unroll
    for (int j = 0; j < TN; j++) { ps[j] = 0.f; ps2[j] = 0.f; }

    #pragma unroll
    for (int i = 0; i < TM; i++) {
        float v[TN];
        #pragma unroll
        for (int j = 0; j < TN / 2; j++) {
            float2 u = unpack2(acc[i][j]);
            v[j * 2] = u.x; v[j * 2 + 1] = u.y;
        }
        #pragma unroll
        for (int j = 0; j < TN; j++) {
            if (BIAS_RELU) v[j] = fmaxf(v[j] + bb[j], 0.f);
            if (STATS) { ps[j] += v[j]; ps2[j] = fmaf(v[j], v[j], ps2[j]); }
        }
        int r = block_m + ty * TM + i;
        *reinterpret_cast<float4*>(&Cmat[(size_t)r * N + block_n + c0]) =
            make_float4(v[0], v[1], v[2], v[3]);
        if (TN == 8)
            *reinterpret_cast<float4*>(&Cmat[(size_t)r * N + block_n + c1]) =
                make_float4(v[4], v[5], v[6], v[7]);
    }

    if (STATS) {
        #pragma unroll
        for (int j = 0; j < TN; j++) {
            int col = (j < 4) ? (c0 + j) : (c1 + j - 4);
            smem[ty * BN + col]           = ps[j];
            smem[16 * BN + ty * BN + col] = ps2[j];
        }
        __syncthreads();
        if (t < BN) {
            float s = 0.f, s2 = 0.f;
            #pragma unroll
            for (int g = 0; g < 16; g++) { s += smem[g * BN + t]; s2 += smem[16 * BN + g * BN + t]; }
            atomicAdd(&g_sum[t],   (double)s);
            atomicAdd(&g_sumsq[t], (double)s2);
        }
    }
}

// ---------------------------------------------------------------------------
// Layer-1 edge GEMM: A recomputed on the fly (B reads already conflict-free).
// ---------------------------------------------------------------------------
__global__ void __launch_bounds__(256)
gemm_edge1(const float* __restrict__ PQ, const int* __restrict__ IDXp,
           const float* __restrict__ abias, const float* __restrict__ W,
           const float* __restrict__ obias, float* __restrict__ H) {
    __shared__ float As[16 * 128];
    __shared__ float Bs[16 * 64];
    __shared__ int   s_bi[128], s_qo[128];
    __shared__ float s_ab[64];
    int t = threadIdx.x;
    int block_m = blockIdx.x * 128;
    if (t < 128) {
        int e = block_m + t;
        int bi = e / KNN;
        s_bi[t] = bi;
        s_qo[t] = ((bi >> 10) << 10) + IDXp[e];
    }
    if (t < 64) s_ab[t] = abias[t];
    __syncthreads();

    int tx = t & 15, ty = t >> 4;
    ull acc[8][2];
    #pragma unroll
    for (int i = 0; i < 8; i++) { acc[i][0] = 0ull; acc[i][1] = 0ull; }

    for (int k0 = 0; k0 < 64; k0 += 16) {
        {
            int r  = t >> 1;
            int co = (t & 1) * 8;
            int bi = s_bi[r], qo = s_qo[r];
            const float* Pp = PQ + (size_t)bi * 128 + k0 + co;
            const float* Qp = PQ + (size_t)qo * 128 + 64 + k0 + co;
            float4 p0 = *reinterpret_cast<const float4*>(Pp);
            float4 p1 = *reinterpret_cast<const float4*>(Pp + 4);
            float4 q0 = *reinterpret_cast<const float4*>(Qp);
            float4 q1 = *reinterpret_cast<const float4*>(Qp + 4);
            As[(co + 0) * 128 + r] = fmaxf(p0.x + q0.x + s_ab[k0 + co + 0], 0.f);
            As[(co + 1) * 128 + r] = fmaxf(p0.y + q0.y + s_ab[k0 + co + 1], 0.f);
            As[(co + 2) * 128 + r] = fmaxf(p0.z + q0.z + s_ab[k0 + co + 2], 0.f);
            As[(co + 3) * 128 + r] = fmaxf(p0.w + q0.w + s_ab[k0 + co + 3], 0.f);
            As[(co + 4) * 128 + r] = fmaxf(p1.x + q1.x + s_ab[k0 + co + 4], 0.f);
            As[(co + 5) * 128 + r] = fmaxf(p1.y + q1.y + s_ab[k0 + co + 5], 0.f);
            As[(co + 6) * 128 + r] = fmaxf(p1.z + q1.z + s_ab[k0 + co + 6], 0.f);
            As[(co + 7) * 128 + r] = fmaxf(p1.w + q1.w + s_ab[k0 + co + 7], 0.f);
        }
        {
            int kk = t >> 4, cc = (t & 15) * 4;
            *reinterpret_cast<float4*>(&Bs[kk * 64 + cc]) =
                *reinterpret_cast<const float4*>(&W[(size_t)(k0 + kk) * 64 + cc]);
        }
        __syncthreads();
        #pragma unroll
        for (int kk = 0; kk < 16; kk++) {
            float4 a0 = *reinterpret_cast<const float4*>(&As[kk * 128 + ty * 8]);
            float4 a1 = *reinterpret_cast<const float4*>(&As[kk * 128 + ty * 8 + 4]);
            float4 b0 = *reinterpret_cast<const float4*>(&Bs[kk * 64 + tx * 4]);
            ull rb0 = pack2(b0.x, b0.y), rb1 = pack2(b0.z, b0.w);
            float ra[8] = {a0.x, a0.y, a0.z, a0.w, a1.x, a1.y, a1.z, a1.w};
            #pragma unroll
            for (int i = 0; i < 8; i++) {
                ull ai = pack2(ra[i], ra[i]);
                fma2(acc[i][0], ai, rb0);
                fma2(acc[i][1], ai, rb1);
            }
        }
        __syncthreads();
    }
    float ob[4];
    #pragma unroll
    for (int j = 0; j < 4; j++) ob[j] = obias[tx * 4 + j];
    float ps[4] = {0, 0, 0, 0}, ps2[4] = {0, 0, 0, 0};
    #pragma unroll
    for (int i = 0; i < 8; i++) {
        float2 u0 = unpack2(acc[i][0]), u1 = unpack2(acc[i][1]);
        float v[4] = {u0.x, u0.y, u1.x, u1.y};
        #pragma unroll
        for (int j = 0; j < 4; j++) {
            v[j] = fmaxf(v[j] + ob[j], 0.f);
            ps[j] += v[j]; ps2[j] = fmaf(v[j], v[j], ps2[j]);
        }
        int r = block_m + ty * 8 + i;
        *reinterpret_cast<float4*>(&H[(size_t)r * 64 + tx * 4]) =
            make_float4(v[0], v[1], v[2], v[3]);
    }
    #pragma unroll
    for (int j = 0; j < 4; j++) {
        As[ty * 64 + tx * 4 + j]        = ps[j];
        As[1024 + ty * 64 + tx * 4 + j] = ps2[j];
    }
    __syncthreads();
    if (t < 64) {
        float s = 0.f, s2 = 0.f;
        #pragma unroll
        for (int g = 0; g < 16; g++) { s += As[g * 64 + t]; s2 += As[1024 + g * 64 + t]; }
        atomicAdd(&g_sum[t],   (double)s);
        atomicAdd(&g_sumsq[t], (double)s2);
    }
}

// ---------------------------------------------------------------------------
// Conv1: stats of recomputed edge features relu(P+Q+b)
// ---------------------------------------------------------------------------
template <int CH>
__global__ void stats_edges_kernel(const float* __restrict__ PQ,
                                   const int* __restrict__ IDXp,
                                   const float* __restrict__ bias) {
    constexpr int G = 256 / CH;
    int c = threadIdx.x % CH;
    int g = threadIdx.x / CH;
    float bb = bias[c];
    float s = 0.f, s2 = 0.f;
    for (int node = blockIdx.x * G + g; node < NROW; node += 128 * G) {
        float p = PQ[(size_t)node * (2 * CH) + c] + bb;
        int base = (node >> 10) << 10;
        const int* ix = IDXp + node * KNN;
        #pragma unroll 5
        for (int kk = 0; kk < KNN; kk++) {
            int j = base + ix[kk];
            float v = fmaxf(p + PQ[(size_t)j * (2 * CH) + CH + c], 0.f);
            s += v; s2 = fmaf(v, v, s2);
        }
    }
    __shared__ float sh[2][256];
    sh[0][threadIdx.x] = s; sh[1][threadIdx.x] = s2;
    __syncthreads();
    if (g == 0) {
        #pragma unroll
        for (int gg = 1; gg < G; gg++) { s += sh[0][gg * CH + c]; s2 += sh[1][gg * CH + c]; }
        atomicAdd(&g_sum[c],   (double)s);
        atomicAdd(&g_sumsq[c], (double)s2);
    }
}

// ---------------------------------------------------------------------------
// Conv2: fused stats + per-node max/min of recomputed edge features (1 pass)
// ---------------------------------------------------------------------------
__global__ void stats_minmax_edges_kernel(const float* __restrict__ PQ2,
                                          const int* __restrict__ IDXp,
                                          const float* __restrict__ bias,
                                          float* __restrict__ vmax,
                                          float* __restrict__ vmin) {
    int c = threadIdx.x & 127;
    int g = threadIdx.x >> 7;          // 0..1
    float bb = bias[c];
    float s = 0.f, s2 = 0.f;
    for (int node = blockIdx.x * 2 + g; node < NROW; node += 256) {
        float p = PQ2[(size_t)node * 256 + c] + bb;
        int base = (node >> 10) << 10;
        const int* ix = IDXp + node * KNN;
        float mx = -3.4e38f, mn = 3.4e38f;
        #pragma unroll 5
        for (int kk = 0; kk < KNN; kk++) {
            int j = base + ix[kk];
            float v = fmaxf(p + PQ2[(size_t)j * 256 + 128 + c], 0.f);
            s += v; s2 = fmaf(v, v, s2);
            mx = fmaxf(mx, v); mn = fminf(mn, v);
        }
        vmax[(size_t)node * 128 + c] = mx;
        vmin[(size_t)node * 128 + c] = mn;
    }
    __shared__ float sh[2][256];
    sh[0][threadIdx.x] = s; sh[1][threadIdx.x] = s2;
    __syncthreads();
    if (g == 0) {
        s  += sh[0][128 + c];
        s2 += sh[1][128 + c];
        atomicAdd(&g_sum[c],   (double)s);
        atomicAdd(&g_sumsq[c], (double)s2);
    }
}

// hcat[bi,64+c] = s>=0 ? s*vmax+cc : s*vmin+cc
__global__ void apply_minmax_kernel(const float* __restrict__ vmax,
                                    const float* __restrict__ vmin,
                                    float* __restrict__ hcat) {
    int i = blockIdx.x * 256 + threadIdx.x;   // NROW*128
    int c = i & 127, bi = i >> 7;
    float s = g_sc[c], cc = g_cc[c];
    float v = (s >= 0.f) ? vmax[i] : vmin[i];
    hcat[(size_t)bi * 192 + 64 + c] = fmaf(s, v, cc);
}

// ---------------------------------------------------------------------------
template <int CH>
__global__ void finalize_kernel(const float* __restrict__ gam,
                                const float* __restrict__ bet, int E) {
    int c = threadIdx.x;   // 128
    if (c < CH) {
        double mu  = g_sum[c] / (double)E;
        double var = g_sumsq[c] / (double)E - mu * mu;
        float s = gam[c] * rsqrtf((float)var + 1e-5f);
        g_sc[c] = s;
        g_cc[c] = bet[c] - (float)mu * s;
    }
    g_sum[c] = 0.0; g_sumsq[c] = 0.0;
}

__global__ void fold_kernel(const float* __restrict__ gam, const float* __restrict__ bet,
                            const float* __restrict__ W, const float* __restrict__ bias,
                            int E, float* __restrict__ Wf, float* __restrict__ bf) {
    __shared__ float s_s[64], s_c[64];
    int t = threadIdx.x;   // 256
    if (t < 64) {
        double mu  = g_sum[t] / (double)E;
        double var = g_sumsq[t] / (double)E - mu * mu;
        float s = gam[t] * rsqrtf((float)var + 1e-5f);
        s_s[t] = s;
        s_c[t] = bet[t] - (float)mu * s;
        g_sum[t] = 0.0; g_sumsq[t] = 0.0;
    } else if (t < 128) {
        g_sum[t] = 0.0; g_sumsq[t] = 0.0;
    }
    __syncthreads();
    for (int e = t; e < 64 * 64; e += 256) Wf[e] = s_s[e >> 6] * W[e];
    if (t < 64) {
        float acc = bias[t];
        #pragma unroll 4
        for (int kk = 0; kk < 64; kk++) acc = fmaf(s_c[kk], W[kk * 64 + t], acc);
        bf[t] = acc;
    }
}

// ---------------------------------------------------------------------------
__global__ void maxagg1_kernel(const float* __restrict__ H, float* __restrict__ hcat,
                               float* __restrict__ x1, float* __restrict__ sq) {
    int bi = blockIdx.x;
    int c  = threadIdx.x;   // 64
    const float* h = H + (size_t)bi * (KNN * 64) + c;
    float s = g_sc[c], cc = g_cc[c];
    float m = -3.4e38f;
    #pragma unroll
    for (int kk = 0; kk < KNN; kk++) m = fmaxf(m, fmaf(s, h[kk * 64], cc));
    hcat[(size_t)bi * 192 + c] = m;
    x1[(size_t)bi * 64 + c]    = m;
    float q = m * m;
    #pragma unroll
    for (int o = 16; o; o >>= 1) q += __shfl_xor_sync(0xffffffffu, q, o);
    __shared__ float sh[2];
    if ((c & 31) == 0) sh[c >> 5] = q;
    __syncthreads();
    if (c == 0) sq[bi] = sh[0] + sh[1];
}

__global__ void apply_bn_kernel(const float* __restrict__ Y, float* __restrict__ out) {
    int i = blockIdx.x * 256 + threadIdx.x;
    int c = i & 127;
    out[i] = fmaf(g_sc[c], Y[i], g_cc[c]);
}

// ---------------------------------------------------------------------------
extern "C" void kernel_launch(void* const* d_in, const int* in_sizes, int n_in,
                              void* d_out, int out_size) {
    const float* x0    = (const float*)d_in[1];
    const float* c1w0  = (const float*)d_in[2];
    const float* c1b0  = (const float*)d_in[3];
    const float* c1g0  = (const float*)d_in[4];
    const float* c1be0 = (const float*)d_in[5];
    const float* c1w1  = (const float*)d_in[6];
    const float* c1b1  = (const float*)d_in[7];
    const float* c1g1  = (const float*)d_in[8];
    const float* c1be1 = (const float*)d_in[9];
    const float* c1w2  = (const float*)d_in[10];
    const float* c1b2  = (const float*)d_in[11];
    const float* c1g2  = (const float*)d_in[12];
    const float* c1be2 = (const float*)d_in[13];
    const float* c2w0  = (const float*)d_in[14];
    const float* c2b0  = (const float*)d_in[15];
    const float* c2g0  = (const float*)d_in[16];
    const float* c2be0 = (const float*)d_in[17];
    const float* lw    = (const float*)d_in[18];
    const float* lb    = (const float*)d_in[19];
    const float* lg    = (const float*)d_in[20];
    const float* lbe   = (const float*)d_in[21];
    float* out = (float*)d_out;

    void* sp = nullptr; cudaGetSymbolAddress(&sp, g_scratch);
    float* S = (float*)sp;
    void* ip = nullptr; cudaGetSymbolAddress(&ip, g_knn_idx);
    int* IDX = (int*)ip;

    float* D     = S + OFF_D;
    float* PQ    = S + OFF_PQ;
    float* PQ2   = S + OFF_PQ2;
    float* H1    = S + OFF_H1;
    float* H2    = S + OFF_H2;
    float* HCAT  = S + OFF_HCAT;
    float* X1    = S + OFF_X1;
    float* Y0    = S + OFF_Y0;
    float* SQ    = S + OFF_SQ;
    float* WCAT  = S + OFF_WCAT;
    float* WCAT2 = S + OFF_WCAT2;
    float* WF    = S + OFF_WF;
    float* BF    = S + OFF_BF;
    float* VMAX  = S + OFF_H1;                       // H1 dead by conv2
    float* VMIN  = S + OFF_H1 + (size_t)NROW * 128;

    // dependency-free weight prep first => ncu capture slot lands on dist1
    build_wcat1<<<128, 256>>>(c1w0, WCAT);
    build_wcat2<<<64, 256>>>(c2w0, WCAT2);
    rowsq_kernel<256><<<NROW, 32>>>(x0, SQ);

    // ---- EdgeConv 1 ----
    dist_kernel<256><<<dim3(36, 1, 8), 256>>>(x0, SQ, D);
    topk_kernel<<<NROW / 8, 256>>>(D, IDX);
    gemm_nodes<128, 128, 8, 8, false, false><<<dim3(1, NROW / 128), 256>>>(x0, WCAT, nullptr, PQ, NROW, 128, 256);
    stats_edges_kernel<64><<<128, 256>>>(PQ, IDX, c1b0);
    fold_kernel<<<1, 256>>>(c1g0, c1be0, c1w1, c1b1, NEDGE, WF, BF);
    gemm_edge1<<<NEDGE / 128, 256>>>(PQ, IDX, c1b0, WF, BF, H1);
    fold_kernel<<<1, 256>>>(c1g1, c1be1, c1w2, c1b2, NEDGE, WF, BF);
    gemm_nodes<128, 64, 8, 4, true, true><<<dim3(1, NEDGE / 128), 256>>>(H1, WF, BF, H2, NEDGE, 64, 64);
    finalize_kernel<64><<<1, 128>>>(c1g2, c1be2, NEDGE);
    maxagg1_kernel<<<NROW, 64>>>(H2, HCAT, X1, SQ);

    // ---- EdgeConv 2 ----
    dist_kernel<64><<<dim3(36, 1, 8), 256>>>(X1, SQ, D);
    topk_kernel<<<NROW / 8, 256>>>(D, IDX);
    gemm_nodes<128, 128, 8, 8, false, false><<<dim3(2, NROW / 128), 256>>>(X1, WCAT2, nullptr, PQ2, NROW, 256, 64);
    stats_minmax_edges_kernel<<<128, 256>>>(PQ2, IDX, c2b0, VMAX, VMIN);
    finalize_kernel<128><<<1, 128>>>(c2g0, c2be0, NEDGE);
    apply_minmax_kernel<<<NROW * 128 / 256, 256>>>(VMAX, VMIN, HCAT);

    // ---- Final Linear + BN ----
    gemm_nodes<128, 128, 8, 8, true, true><<<dim3(1, NROW / 128), 256>>>(HCAT, lw, lb, Y0, NROW, 128, 192);
    finalize_kernel<128><<<1, 128>>>(lg, lbe, NROW);
    apply_bn_kernel<<<NROW * 128 / 256, 256>>>(Y0, out);
}

// round 11
// speedup vs baseline: 1.0690x; 1.0255x over previous
#include <cuda_runtime.h>
#include <cstdint>

// ---------------------------------------------------------------------------
// DGCNN: 2x EdgeConv (dynamic kNN) + final MLP, training-mode BatchNorm.
// R11 = R10 + double-buffered smem pipelines in dist_kernel and gemm_nodes:
// per K-step: prefetch LDG (overlaps compute) -> compute(cur) -> STS(cur^1)
// -> one barrier (was two). launch_bounds(256,2) keeps 2 blocks/SM.
// ---------------------------------------------------------------------------

typedef unsigned long long ull;

namespace cfg {
constexpr int BB   = 8;
constexpr int NN_  = 1024;
constexpr int KNN  = 20;
constexpr int NROW  = BB * NN_;        // 8192
constexpr int NEDGE = NROW * KNN;      // 163840

constexpr size_t OFF_D    = 0;
constexpr size_t SZ_D     = (size_t)BB * NN_ * NN_;
constexpr size_t OFF_PQ   = OFF_D + SZ_D;
constexpr size_t SZ_PQ    = (size_t)NROW * 128;
constexpr size_t OFF_PQ2  = OFF_PQ + SZ_PQ;
constexpr size_t SZ_PQ2   = (size_t)NROW * 256;
constexpr size_t OFF_H1   = OFF_PQ2 + SZ_PQ2;
constexpr size_t SZ_H64   = (size_t)NEDGE * 64;
constexpr size_t OFF_H2   = OFF_H1 + SZ_H64;
constexpr size_t OFF_HCAT = OFF_H2 + SZ_H64;
constexpr size_t SZ_HCAT  = (size_t)NROW * 192;
constexpr size_t OFF_X1   = OFF_HCAT + SZ_HCAT;
constexpr size_t SZ_X1    = (size_t)NROW * 64;
constexpr size_t OFF_Y0   = OFF_X1 + SZ_X1;
constexpr size_t SZ_Y0    = (size_t)NROW * 128;
constexpr size_t OFF_SQ   = OFF_Y0 + SZ_Y0;
constexpr size_t SZ_SQ    = (size_t)NROW;
constexpr size_t OFF_WCAT = OFF_SQ + SZ_SQ;
constexpr size_t SZ_WCAT  = 256 * 128;
constexpr size_t OFF_WCAT2= OFF_WCAT + SZ_WCAT;
constexpr size_t SZ_WCAT2 = 64 * 256;
constexpr size_t OFF_WF   = OFF_WCAT2 + SZ_WCAT2;
constexpr size_t SZ_WF    = 64 * 64;
constexpr size_t OFF_BF   = OFF_WF + SZ_WF;
constexpr size_t SZ_BF    = 128;
constexpr size_t SCRATCH_TOTAL = OFF_BF + SZ_BF;
}  // namespace cfg
using namespace cfg;

__device__ float  g_scratch[SCRATCH_TOTAL];
__device__ int    g_knn_idx[NEDGE];
__device__ double g_sum[128];
__device__ double g_sumsq[128];
__device__ float  g_sc[128];
__device__ float  g_cc[128];

// ---------------------------------------------------------------------------
__device__ __forceinline__ ull pack2(float x, float y) {
    ull r; asm("mov.b64 %0, {%1, %2};" : "=l"(r) : "f"(x), "f"(y)); return r;
}
__device__ __forceinline__ void fma2(ull& d, ull a, ull b) {
    asm("fma.rn.f32x2 %0, %1, %2, %0;" : "+l"(d) : "l"(a), "l"(b));
}
__device__ __forceinline__ float2 unpack2(ull v) {
    float2 f; asm("mov.b64 {%0, %1}, %2;" : "=f"(f.x), "=f"(f.y) : "l"(v)); return f;
}

// ---------------------------------------------------------------------------
__global__ void build_wcat1(const float* __restrict__ W0, float* __restrict__ Wcat) {
    int e = blockIdx.x * 256 + threadIdx.x;    // 256*128
    int kk = e >> 7, n = e & 127;
    float v;
    if (n < 64) v = W0[kk * 64 + n] - W0[(kk + 256) * 64 + n];
    else        v = W0[(kk + 256) * 64 + (n - 64)];
    Wcat[e] = v;
}
__global__ void build_wcat2(const float* __restrict__ W0, float* __restrict__ Wcat) {
    int e = blockIdx.x * 256 + threadIdx.x;    // 64*256
    int kk = e >> 8, n = e & 255;
    float v;
    if (n < 128) v = W0[kk * 128 + n] - W0[(kk + 64) * 128 + n];
    else         v = W0[(kk + 64) * 128 + (n - 128)];
    Wcat[e] = v;
}

// ---------------------------------------------------------------------------
template <int C>
__global__ void rowsq_kernel(const float* __restrict__ X, float* __restrict__ sq) {
    int row = blockIdx.x;
    const float* x = X + (size_t)row * C;
    float a = 0.f;
    #pragma unroll
    for (int c = threadIdx.x; c < C; c += 32) { float v = x[c]; a = fmaf(v, v, a); }
    #pragma unroll
    for (int o = 16; o; o >>= 1) a += __shfl_xor_sync(0xffffffffu, a, o);
    if (threadIdx.x == 0) sq[row] = a;
}

// ---------------------------------------------------------------------------
// Distance matrix: symmetric triangular tiles, split-half B cols,
// double-buffered smem pipeline (1 barrier per K-step).
// ---------------------------------------------------------------------------
template <int C>
__global__ void __launch_bounds__(256, 2)
dist_kernel(const float* __restrict__ X, const float* __restrict__ sq,
            float* __restrict__ D) {
    __shared__ float As[2][16][128];
    __shared__ float Bs[2][16][128];
    int b  = blockIdx.z;
    const float* Xb  = X  + (size_t)b * NN_ * C;
    const float* sqb = sq + (size_t)b * NN_;
    float* Db = D + (size_t)b * NN_ * NN_;

    int rem = blockIdx.x, bi = 0;
    while (rem >= 8 - bi) { rem -= 8 - bi; bi++; }
    int bj = bi + rem;
    int i0 = bi * 128, j0 = bj * 128;

    int t  = threadIdx.x;
    int tx = t & 15, ty = t >> 4;
    int c0 = tx * 4;
    int c1 = 64 + tx * 4;

    // loader mapping: 2 float4 per operand per thread
    int lr0 = (t >> 2), lr1 = lr0 + 64;
    int lkk = (t & 3) * 4;

    ull acc[8][4];
    #pragma unroll
    for (int i = 0; i < 8; i++)
        #pragma unroll
        for (int j = 0; j < 4; j++) acc[i][j] = 0ull;

    // prologue: tile 0 -> buffer 0
    {
        float4 va0 = *reinterpret_cast<const float4*>(&Xb[(size_t)(i0 + lr0) * C + lkk]);
        float4 va1 = *reinterpret_cast<const float4*>(&Xb[(size_t)(i0 + lr1) * C + lkk]);
        float4 vb0 = *reinterpret_cast<const float4*>(&Xb[(size_t)(j0 + lr0) * C + lkk]);
        float4 vb1 = *reinterpret_cast<const float4*>(&Xb[(size_t)(j0 + lr1) * C + lkk]);
        As[0][lkk + 0][lr0] = va0.x; As[0][lkk + 1][lr0] = va0.y;
        As[0][lkk + 2][lr0] = va0.z; As[0][lkk + 3][lr0] = va0.w;
        As[0][lkk + 0][lr1] = va1.x; As[0][lkk + 1][lr1] = va1.y;
        As[0][lkk + 2][lr1] = va1.z; As[0][lkk + 3][lr1] = va1.w;
        Bs[0][lkk + 0][lr0] = vb0.x; Bs[0][lkk + 1][lr0] = vb0.y;
        Bs[0][lkk + 2][lr0] = vb0.z; Bs[0][lkk + 3][lr0] = vb0.w;
        Bs[0][lkk + 0][lr1] = vb1.x; Bs[0][lkk + 1][lr1] = vb1.y;
        Bs[0][lkk + 2][lr1] = vb1.z; Bs[0][lkk + 3][lr1] = vb1.w;
    }
    __syncthreads();

    constexpr int NT = C / 16;
    for (int kt = 0; kt < NT; kt++) {
        int cur = kt & 1;
        float4 pa0, pa1, pb0, pb1;
        if (kt + 1 < NT) {
            int k0n = (kt + 1) * 16;
            pa0 = *reinterpret_cast<const float4*>(&Xb[(size_t)(i0 + lr0) * C + k0n + lkk]);
            pa1 = *reinterpret_cast<const float4*>(&Xb[(size_t)(i0 + lr1) * C + k0n + lkk]);
            pb0 = *reinterpret_cast<const float4*>(&Xb[(size_t)(j0 + lr0) * C + k0n + lkk]);
            pb1 = *reinterpret_cast<const float4*>(&Xb[(size_t)(j0 + lr1) * C + k0n + lkk]);
        }
        #pragma unroll
        for (int kk = 0; kk < 16; kk++) {
            float4 a0 = *reinterpret_cast<const float4*>(&As[cur][kk][ty * 8]);
            float4 a1 = *reinterpret_cast<const float4*>(&As[cur][kk][ty * 8 + 4]);
            float4 b0 = *reinterpret_cast<const float4*>(&Bs[cur][kk][c0]);
            float4 b1 = *reinterpret_cast<const float4*>(&Bs[cur][kk][c1]);
            ull rb[4] = {pack2(b0.x, b0.y), pack2(b0.z, b0.w),
                         pack2(b1.x, b1.y), pack2(b1.z, b1.w)};
            float ra[8] = {a0.x, a0.y, a0.z, a0.w, a1.x, a1.y, a1.z, a1.w};
            #pragma unroll
            for (int i = 0; i < 8; i++) {
                ull ai = pack2(ra[i], ra[i]);
                #pragma unroll
                for (int j = 0; j < 4; j++) fma2(acc[i][j], ai, rb[j]);
            }
        }
        if (kt + 1 < NT) {
            int nxt = cur ^ 1;
            As[nxt][lkk + 0][lr0] = pa0.x; As[nxt][lkk + 1][lr0] = pa0.y;
            As[nxt][lkk + 2][lr0] = pa0.z; As[nxt][lkk + 3][lr0] = pa0.w;
            As[nxt][lkk + 0][lr1] = pa1.x; As[nxt][lkk + 1][lr1] = pa1.y;
            As[nxt][lkk + 2][lr1] = pa1.z; As[nxt][lkk + 3][lr1] = pa1.w;
            Bs[nxt][lkk + 0][lr0] = pb0.x; Bs[nxt][lkk + 1][lr0] = pb0.y;
            Bs[nxt][lkk + 2][lr0] = pb0.z; Bs[nxt][lkk + 3][lr0] = pb0.w;
            Bs[nxt][lkk + 0][lr1] = pb1.x; Bs[nxt][lkk + 1][lr1] = pb1.y;
            Bs[nxt][lkk + 2][lr1] = pb1.z; Bs[nxt][lkk + 3][lr1] = pb1.w;
        }
        __syncthreads();
    }

    float sj[8];
    #pragma unroll
    for (int j = 0; j < 4; j++) { sj[j] = sqb[j0 + c0 + j]; sj[4 + j] = sqb[j0 + c1 + j]; }

    float o[8][8];
    #pragma unroll
    for (int i = 0; i < 8; i++) {
        float si = sqb[i0 + ty * 8 + i];
        #pragma unroll
        for (int j = 0; j < 4; j++) {
            float2 u = unpack2(acc[i][j]);
            o[i][j * 2]     = si + sj[j * 2]     - 2.f * u.x;
            o[i][j * 2 + 1] = si + sj[j * 2 + 1] - 2.f * u.y;
        }
    }
    #pragma unroll
    for (int i = 0; i < 8; i++) {
        int gi = i0 + ty * 8 + i;
        *reinterpret_cast<float4*>(&Db[(size_t)gi * NN_ + j0 + c0]) =
            make_float4(o[i][0], o[i][1], o[i][2], o[i][3]);
        *reinterpret_cast<float4*>(&Db[(size_t)gi * NN_ + j0 + c1]) =
            make_float4(o[i][4], o[i][5], o[i][6], o[i][7]);
    }
    if (bi != bj) {
        #pragma unroll
        for (int j = 0; j < 8; j++) {
            int gj = j0 + ((j < 4) ? (c0 + j) : (c1 + j - 4));
            float4* dst = reinterpret_cast<float4*>(&Db[(size_t)gj * NN_ + i0 + ty * 8]);
            dst[0] = make_float4(o[0][j], o[1][j], o[2][j], o[3][j]);
            dst[1] = make_float4(o[4][j], o[5][j], o[6][j], o[7][j]);
        }
    }
}

// ---------------------------------------------------------------------------
// Top-20 smallest per row; one warp per row, coalesced float4 loads.
// ---------------------------------------------------------------------------
__global__ void topk_kernel(const float* __restrict__ D, int* __restrict__ idx) {
    int row  = blockIdx.x * 8 + (threadIdx.x >> 5);
    int lane = threadIdx.x & 31;
    const float4* d4 = reinterpret_cast<const float4*>(D + (size_t)row * NN_);
    float v[32];
    #pragma unroll
    for (int q = 0; q < 8; q++) {
        float4 x = d4[lane + 32 * q];
        v[4 * q + 0] = x.x; v[4 * q + 1] = x.y;
        v[4 * q + 2] = x.z; v[4 * q + 3] = x.w;
    }

    for (int s = 0; s < KNN; s++) {
        float m = v[0]; int mq = 0;
        #pragma unroll
        for (int q = 1; q < 32; q++) { if (v[q] < m) { m = v[q]; mq = q; } }
        int gidx = 4 * lane + 128 * (mq >> 2) + (mq & 3);
        float bm = m; int bidx = gidx;
        #pragma unroll
        for (int o = 16; o; o >>= 1) {
            float om = __shfl_xor_sync(0xffffffffu, bm, o);
            int   oi = __shfl_xor_sync(0xffffffffu, bidx, o);
            if (om < bm || (om == bm && oi < bidx)) { bm = om; bidx = oi; }
        }
        if (lane == 0) idx[row * KNN + s] = bidx;
        int wl = (bidx >> 2) & 31;
        if (lane == wl) {
            int slot = 4 * (bidx >> 7) + (bidx & 3);
            #pragma unroll
            for (int q = 0; q < 32; q++) if (q == slot) v[q] = 3.4e38f;
        }
    }
}

// ---------------------------------------------------------------------------
// Generic fp32 GEMM (f32x2, split-half cols for TN==8), double-buffered smem.
// ---------------------------------------------------------------------------
template <int BM, int BN, int TM, int TN, bool BIAS_RELU, bool STATS>
__global__ void __launch_bounds__(256, 2)
gemm_nodes(const float* __restrict__ A, const float* __restrict__ Bm,
           const float* __restrict__ bias, float* __restrict__ Cmat,
           int M, int N, int K) {
    constexpr int BK = 16;
    constexpr int TX = BN / TN;
    static_assert(TX == 16 && (256 / TX) * TM == BM, "layout");
    constexpr int N4A = BM / 64;
    constexpr int N4B = BN / 64;
    __shared__ float smem[2 * BK * (BM + BN)];
    // buffers: As[buf] at buf*BK*BM, Bs[buf] at 2*BK*BM + buf*BK*BN
    int block_m = blockIdx.y * BM, block_n = blockIdx.x * BN;
    int t  = threadIdx.x;
    int tx = t % TX, ty = t / TX;
    int c0 = tx * 4;
    int c1 = BN / 2 + tx * 4;

    int ar  = t >> 2;                 // A loader row (first)
    int akk = (t & 3) * 4;            // A loader k-offset
    int bkk = t >> 4;                 // B loader k row
    int bcc = (t & 15) * 4;           // B loader col base

    ull acc[TM][TN / 2];
    #pragma unroll
    for (int i = 0; i < TM; i++)
        #pragma unroll
        for (int j = 0; j < TN / 2; j++) acc[i][j] = 0ull;

    // prologue: tile 0 -> buffer 0
    {
        float* As0 = smem;
        float* Bs0 = smem + 2 * BK * BM;
        #pragma unroll
        for (int it = 0; it < N4A; it++) {
            int r = ar + it * 64;
            float4 v = *reinterpret_cast<const float4*>(&A[(size_t)(block_m + r) * K + akk]);
            As0[(akk + 0) * BM + r] = v.x; As0[(akk + 1) * BM + r] = v.y;
            As0[(akk + 2) * BM + r] = v.z; As0[(akk + 3) * BM + r] = v.w;
        }
        #pragma unroll
        for (int it = 0; it < N4B; it++) {
            int cc = bcc + it * 64;
            *reinterpret_cast<float4*>(&Bs0[bkk * BN + cc]) =
                *reinterpret_cast<const float4*>(&Bm[(size_t)bkk * N + block_n + cc]);
        }
    }
    __syncthreads();

    int NT = K / BK;
    for (int kt = 0; kt < NT; kt++) {
        int cur = kt & 1;
        float* Asb = smem + cur * BK * BM;
        float* Bsb = smem + 2 * BK * BM + cur * BK * BN;
        float4 pa[N4A], pb[N4B];
        if (kt + 1 < NT) {
            int k0n = (kt + 1) * BK;
            #pragma unroll
            for (int it = 0; it < N4A; it++) {
                int r = ar + it * 64;
                pa[it] = *reinterpret_cast<const float4*>(&A[(size_t)(block_m + r) * K + k0n + akk]);
            }
            #pragma unroll
            for (int it = 0; it < N4B; it++) {
                int cc = bcc + it * 64;
                pb[it] = *reinterpret_cast<const float4*>(&Bm[(size_t)(k0n + bkk) * N + block_n + cc]);
            }
        }
        #pragma unroll
        for (int kk = 0; kk < BK; kk++) {
            float ra[TM];
            #pragma unroll
            for (int i4 = 0; i4 < TM / 4; i4++) {
                float4 a = *reinterpret_cast<const float4*>(&Asb[kk * BM + ty * TM + i4 * 4]);
                ra[i4 * 4 + 0] = a.x; ra[i4 * 4 + 1] = a.y;
                ra[i4 * 4 + 2] = a.z; ra[i4 * 4 + 3] = a.w;
            }
            ull rb[TN / 2];
            {
                float4 bq0 = *reinterpret_cast<const float4*>(&Bsb[kk * BN + c0]);
                rb[0] = pack2(bq0.x, bq0.y);
                rb[1] = pack2(bq0.z, bq0.w);
                if (TN == 8) {
                    float4 bq1 = *reinterpret_cast<const float4*>(&Bsb[kk * BN + c1]);
                    rb[2] = pack2(bq1.x, bq1.y);
                    rb[3] = pack2(bq1.z, bq1.w);
                }
            }
            #pragma unroll
            for (int i = 0; i < TM; i++) {
                ull ai = pack2(ra[i], ra[i]);
                #pragma unroll
                for (int j = 0; j < TN / 2; j++) fma2(acc[i][j], ai, rb[j]);
            }
        }
        if (kt + 1 < NT) {
            float* Asn = smem + (cur ^ 1) * BK * BM;
            float* Bsn = smem + 2 * BK * BM + (cur ^ 1) * BK * BN;
            #pragma unroll
            for (int it = 0; it < N4A; it++) {
                int r = ar + it * 64;
                Asn[(akk + 0) * BM + r] = pa[it].x; Asn[(akk + 1) * BM + r] = pa[it].y;
                Asn[(akk + 2) * BM + r] = pa[it].z; Asn[(akk + 3) * BM + r] = pa[it].w;
            }
            #pragma unroll
            for (int it = 0; it < N4B; it++) {
                int cc = bcc + it * 64;
                *reinterpret_cast<float4*>(&Bsn[bkk * BN + cc]) = pb[it];
            }
        }
        __syncthreads();
    }

    float bb[TN];
    if (BIAS_RELU) {
        #pragma unroll
        for (int j = 0; j < TN; j++)
            bb[j] = bias[block_n + ((j < 4) ? (c0 + j) : (c1 + j - 4))];
    }
    float ps[TN], ps2[TN];
    #pragma unroll
    for (int j = 0; j < TN; j++) { ps[j] = 0.f; ps2[j] = 0.f; }

    #pragma unroll
    for (int i = 0; i < TM; i++) {
        float v[TN];
        #pragma unroll
        for (int j = 0; j < TN / 2; j++) {
            float2 u = unpack2(acc[i][j]);
            v[j * 2] = u.x; v[j * 2 + 1] = u.y;
        }
        #pragma unroll
        for (int j = 0; j < TN; j++) {
            if (BIAS_RELU) v[j] = fmaxf(v[j] + bb[j], 0.f);
            if (STATS) { ps[j] += v[j]; ps2[j] = fmaf(v[j], v[j], ps2[j]); }
        }
        int r = block_m + ty * TM + i;
        *reinterpret_cast<float4*>(&Cmat[(size_t)r * N + block_n + c0]) =
            make_float4(v[0], v[1], v[2], v[3]);
        if (TN == 8)
            *reinterpret_cast<float4*>(&Cmat[(size_t)r * N + block_n + c1]) =
                make_float4(v[4], v[5], v[6], v[7]);
    }

    if (STATS) {
        // reuse smem front: [0,16*BN) sums, [16*BN,32*BN) sumsq (<= 2*BK*BM)
        #pragma unroll
        for (int j = 0; j < TN; j++) {
            int col = (j < 4) ? (c0 + j) : (c1 + j - 4);
            smem[ty * BN + col]           = ps[j];
            smem[16 * BN + ty * BN + col] = ps2[j];
        }
        __syncthreads();
        if (t < BN) {
            float s = 0.f, s2 = 0.f;
            #pragma unroll
            for (int g = 0; g < 16; g++) { s += smem[g * BN + t]; s2 += smem[16 * BN + g * BN + t]; }
            atomicAdd(&g_sum[t],   (double)s);
            atomicAdd(&g_sumsq[t], (double)s2);
        }
    }
}

// ---------------------------------------------------------------------------
// Layer-1 edge GEMM: A recomputed on the fly (unchanged, conflict-free B).
// ---------------------------------------------------------------------------
__global__ void __launch_bounds__(256)
gemm_edge1(const float* __restrict__ PQ, const int* __restrict__ IDXp,
           const float* __restrict__ abias, const float* __restrict__ W,
           const float* __restrict__ obias, float* __restrict__ H) {
    __shared__ float As[16 * 128];
    __shared__ float Bs[16 * 64];
    __shared__ int   s_bi[128], s_qo[128];
    __shared__ float s_ab[64];
    int t = threadIdx.x;
    int block_m = blockIdx.x * 128;
    if (t < 128) {
        int e = block_m + t;
        int bi = e / KNN;
        s_bi[t] = bi;
        s_qo[t] = ((bi >> 10) << 10) + IDXp[e];
    }
    if (t < 64) s_ab[t] = abias[t];
    __syncthreads();

    int tx = t & 15, ty = t >> 4;
    ull acc[8][2];
    #pragma unroll
    for (int i = 0; i < 8; i++) { acc[i][0] = 0ull; acc[i][1] = 0ull; }

    for (int k0 = 0; k0 < 64; k0 += 16) {
        {
            int r  = t >> 1;
            int co = (t & 1) * 8;
            int bi = s_bi[r], qo = s_qo[r];
            const float* Pp = PQ + (size_t)bi * 128 + k0 + co;
            const float* Qp = PQ + (size_t)qo * 128 + 64 + k0 + co;
            float4 p0 = *reinterpret_cast<const float4*>(Pp);
            float4 p1 = *reinterpret_cast<const float4*>(Pp + 4);
            float4 q0 = *reinterpret_cast<const float4*>(Qp);
            float4 q1 = *reinterpret_cast<const float4*>(Qp + 4);
            As[(co + 0) * 128 + r] = fmaxf(p0.x + q0.x + s_ab[k0 + co + 0], 0.f);
            As[(co + 1) * 128 + r] = fmaxf(p0.y + q0.y + s_ab[k0 + co + 1], 0.f);
            As[(co + 2) * 128 + r] = fmaxf(p0.z + q0.z + s_ab[k0 + co + 2], 0.f);
            As[(co + 3) * 128 + r] = fmaxf(p0.w + q0.w + s_ab[k0 + co + 3], 0.f);
            As[(co + 4) * 128 + r] = fmaxf(p1.x + q1.x + s_ab[k0 + co + 4], 0.f);
            As[(co + 5) * 128 + r] = fmaxf(p1.y + q1.y + s_ab[k0 + co + 5], 0.f);
            As[(co + 6) * 128 + r] = fmaxf(p1.z + q1.z + s_ab[k0 + co + 6], 0.f);
            As[(co + 7) * 128 + r] = fmaxf(p1.w + q1.w + s_ab[k0 + co + 7], 0.f);
        }
        {
            int kk = t >> 4, cc = (t & 15) * 4;
            *reinterpret_cast<float4*>(&Bs[kk * 64 + cc]) =
                *reinterpret_cast<const float4*>(&W[(size_t)(k0 + kk) * 64 + cc]);
        }
        __syncthreads();
        #pragma unroll
        for (int kk = 0; kk < 16; kk++) {
            float4 a0 = *reinterpret_cast<const float4*>(&As[kk * 128 + ty * 8]);
            float4 a1 = *reinterpret_cast<const float4*>(&As[kk * 128 + ty * 8 + 4]);
            float4 b0 = *reinterpret_cast<const float4*>(&Bs[kk * 64 + tx * 4]);
            ull rb0 = pack2(b0.x, b0.y), rb1 = pack2(b0.z, b0.w);
            float ra[8] = {a0.x, a0.y, a0.z, a0.w, a1.x, a1.y, a1.z, a1.w};
            #pragma unroll
            for (int i = 0; i < 8; i++) {
                ull ai = pack2(ra[i], ra[i]);
                fma2(acc[i][0], ai, rb0);
                fma2(acc[i][1], ai, rb1);
            }
        }
        __syncthreads();
    }
    float ob[4];
    #pragma unroll
    for (int j = 0; j < 4; j++) ob[j] = obias[tx * 4 + j];
    float ps[4] = {0, 0, 0, 0}, ps2[4] = {0, 0, 0, 0};
    #pragma unroll
    for (int i = 0; i < 8; i++) {
        float2 u0 = unpack2(acc[i][0]), u1 = unpack2(acc[i][1]);
        float v[4] = {u0.x, u0.y, u1.x, u1.y};
        #pragma unroll
        for (int j = 0; j < 4; j++) {
            v[j] = fmaxf(v[j] + ob[j], 0.f);
            ps[j] += v[j]; ps2[j] = fmaf(v[j], v[j], ps2[j]);
        }
        int r = block_m + ty * 8 + i;
        *reinterpret_cast<float4*>(&H[(size_t)r * 64 + tx * 4]) =
            make_float4(v[0], v[1], v[2], v[3]);
    }
    #pragma unroll
    for (int j = 0; j < 4; j++) {
        As[ty * 64 + tx * 4 + j]        = ps[j];
        As[1024 + ty * 64 + tx * 4 + j] = ps2[j];
    }
    __syncthreads();
    if (t < 64) {
        float s = 0.f, s2 = 0.f;
        #pragma unroll
        for (int g = 0; g < 16; g++) { s += As[g * 64 + t]; s2 += As[1024 + g * 64 + t]; }
        atomicAdd(&g_sum[t],   (double)s);
        atomicAdd(&g_sumsq[t], (double)s2);
    }
}

// ---------------------------------------------------------------------------
// Conv1: stats of recomputed edge features relu(P+Q+b)
// ---------------------------------------------------------------------------
template <int CH>
__global__ void stats_edges_kernel(const float* __restrict__ PQ,
                                   const int* __restrict__ IDXp,
                                   const float* __restrict__ bias) {
    constexpr int G = 256 / CH;
    int c = threadIdx.x % CH;
    int g = threadIdx.x / CH;
    float bb = bias[c];
    float s = 0.f, s2 = 0.f;
    for (int node = blockIdx.x * G + g; node < NROW; node += 128 * G) {
        float p = PQ[(size_t)node * (2 * CH) + c] + bb;
        int base = (node >> 10) << 10;
        const int* ix = IDXp + node * KNN;
        #pragma unroll 5
        for (int kk = 0; kk < KNN; kk++) {
            int j = base + ix[kk];
            float v = fmaxf(p + PQ[(size_t)j * (2 * CH) + CH + c], 0.f);
            s += v; s2 = fmaf(v, v, s2);
        }
    }
    __shared__ float sh[2][256];
    sh[0][threadIdx.x] = s; sh[1][threadIdx.x] = s2;
    __syncthreads();
    if (g == 0) {
        #pragma unroll
        for (int gg = 1; gg < G; gg++) { s += sh[0][gg * CH + c]; s2 += sh[1][gg * CH + c]; }
        atomicAdd(&g_sum[c],   (double)s);
        atomicAdd(&g_sumsq[c], (double)s2);
    }
}

// ---------------------------------------------------------------------------
// Conv2: fused stats + per-node max/min of recomputed edge features (1 pass)
// ---------------------------------------------------------------------------
__global__ void stats_minmax_edges_kernel(const float* __restrict__ PQ2,
                                          const int* __restrict__ IDXp,
                                          const float* __restrict__ bias,
                                          float* __restrict__ vmax,
                                          float* __restrict__ vmin) {
    int c = threadIdx.x & 127;
    int g = threadIdx.x >> 7;          // 0..1
    float bb = bias[c];
    float s = 0.f, s2 = 0.f;
    for (int node = blockIdx.x * 2 + g; node < NROW; node += 256) {
        float p = PQ2[(size_t)node * 256 + c] + bb;
        int base = (node >> 10) << 10;
        const int* ix = IDXp + node * KNN;
        float mx = -3.4e38f, mn = 3.4e38f;
        #pragma unroll 5
        for (int kk = 0; kk < KNN; kk++) {
            int j = base + ix[kk];
            float v = fmaxf(p + PQ2[(size_t)j * 256 + 128 + c], 0.f);
            s += v; s2 = fmaf(v, v, s2);
            mx = fmaxf(mx, v); mn = fminf(mn, v);
        }
        vmax[(size_t)node * 128 + c] = mx;
        vmin[(size_t)node * 128 + c] = mn;
    }
    __shared__ float sh[2][256];
    sh[0][threadIdx.x] = s; sh[1][threadIdx.x] = s2;
    __syncthreads();
    if (g == 0) {
        s  += sh[0][128 + c];
        s2 += sh[1][128 + c];
        atomicAdd(&g_sum[c],   (double)s);
        atomicAdd(&g_sumsq[c], (double)s2);
    }
}

// hcat[bi,64+c] = s>=0 ? s*vmax+cc : s*vmin+cc
__global__ void apply_minmax_kernel(const float* __restrict__ vmax,
                                    const float* __restrict__ vmin,
                                    float* __restrict__ hcat) {
    int i = blockIdx.x * 256 + threadIdx.x;   // NROW*128
    int c = i & 127, bi = i >> 7;
    float s = g_sc[c], cc = g_cc[c];
    float v = (s >= 0.f) ? vmax[i] : vmin[i];
    hcat[(size_t)bi * 192 + 64 + c] = fmaf(s, v, cc);
}

// ---------------------------------------------------------------------------
template <int CH>
__global__ void finalize_kernel(const float* __restrict__ gam,
                                const float* __restrict__ bet, int E) {
    int c = threadIdx.x;   // 128
    if (c < CH) {
        double mu  = g_sum[c] / (double)E;
        double var = g_sumsq[c] / (double)E - mu * mu;
        float s = gam[c] * rsqrtf((float)var + 1e-5f);
        g_sc[c] = s;
        g_cc[c] = bet[c] - (float)mu * s;
    }
    g_sum[c] = 0.0; g_sumsq[c] = 0.0;
}

__global__ void fold_kernel(const float* __restrict__ gam, const float* __restrict__ bet,
                            const float* __restrict__ W, const float* __restrict__ bias,
                            int E, float* __restrict__ Wf, float* __restrict__ bf) {
    __shared__ float s_s[64], s_c[64];
    int t = threadIdx.x;   // 256
    if (t < 64) {
        double mu  = g_sum[t] / (double)E;
        double var = g_sumsq[t] / (double)E - mu * mu;
        float s = gam[t] * rsqrtf((float)var + 1e-5f);
        s_s[t] = s;
        s_c[t] = bet[t] - (float)mu * s;
        g_sum[t] = 0.0; g_sumsq[t] = 0.0;
    } else if (t < 128) {
        g_sum[t] = 0.0; g_sumsq[t] = 0.0;
    }
    __syncthreads();
    for (int e = t; e < 64 * 64; e += 256) Wf[e] = s_s[e >> 6] * W[e];
    if (t < 64) {
        float acc = bias[t];
        #pragma unroll 4
        for (int kk = 0; kk < 64; kk++) acc = fmaf(s_c[kk], W[kk * 64 + t], acc);
        bf[t] = acc;
    }
}

// ---------------------------------------------------------------------------
__global__ void maxagg1_kernel(const float* __restrict__ H, float* __restrict__ hcat,
                               float* __restrict__ x1, float* __restrict__ sq) {
    int bi = blockIdx.x;
    int c  = threadIdx.x;   // 64
    const float* h = H + (size_t)bi * (KNN * 64) + c;
    float s = g_sc[c], cc = g_cc[c];
    float m = -3.4e38f;
    #pragma unroll
    for (int kk = 0; kk < KNN; kk++) m = fmaxf(m, fmaf(s, h[kk * 64], cc));
    hcat[(size_t)bi * 192 + c] = m;
    x1[(size_t)bi * 64 + c]    = m;
    float q = m * m;
    #pragma unroll
    for (int o = 16; o; o >>= 1) q += __shfl_xor_sync(0xffffffffu, q, o);
    __shared__ float sh[2];
    if ((c & 31) == 0) sh[c >> 5] = q;
    __syncthreads();
    if (c == 0) sq[bi] = sh[0] + sh[1];
}

__global__ void apply_bn_kernel(const float* __restrict__ Y, float* __restrict__ out) {
    int i = blockIdx.x * 256 + threadIdx.x;
    int c = i & 127;
    out[i] = fmaf(g_sc[c], Y[i], g_cc[c]);
}

// ---------------------------------------------------------------------------
extern "C" void kernel_launch(void* const* d_in, const int* in_sizes, int n_in,
                              void* d_out, int out_size) {
    const float* x0    = (const float*)d_in[1];
    const float* c1w0  = (const float*)d_in[2];
    const float* c1b0  = (const float*)d_in[3];
    const float* c1g0  = (const float*)d_in[4];
    const float* c1be0 = (const float*)d_in[5];
    const float* c1w1  = (const float*)d_in[6];
    const float* c1b1  = (const float*)d_in[7];
    const float* c1g1  = (const float*)d_in[8];
    const float* c1be1 = (const float*)d_in[9];
    const float* c1w2  = (const float*)d_in[10];
    const float* c1b2  = (const float*)d_in[11];
    const float* c1g2  = (const float*)d_in[12];
    const float* c1be2 = (const float*)d_in[13];
    const float* c2w0  = (const float*)d_in[14];
    const float* c2b0  = (const float*)d_in[15];
    const float* c2g0  = (const float*)d_in[16];
    const float* c2be0 = (const float*)d_in[17];
    const float* lw    = (const float*)d_in[18];
    const float* lb    = (const float*)d_in[19];
    const float* lg    = (const float*)d_in[20];
    const float* lbe   = (const float*)d_in[21];
    float* out = (float*)d_out;

    void* sp = nullptr; cudaGetSymbolAddress(&sp, g_scratch);
    float* S = (float*)sp;
    void* ip = nullptr; cudaGetSymbolAddress(&ip, g_knn_idx);
    int* IDX = (int*)ip;

    float* D     = S + OFF_D;
    float* PQ    = S + OFF_PQ;
    float* PQ2   = S + OFF_PQ2;
    float* H1    = S + OFF_H1;
    float* H2    = S + OFF_H2;
    float* HCAT  = S + OFF_HCAT;
    float* X1    = S + OFF_X1;
    float* Y0    = S + OFF_Y0;
    float* SQ    = S + OFF_SQ;
    float* WCAT  = S + OFF_WCAT;
    float* WCAT2 = S + OFF_WCAT2;
    float* WF    = S + OFF_WF;
    float* BF    = S + OFF_BF;
    float* VMAX  = S + OFF_H1;                       // H1 dead by conv2
    float* VMIN  = S + OFF_H1 + (size_t)NROW * 128;

    // dependency-free weight prep first => ncu capture slot lands on dist1
    build_wcat1<<<128, 256>>>(c1w0, WCAT);
    build_wcat2<<<64, 256>>>(c2w0, WCAT2);
    rowsq_kernel<256><<<NROW, 32>>>(x0, SQ);

    // ---- EdgeConv 1 ----
    dist_kernel<256><<<dim3(36, 1, 8), 256>>>(x0, SQ, D);
    topk_kernel<<<NROW / 8, 256>>>(D, IDX);
    gemm_nodes<128, 128, 8, 8, false, false><<<dim3(1, NROW / 128), 256>>>(x0, WCAT, nullptr, PQ, NROW, 128, 256);
    stats_edges_kernel<64><<<128, 256>>>(PQ, IDX, c1b0);
    fold_kernel<<<1, 256>>>(c1g0, c1be0, c1w1, c1b1, NEDGE, WF, BF);
    gemm_edge1<<<NEDGE / 128, 256>>>(PQ, IDX, c1b0, WF, BF, H1);
    fold_kernel<<<1, 256>>>(c1g1, c1be1, c1w2, c1b2, NEDGE, WF, BF);
    gemm_nodes<128, 64, 8, 4, true, true><<<dim3(1, NEDGE / 128), 256>>>(H1, WF, BF, H2, NEDGE, 64, 64);
    finalize_kernel<64><<<1, 128>>>(c1g2, c1be2, NEDGE);
    maxagg1_kernel<<<NROW, 64>>>(H2, HCAT, X1, SQ);

    // ---- EdgeConv 2 ----
    dist_kernel<64><<<dim3(36, 1, 8), 256>>>(X1, SQ, D);
    topk_kernel<<<NROW / 8, 256>>>(D, IDX);
    gemm_nodes<128, 128, 8, 8, false, false><<<dim3(2, NROW / 128), 256>>>(X1, WCAT2, nullptr, PQ2, NROW, 256, 64);
    stats_minmax_edges_kernel<<<128, 256>>>(PQ2, IDX, c2b0, VMAX, VMIN);
    finalize_kernel<128><<<1, 128>>>(c2g0, c2be0, NEDGE);
    apply_minmax_kernel<<<NROW * 128 / 256, 256>>>(VMAX, VMIN, HCAT);

    // ---- Final Linear + BN ----
    gemm_nodes<128, 128, 8, 8, true, true><<<dim3(1, NROW / 128), 256>>>(HCAT, lw, lb, Y0, NROW, 128, 192);
    finalize_kernel<128><<<1, 128>>>(lg, lbe, NROW);
    apply_bn_kernel<<<NROW * 128 / 256, 256>>>(Y0, out);
}

// round 12
// speedup vs baseline: 1.0986x; 1.0277x over previous
#include <cuda_runtime.h>
#include <cstdint>

// ---------------------------------------------------------------------------
// DGCNN: 2x EdgeConv (dynamic kNN) + final MLP, training-mode BatchNorm.
// R12 = R11 + (a) topk tree-min + equality-mask (serial chain 380->~185 cyc
// per round, identical tie semantics), (b) PQ/final gemms split to BN=64 ->
// 128 blocks (full-chip spread); stats atomics indexed by block_n + t.
// ---------------------------------------------------------------------------

typedef unsigned long long ull;

namespace cfg {
constexpr int BB   = 8;
constexpr int NN_  = 1024;
constexpr int KNN  = 20;
constexpr int NROW  = BB * NN_;        // 8192
constexpr int NEDGE = NROW * KNN;      // 163840

constexpr size_t OFF_D    = 0;
constexpr size_t SZ_D     = (size_t)BB * NN_ * NN_;
constexpr size_t OFF_PQ   = OFF_D + SZ_D;
constexpr size_t SZ_PQ    = (size_t)NROW * 128;
constexpr size_t OFF_PQ2  = OFF_PQ + SZ_PQ;
constexpr size_t SZ_PQ2   = (size_t)NROW * 256;
constexpr size_t OFF_H1   = OFF_PQ2 + SZ_PQ2;
constexpr size_t SZ_H64   = (size_t)NEDGE * 64;
constexpr size_t OFF_H2   = OFF_H1 + SZ_H64;
constexpr size_t OFF_HCAT = OFF_H2 + SZ_H64;
constexpr size_t SZ_HCAT  = (size_t)NROW * 192;
constexpr size_t OFF_X1   = OFF_HCAT + SZ_HCAT;
constexpr size_t SZ_X1    = (size_t)NROW * 64;
constexpr size_t OFF_Y0   = OFF_X1 + SZ_X1;
constexpr size_t SZ_Y0    = (size_t)NROW * 128;
constexpr size_t OFF_SQ   = OFF_Y0 + SZ_Y0;
constexpr size_t SZ_SQ    = (size_t)NROW;
constexpr size_t OFF_WCAT = OFF_SQ + SZ_SQ;
constexpr size_t SZ_WCAT  = 256 * 128;
constexpr size_t OFF_WCAT2= OFF_WCAT + SZ_WCAT;
constexpr size_t SZ_WCAT2 = 64 * 256;
constexpr size_t OFF_WF   = OFF_WCAT2 + SZ_WCAT2;
constexpr size_t SZ_WF    = 64 * 64;
constexpr size_t OFF_BF   = OFF_WF + SZ_WF;
constexpr size_t SZ_BF    = 128;
constexpr size_t SCRATCH_TOTAL = OFF_BF + SZ_BF;
}  // namespace cfg
using namespace cfg;

__device__ float  g_scratch[SCRATCH_TOTAL];
__device__ int    g_knn_idx[NEDGE];
__device__ double g_sum[128];
__device__ double g_sumsq[128];
__device__ float  g_sc[128];
__device__ float  g_cc[128];

// ---------------------------------------------------------------------------
__device__ __forceinline__ ull pack2(float x, float y) {
    ull r; asm("mov.b64 %0, {%1, %2};" : "=l"(r) : "f"(x), "f"(y)); return r;
}
__device__ __forceinline__ void fma2(ull& d, ull a, ull b) {
    asm("fma.rn.f32x2 %0, %1, %2, %0;" : "+l"(d) : "l"(a), "l"(b));
}
__device__ __forceinline__ float2 unpack2(ull v) {
    float2 f; asm("mov.b64 {%0, %1}, %2;" : "=f"(f.x), "=f"(f.y) : "l"(v)); return f;
}

// ---------------------------------------------------------------------------
__global__ void build_wcat1(const float* __restrict__ W0, float* __restrict__ Wcat) {
    int e = blockIdx.x * 256 + threadIdx.x;    // 256*128
    int kk = e >> 7, n = e & 127;
    float v;
    if (n < 64) v = W0[kk * 64 + n] - W0[(kk + 256) * 64 + n];
    else        v = W0[(kk + 256) * 64 + (n - 64)];
    Wcat[e] = v;
}
__global__ void build_wcat2(const float* __restrict__ W0, float* __restrict__ Wcat) {
    int e = blockIdx.x * 256 + threadIdx.x;    // 64*256
    int kk = e >> 8, n = e & 255;
    float v;
    if (n < 128) v = W0[kk * 128 + n] - W0[(kk + 64) * 128 + n];
    else         v = W0[(kk + 64) * 128 + (n - 128)];
    Wcat[e] = v;
}

// ---------------------------------------------------------------------------
template <int C>
__global__ void rowsq_kernel(const float* __restrict__ X, float* __restrict__ sq) {
    int row = blockIdx.x;
    const float* x = X + (size_t)row * C;
    float a = 0.f;
    #pragma unroll
    for (int c = threadIdx.x; c < C; c += 32) { float v = x[c]; a = fmaf(v, v, a); }
    #pragma unroll
    for (int o = 16; o; o >>= 1) a += __shfl_xor_sync(0xffffffffu, a, o);
    if (threadIdx.x == 0) sq[row] = a;
}

// ---------------------------------------------------------------------------
// Distance matrix: symmetric triangular tiles, split-half B cols,
// double-buffered smem pipeline (1 barrier per K-step).
// ---------------------------------------------------------------------------
template <int C>
__global__ void __launch_bounds__(256, 2)
dist_kernel(const float* __restrict__ X, const float* __restrict__ sq,
            float* __restrict__ D) {
    __shared__ float As[2][16][128];
    __shared__ float Bs[2][16][128];
    int b  = blockIdx.z;
    const float* Xb  = X  + (size_t)b * NN_ * C;
    const float* sqb = sq + (size_t)b * NN_;
    float* Db = D + (size_t)b * NN_ * NN_;

    int rem = blockIdx.x, bi = 0;
    while (rem >= 8 - bi) { rem -= 8 - bi; bi++; }
    int bj = bi + rem;
    int i0 = bi * 128, j0 = bj * 128;

    int t  = threadIdx.x;
    int tx = t & 15, ty = t >> 4;
    int c0 = tx * 4;
    int c1 = 64 + tx * 4;

    int lr0 = (t >> 2), lr1 = lr0 + 64;
    int lkk = (t & 3) * 4;

    ull acc[8][4];
    #pragma unroll
    for (int i = 0; i < 8; i++)
        #pragma unroll
        for (int j = 0; j < 4; j++) acc[i][j] = 0ull;

    {
        float4 va0 = *reinterpret_cast<const float4*>(&Xb[(size_t)(i0 + lr0) * C + lkk]);
        float4 va1 = *reinterpret_cast<const float4*>(&Xb[(size_t)(i0 + lr1) * C + lkk]);
        float4 vb0 = *reinterpret_cast<const float4*>(&Xb[(size_t)(j0 + lr0) * C + lkk]);
        float4 vb1 = *reinterpret_cast<const float4*>(&Xb[(size_t)(j0 + lr1) * C + lkk]);
        As[0][lkk + 0][lr0] = va0.x; As[0][lkk + 1][lr0] = va0.y;
        As[0][lkk + 2][lr0] = va0.z; As[0][lkk + 3][lr0] = va0.w;
        As[0][lkk + 0][lr1] = va1.x; As[0][lkk + 1][lr1] = va1.y;
        As[0][lkk + 2][lr1] = va1.z; As[0][lkk + 3][lr1] = va1.w;
        Bs[0][lkk + 0][lr0] = vb0.x; Bs[0][lkk + 1][lr0] = vb0.y;
        Bs[0][lkk + 2][lr0] = vb0.z; Bs[0][lkk + 3][lr0] = vb0.w;
        Bs[0][lkk + 0][lr1] = vb1.x; Bs[0][lkk + 1][lr1] = vb1.y;
        Bs[0][lkk + 2][lr1] = vb1.z; Bs[0][lkk + 3][lr1] = vb1.w;
    }
    __syncthreads();

    constexpr int NT = C / 16;
    for (int kt = 0; kt < NT; kt++) {
        int cur = kt & 1;
        float4 pa0, pa1, pb0, pb1;
        if (kt + 1 < NT) {
            int k0n = (kt + 1) * 16;
            pa0 = *reinterpret_cast<const float4*>(&Xb[(size_t)(i0 + lr0) * C + k0n + lkk]);
            pa1 = *reinterpret_cast<const float4*>(&Xb[(size_t)(i0 + lr1) * C + k0n + lkk]);
            pb0 = *reinterpret_cast<const float4*>(&Xb[(size_t)(j0 + lr0) * C + k0n + lkk]);
            pb1 = *reinterpret_cast<const float4*>(&Xb[(size_t)(j0 + lr1) * C + k0n + lkk]);
        }
        #pragma unroll
        for (int kk = 0; kk < 16; kk++) {
            float4 a0 = *reinterpret_cast<const float4*>(&As[cur][kk][ty * 8]);
            float4 a1 = *reinterpret_cast<const float4*>(&As[cur][kk][ty * 8 + 4]);
            float4 b0 = *reinterpret_cast<const float4*>(&Bs[cur][kk][c0]);
            float4 b1 = *reinterpret_cast<const float4*>(&Bs[cur][kk][c1]);
            ull rb[4] = {pack2(b0.x, b0.y), pack2(b0.z, b0.w),
                         pack2(b1.x, b1.y), pack2(b1.z, b1.w)};
            float ra[8] = {a0.x, a0.y, a0.z, a0.w, a1.x, a1.y, a1.z, a1.w};
            #pragma unroll
            for (int i = 0; i < 8; i++) {
                ull ai = pack2(ra[i], ra[i]);
                #pragma unroll
                for (int j = 0; j < 4; j++) fma2(acc[i][j], ai, rb[j]);
            }
        }
        if (kt + 1 < NT) {
            int nxt = cur ^ 1;
            As[nxt][lkk + 0][lr0] = pa0.x; As[nxt][lkk + 1][lr0] = pa0.y;
            As[nxt][lkk + 2][lr0] = pa0.z; As[nxt][lkk + 3][lr0] = pa0.w;
            As[nxt][lkk + 0][lr1] = pa1.x; As[nxt][lkk + 1][lr1] = pa1.y;
            As[nxt][lkk + 2][lr1] = pa1.z; As[nxt][lkk + 3][lr1] = pa1.w;
            Bs[nxt][lkk + 0][lr0] = pb0.x; Bs[nxt][lkk + 1][lr0] = pb0.y;
            Bs[nxt][lkk + 2][lr0] = pb0.z; Bs[nxt][lkk + 3][lr0] = pb0.w;
            Bs[nxt][lkk + 0][lr1] = pb1.x; Bs[nxt][lkk + 1][lr1] = pb1.y;
            Bs[nxt][lkk + 2][lr1] = pb1.z; Bs[nxt][lkk + 3][lr1] = pb1.w;
        }
        __syncthreads();
    }

    float sj[8];
    #pragma unroll
    for (int j = 0; j < 4; j++) { sj[j] = sqb[j0 + c0 + j]; sj[4 + j] = sqb[j0 + c1 + j]; }

    float o[8][8];
    #pragma unroll
    for (int i = 0; i < 8; i++) {
        float si = sqb[i0 + ty * 8 + i];
        #pragma unroll
        for (int j = 0; j < 4; j++) {
            float2 u = unpack2(acc[i][j]);
            o[i][j * 2]     = si + sj[j * 2]     - 2.f * u.x;
            o[i][j * 2 + 1] = si + sj[j * 2 + 1] - 2.f * u.y;
        }
    }
    #pragma unroll
    for (int i = 0; i < 8; i++) {
        int gi = i0 + ty * 8 + i;
        *reinterpret_cast<float4*>(&Db[(size_t)gi * NN_ + j0 + c0]) =
            make_float4(o[i][0], o[i][1], o[i][2], o[i][3]);
        *reinterpret_cast<float4*>(&Db[(size_t)gi * NN_ + j0 + c1]) =
            make_float4(o[i][4], o[i][5], o[i][6], o[i][7]);
    }
    if (bi != bj) {
        #pragma unroll
        for (int j = 0; j < 8; j++) {
            int gj = j0 + ((j < 4) ? (c0 + j) : (c1 + j - 4));
            float4* dst = reinterpret_cast<float4*>(&Db[(size_t)gj * NN_ + i0 + ty * 8]);
            dst[0] = make_float4(o[0][j], o[1][j], o[2][j], o[3][j]);
            dst[1] = make_float4(o[4][j], o[5][j], o[6][j], o[7][j]);
        }
    }
}

// ---------------------------------------------------------------------------
// Top-20 smallest per row; one warp per row, coalesced float4 loads.
// Tree-min + equality mask: smallest matching slot == smallest gidx, so
// semantics identical to the sequential first-match scan.
// ---------------------------------------------------------------------------
__global__ void topk_kernel(const float* __restrict__ D, int* __restrict__ idx) {
    int row  = blockIdx.x * 8 + (threadIdx.x >> 5);
    int lane = threadIdx.x & 31;
    const float4* d4 = reinterpret_cast<const float4*>(D + (size_t)row * NN_);
    float v[32];
    #pragma unroll
    for (int q = 0; q < 8; q++) {
        float4 x = d4[lane + 32 * q];
        v[4 * q + 0] = x.x; v[4 * q + 1] = x.y;
        v[4 * q + 2] = x.z; v[4 * q + 3] = x.w;
    }

    for (int s = 0; s < KNN; s++) {
        // depth-5 min tree
        float m16[16];
        #pragma unroll
        for (int q = 0; q < 16; q++) m16[q] = fminf(v[q], v[q + 16]);
        float m8[8];
        #pragma unroll
        for (int q = 0; q < 8; q++) m8[q] = fminf(m16[q], m16[q + 8]);
        float m4[4];
        #pragma unroll
        for (int q = 0; q < 4; q++) m4[q] = fminf(m8[q], m8[q + 4]);
        float m2a = fminf(m4[0], m4[2]), m2b = fminf(m4[1], m4[3]);
        float m = fminf(m2a, m2b);
        // equality mask (parallel OR-tree); smallest set bit = smallest slot
        unsigned mask = 0u;
        #pragma unroll
        for (int q = 0; q < 32; q++) mask |= (v[q] == m) ? (1u << q) : 0u;
        int slot = __ffs(mask) - 1;
        int gidx = 4 * lane + 128 * (slot >> 2) + (slot & 3);

        float bm = m; int bidx = gidx;
        #pragma unroll
        for (int o = 16; o; o >>= 1) {
            float om = __shfl_xor_sync(0xffffffffu, bm, o);
            int   oi = __shfl_xor_sync(0xffffffffu, bidx, o);
            if (om < bm || (om == bm && oi < bidx)) { bm = om; bidx = oi; }
        }
        if (lane == 0) idx[row * KNN + s] = bidx;
        int wl = (bidx >> 2) & 31;
        if (lane == wl) {
            int ws = 4 * (bidx >> 7) + (bidx & 3);
            #pragma unroll
            for (int q = 0; q < 32; q++) if (q == ws) v[q] = 3.4e38f;
        }
    }
}

// ---------------------------------------------------------------------------
// Generic fp32 GEMM (f32x2, split-half cols for TN==8), double-buffered smem.
// STATS atomics indexed by block_n + t (correct for grid.x > 1).
// ---------------------------------------------------------------------------
template <int BM, int BN, int TM, int TN, bool BIAS_RELU, bool STATS>
__global__ void __launch_bounds__(256, 2)
gemm_nodes(const float* __restrict__ A, const float* __restrict__ Bm,
           const float* __restrict__ bias, float* __restrict__ Cmat,
           int M, int N, int K) {
    constexpr int BK = 16;
    constexpr int TX = BN / TN;
    static_assert(TX == 16 && (256 / TX) * TM == BM, "layout");
    constexpr int N4A = BM / 64;
    constexpr int N4B = BN / 64;
    __shared__ float smem[2 * BK * (BM + BN)];
    int block_m = blockIdx.y * BM, block_n = blockIdx.x * BN;
    int t  = threadIdx.x;
    int tx = t % TX, ty = t / TX;
    int c0 = tx * 4;
    int c1 = BN / 2 + tx * 4;

    int ar  = t >> 2;
    int akk = (t & 3) * 4;
    int bkk = t >> 4;
    int bcc = (t & 15) * 4;

    ull acc[TM][TN / 2];
    #pragma unroll
    for (int i = 0; i < TM; i++)
        #pragma unroll
        for (int j = 0; j < TN / 2; j++) acc[i][j] = 0ull;

    {
        float* As0 = smem;
        float* Bs0 = smem + 2 * BK * BM;
        #pragma unroll
        for (int it = 0; it < N4A; it++) {
            int r = ar + it * 64;
            float4 v = *reinterpret_cast<const float4*>(&A[(size_t)(block_m + r) * K + akk]);
            As0[(akk + 0) * BM + r] = v.x; As0[(akk + 1) * BM + r] = v.y;
            As0[(akk + 2) * BM + r] = v.z; As0[(akk + 3) * BM + r] = v.w;
        }
        #pragma unroll
        for (int it = 0; it < N4B; it++) {
            int cc = bcc + it * 64;
            *reinterpret_cast<float4*>(&Bs0[bkk * BN + cc]) =
                *reinterpret_cast<const float4*>(&Bm[(size_t)bkk * N + block_n + cc]);
        }
    }
    __syncthreads();

    int NT = K / BK;
    for (int kt = 0; kt < NT; kt++) {
        int cur = kt & 1;
        float* Asb = smem + cur * BK * BM;
        float* Bsb = smem + 2 * BK * BM + cur * BK * BN;
        float4 pa[N4A], pb[N4B];
        if (kt + 1 < NT) {
            int k0n = (kt + 1) * BK;
            #pragma unroll
            for (int it = 0; it < N4A; it++) {
                int r = ar + it * 64;
                pa[it] = *reinterpret_cast<const float4*>(&A[(size_t)(block_m + r) * K + k0n + akk]);
            }
            #pragma unroll
            for (int it = 0; it < N4B; it++) {
                int cc = bcc + it * 64;
                pb[it] = *reinterpret_cast<const float4*>(&Bm[(size_t)(k0n + bkk) * N + block_n + cc]);
            }
        }
        #pragma unroll
        for (int kk = 0; kk < BK; kk++) {
            float ra[TM];
            #pragma unroll
            for (int i4 = 0; i4 < TM / 4; i4++) {
                float4 a = *reinterpret_cast<const float4*>(&Asb[kk * BM + ty * TM + i4 * 4]);
                ra[i4 * 4 + 0] = a.x; ra[i4 * 4 + 1] = a.y;
                ra[i4 * 4 + 2] = a.z; ra[i4 * 4 + 3] = a.w;
            }
            ull rb[TN / 2];
            {
                float4 bq0 = *reinterpret_cast<const float4*>(&Bsb[kk * BN + c0]);
                rb[0] = pack2(bq0.x, bq0.y);
                rb[1] = pack2(bq0.z, bq0.w);
                if (TN == 8) {
                    float4 bq1 = *reinterpret_cast<const float4*>(&Bsb[kk * BN + c1]);
                    rb[2] = pack2(bq1.x, bq1.y);
                    rb[3] = pack2(bq1.z, bq1.w);
                }
            }
            #pragma unroll
            for (int i = 0; i < TM; i++) {
                ull ai = pack2(ra[i], ra[i]);
                #pragma unroll
                for (int j = 0; j < TN / 2; j++) fma2(acc[i][j], ai, rb[j]);
            }
        }
        if (kt + 1 < NT) {
            float* Asn = smem + (cur ^ 1) * BK * BM;
            float* Bsn = smem + 2 * BK * BM + (cur ^ 1) * BK * BN;
            #pragma unroll
            for (int it = 0; it < N4A; it++) {
                int r = ar + it * 64;
                Asn[(akk + 0) * BM + r] = pa[it].x; Asn[(akk + 1) * BM + r] = pa[it].y;
                Asn[(akk + 2) * BM + r] = pa[it].z; Asn[(akk + 3) * BM + r] = pa[it].w;
            }
            #pragma unroll
            for (int it = 0; it < N4B; it++) {
                int cc = bcc + it * 64;
                *reinterpret_cast<float4*>(&Bsn[bkk * BN + cc]) = pb[it];
            }
        }
        __syncthreads();
    }

    float bb[TN];
    if (BIAS_RELU) {
        #pragma unroll
        for (int j = 0; j < TN; j++)
            bb[j] = bias[block_n + ((j < 4) ? (c0 + j) : (c1 + j - 4))];
    }
    float ps[TN], ps2[TN];
    #pragma unroll
    for (int j = 0; j < TN; j++) { ps[j] = 0.f; ps2[j] = 0.f; }

    #pragma unroll
    for (int i = 0; i < TM; i++) {
        float v[TN];
        #pragma unroll
        for (int j = 0; j < TN / 2; j++) {
            float2 u = unpack2(acc[i][j]);
            v[j * 2] = u.x; v[j * 2 + 1] = u.y;
        }
        #pragma unroll
        for (int j = 0; j < TN; j++) {
            if (BIAS_RELU) v[j] = fmaxf(v[j] + bb[j], 0.f);
            if (STATS) { ps[j] += v[j]; ps2[j] = fmaf(v[j], v[j], ps2[j]); }
        }
        int r = block_m + ty * TM + i;
        *reinterpret_cast<float4*>(&Cmat[(size_t)r * N + block_n + c0]) =
            make_float4(v[0], v[1], v[2], v[3]);
        if (TN == 8)
            *reinterpret_cast<float4*>(&Cmat[(size_t)r * N + block_n + c1]) =
                make_float4(v[4], v[5], v[6], v[7]);
    }

    if (STATS) {
        #pragma unroll
        for (int j = 0; j < TN; j++) {
            int col = (j < 4) ? (c0 + j) : (c1 + j - 4);
            smem[ty * BN + col]           = ps[j];
            smem[16 * BN + ty * BN + col] = ps2[j];
        }
        __syncthreads();
        if (t < BN) {
            float s = 0.f, s2 = 0.f;
            #pragma unroll
            for (int g = 0; g < 16; g++) { s += smem[g * BN + t]; s2 += smem[16 * BN + g * BN + t]; }
            atomicAdd(&g_sum[block_n + t],   (double)s);
            atomicAdd(&g_sumsq[block_n + t], (double)s2);
        }
    }
}

// ---------------------------------------------------------------------------
// Layer-1 edge GEMM: A recomputed on the fly (unchanged, conflict-free B).
// ---------------------------------------------------------------------------
__global__ void __launch_bounds__(256)
gemm_edge1(const float* __restrict__ PQ, const int* __restrict__ IDXp,
           const float* __restrict__ abias, const float* __restrict__ W,
           const float* __restrict__ obias, float* __restrict__ H) {
    __shared__ float As[16 * 128];
    __shared__ float Bs[16 * 64];
    __shared__ int   s_bi[128], s_qo[128];
    __shared__ float s_ab[64];
    int t = threadIdx.x;
    int block_m = blockIdx.x * 128;
    if (t < 128) {
        int e = block_m + t;
        int bi = e / KNN;
        s_bi[t] = bi;
        s_qo[t] = ((bi >> 10) << 10) + IDXp[e];
    }
    if (t < 64) s_ab[t] = abias[t];
    __syncthreads();

    int tx = t & 15, ty = t >> 4;
    ull acc[8][2];
    #pragma unroll
    for (int i = 0; i < 8; i++) { acc[i][0] = 0ull; acc[i][1] = 0ull; }

    for (int k0 = 0; k0 < 64; k0 += 16) {
        {
            int r  = t >> 1;
            int co = (t & 1) * 8;
            int bi = s_bi[r], qo = s_qo[r];
            const float* Pp = PQ + (size_t)bi * 128 + k0 + co;
            const float* Qp = PQ + (size_t)qo * 128 + 64 + k0 + co;
            float4 p0 = *reinterpret_cast<const float4*>(Pp);
            float4 p1 = *reinterpret_cast<const float4*>(Pp + 4);
            float4 q0 = *reinterpret_cast<const float4*>(Qp);
            float4 q1 = *reinterpret_cast<const float4*>(Qp + 4);
            As[(co + 0) * 128 + r] = fmaxf(p0.x + q0.x + s_ab[k0 + co + 0], 0.f);
            As[(co + 1) * 128 + r] = fmaxf(p0.y + q0.y + s_ab[k0 + co + 1], 0.f);
            As[(co + 2) * 128 + r] = fmaxf(p0.z + q0.z + s_ab[k0 + co + 2], 0.f);
            As[(co + 3) * 128 + r] = fmaxf(p0.w + q0.w + s_ab[k0 + co + 3], 0.f);
            As[(co + 4) * 128 + r] = fmaxf(p1.x + q1.x + s_ab[k0 + co + 4], 0.f);
            As[(co + 5) * 128 + r] = fmaxf(p1.y + q1.y + s_ab[k0 + co + 5], 0.f);
            As[(co + 6) * 128 + r] = fmaxf(p1.z + q1.z + s_ab[k0 + co + 6], 0.f);
            As[(co + 7) * 128 + r] = fmaxf(p1.w + q1.w + s_ab[k0 + co + 7], 0.f);
        }
        {
            int kk = t >> 4, cc = (t & 15) * 4;
            *reinterpret_cast<float4*>(&Bs[kk * 64 + cc]) =
                *reinterpret_cast<const float4*>(&W[(size_t)(k0 + kk) * 64 + cc]);
        }
        __syncthreads();
        #pragma unroll
        for (int kk = 0; kk < 16; kk++) {
            float4 a0 = *reinterpret_cast<const float4*>(&As[kk * 128 + ty * 8]);
            float4 a1 = *reinterpret_cast<const float4*>(&As[kk * 128 + ty * 8 + 4]);
            float4 b0 = *reinterpret_cast<const float4*>(&Bs[kk * 64 + tx * 4]);
            ull rb0 = pack2(b0.x, b0.y), rb1 = pack2(b0.z, b0.w);
            float ra[8] = {a0.x, a0.y, a0.z, a0.w, a1.x, a1.y, a1.z, a1.w};
            #pragma unroll
            for (int i = 0; i < 8; i++) {
                ull ai = pack2(ra[i], ra[i]);
                fma2(acc[i][0], ai, rb0);
                fma2(acc[i][1], ai, rb1);
            }
        }
        __syncthreads();
    }
    float ob[4];
    #pragma unroll
    for (int j = 0; j < 4; j++) ob[j] = obias[tx * 4 + j];
    float ps[4] = {0, 0, 0, 0}, ps2[4] = {0, 0, 0, 0};
    #pragma unroll
    for (int i = 0; i < 8; i++) {
        float2 u0 = unpack2(acc[i][0]), u1 = unpack2(acc[i][1]);
        float v[4] = {u0.x, u0.y, u1.x, u1.y};
        #pragma unroll
        for (int j = 0; j < 4; j++) {
            v[j] = fmaxf(v[j] + ob[j], 0.f);
            ps[j] += v[j]; ps2[j] = fmaf(v[j], v[j], ps2[j]);
        }
        int r = block_m + ty * 8 + i;
        *reinterpret_cast<float4*>(&H[(size_t)r * 64 + tx * 4]) =
            make_float4(v[0], v[1], v[2], v[3]);
    }
    #pragma unroll
    for (int j = 0; j < 4; j++) {
        As[ty * 64 + tx * 4 + j]        = ps[j];
        As[1024 + ty * 64 + tx * 4 + j] = ps2[j];
    }
    __syncthreads();
    if (t < 64) {
        float s = 0.f, s2 = 0.f;
        #pragma unroll
        for (int g = 0; g < 16; g++) { s += As[g * 64 + t]; s2 += As[1024 + g * 64 + t]; }
        atomicAdd(&g_sum[t],   (double)s);
        atomicAdd(&g_sumsq[t], (double)s2);
    }
}

// ---------------------------------------------------------------------------
// Conv1: stats of recomputed edge features relu(P+Q+b)
// ---------------------------------------------------------------------------
template <int CH>
__global__ void stats_edges_kernel(const float* __restrict__ PQ,
                                   const int* __restrict__ IDXp,
                                   const float* __restrict__ bias) {
    constexpr int G = 256 / CH;
    int c = threadIdx.x % CH;
    int g = threadIdx.x / CH;
    float bb = bias[c];
    float s = 0.f, s2 = 0.f;
    for (int node = blockIdx.x * G + g; node < NROW; node += 128 * G) {
        float p = PQ[(size_t)node * (2 * CH) + c] + bb;
        int base = (node >> 10) << 10;
        const int* ix = IDXp + node * KNN;
        #pragma unroll 5
        for (int kk = 0; kk < KNN; kk++) {
            int j = base + ix[kk];
            float v = fmaxf(p + PQ[(size_t)j * (2 * CH) + CH + c], 0.f);
            s += v; s2 = fmaf(v, v, s2);
        }
    }
    __shared__ float sh[2][256];
    sh[0][threadIdx.x] = s; sh[1][threadIdx.x] = s2;
    __syncthreads();
    if (g == 0) {
        #pragma unroll
        for (int gg = 1; gg < G; gg++) { s += sh[0][gg * CH + c]; s2 += sh[1][gg * CH + c]; }
        atomicAdd(&g_sum[c],   (double)s);
        atomicAdd(&g_sumsq[c], (double)s2);
    }
}

// ---------------------------------------------------------------------------
// Conv2: fused stats + per-node max/min of recomputed edge features (1 pass)
// ---------------------------------------------------------------------------
__global__ void stats_minmax_edges_kernel(const float* __restrict__ PQ2,
                                          const int* __restrict__ IDXp,
                                          const float* __restrict__ bias,
                                          float* __restrict__ vmax,
                                          float* __restrict__ vmin) {
    int c = threadIdx.x & 127;
    int g = threadIdx.x >> 7;          // 0..1
    float bb = bias[c];
    float s = 0.f, s2 = 0.f;
    for (int node = blockIdx.x * 2 + g; node < NROW; node += 256) {
        float p = PQ2[(size_t)node * 256 + c] + bb;
        int base = (node >> 10) << 10;
        const int* ix = IDXp + node * KNN;
        float mx = -3.4e38f, mn = 3.4e38f;
        #pragma unroll 5
        for (int kk = 0; kk < KNN; kk++) {
            int j = base + ix[kk];
            float v = fmaxf(p + PQ2[(size_t)j * 256 + 128 + c], 0.f);
            s += v; s2 = fmaf(v, v, s2);
            mx = fmaxf(mx, v); mn = fminf(mn, v);
        }
        vmax[(size_t)node * 128 + c] = mx;
        vmin[(size_t)node * 128 + c] = mn;
    }
    __shared__ float sh[2][256];
    sh[0][threadIdx.x] = s; sh[1][threadIdx.x] = s2;
    __syncthreads();
    if (g == 0) {
        s  += sh[0][128 + c];
        s2 += sh[1][128 + c];
        atomicAdd(&g_sum[c],   (double)s);
        atomicAdd(&g_sumsq[c], (double)s2);
    }
}

// hcat[bi,64+c] = s>=0 ? s*vmax+cc : s*vmin+cc
__global__ void apply_minmax_kernel(const float* __restrict__ vmax,
                                    const float* __restrict__ vmin,
                                    float* __restrict__ hcat) {
    int i = blockIdx.x * 256 + threadIdx.x;   // NROW*128
    int c = i & 127, bi = i >> 7;
    float s = g_sc[c], cc = g_cc[c];
    float v = (s >= 0.f) ? vmax[i] : vmin[i];
    hcat[(size_t)bi * 192 + 64 + c] = fmaf(s, v, cc);
}

// ---------------------------------------------------------------------------
template <int CH>
__global__ void finalize_kernel(const float* __restrict__ gam,
                                const float* __restrict__ bet, int E) {
    int c = threadIdx.x;   // 128
    if (c < CH) {
        double mu  = g_sum[c] / (double)E;
        double var = g_sumsq[c] / (double)E - mu * mu;
        float s = gam[c] * rsqrtf((float)var + 1e-5f);
        g_sc[c] = s;
        g_cc[c] = bet[c] - (float)mu * s;
    }
    g_sum[c] = 0.0; g_sumsq[c] = 0.0;
}

__global__ void fold_kernel(const float* __restrict__ gam, const float* __restrict__ bet,
                            const float* __restrict__ W, const float* __restrict__ bias,
                            int E, float* __restrict__ Wf, float* __restrict__ bf) {
    __shared__ float s_s[64], s_c[64];
    int t = threadIdx.x;   // 256
    if (t < 64) {
        double mu  = g_sum[t] / (double)E;
        double var = g_sumsq[t] / (double)E - mu * mu;
        float s = gam[t] * rsqrtf((float)var + 1e-5f);
        s_s[t] = s;
        s_c[t] = bet[t] - (float)mu * s;
        g_sum[t] = 0.0; g_sumsq[t] = 0.0;
    } else if (t < 128) {
        g_sum[t] = 0.0; g_sumsq[t] = 0.0;
    }
    __syncthreads();
    for (int e = t; e < 64 * 64; e += 256) Wf[e] = s_s[e >> 6] * W[e];
    if (t < 64) {
        float acc = bias[t];
        #pragma unroll 4
        for (int kk = 0; kk < 64; kk++) acc = fmaf(s_c[kk], W[kk * 64 + t], acc);
        bf[t] = acc;
    }
}

// ---------------------------------------------------------------------------
__global__ void maxagg1_kernel(const float* __restrict__ H, float* __restrict__ hcat,
                               float* __restrict__ x1, float* __restrict__ sq) {
    int bi = blockIdx.x;
    int c  = threadIdx.x;   // 64
    const float* h = H + (size_t)bi * (KNN * 64) + c;
    float s = g_sc[c], cc = g_cc[c];
    float m = -3.4e38f;
    #pragma unroll
    for (int kk = 0; kk < KNN; kk++) m = fmaxf(m, fmaf(s, h[kk * 64], cc));
    hcat[(size_t)bi * 192 + c] = m;
    x1[(size_t)bi * 64 + c]    = m;
    float q = m * m;
    #pragma unroll
    for (int o = 16; o; o >>= 1) q += __shfl_xor_sync(0xffffffffu, q, o);
    __shared__ float sh[2];
    if ((c & 31) == 0) sh[c >> 5] = q;
    __syncthreads();
    if (c == 0) sq[bi] = sh[0] + sh[1];
}

__global__ void apply_bn_kernel(const float* __restrict__ Y, float* __restrict__ out) {
    int i = blockIdx.x * 256 + threadIdx.x;
    int c = i & 127;
    out[i] = fmaf(g_sc[c], Y[i], g_cc[c]);
}

// ---------------------------------------------------------------------------
extern "C" void kernel_launch(void* const* d_in, const int* in_sizes, int n_in,
                              void* d_out, int out_size) {
    const float* x0    = (const float*)d_in[1];
    const float* c1w0  = (const float*)d_in[2];
    const float* c1b0  = (const float*)d_in[3];
    const float* c1g0  = (const float*)d_in[4];
    const float* c1be0 = (const float*)d_in[5];
    const float* c1w1  = (const float*)d_in[6];
    const float* c1b1  = (const float*)d_in[7];
    const float* c1g1  = (const float*)d_in[8];
    const float* c1be1 = (const float*)d_in[9];
    const float* c1w2  = (const float*)d_in[10];
    const float* c1b2  = (const float*)d_in[11];
    const float* c1g2  = (const float*)d_in[12];
    const float* c1be2 = (const float*)d_in[13];
    const float* c2w0  = (const float*)d_in[14];
    const float* c2b0  = (const float*)d_in[15];
    const float* c2g0  = (const float*)d_in[16];
    const float* c2be0 = (const float*)d_in[17];
    const float* lw    = (const float*)d_in[18];
    const float* lb    = (const float*)d_in[19];
    const float* lg    = (const float*)d_in[20];
    const float* lbe   = (const float*)d_in[21];
    float* out = (float*)d_out;

    void* sp = nullptr; cudaGetSymbolAddress(&sp, g_scratch);
    float* S = (float*)sp;
    void* ip = nullptr; cudaGetSymbolAddress(&ip, g_knn_idx);
    int* IDX = (int*)ip;

    float* D     = S + OFF_D;
    float* PQ    = S + OFF_PQ;
    float* PQ2   = S + OFF_PQ2;
    float* H1    = S + OFF_H1;
    float* H2    = S + OFF_H2;
    float* HCAT  = S + OFF_HCAT;
    float* X1    = S + OFF_X1;
    float* Y0    = S + OFF_Y0;
    float* SQ    = S + OFF_SQ;
    float* WCAT  = S + OFF_WCAT;
    float* WCAT2 = S + OFF_WCAT2;
    float* WF    = S + OFF_WF;
    float* BF    = S + OFF_BF;
    float* VMAX  = S + OFF_H1;                       // H1 dead by conv2
    float* VMIN  = S + OFF_H1 + (size_t)NROW * 128;

    // dependency-free weight prep first => ncu capture slot lands on dist1
    build_wcat1<<<128, 256>>>(c1w0, WCAT);
    build_wcat2<<<64, 256>>>(c2w0, WCAT2);
    rowsq_kernel<256><<<NROW, 32>>>(x0, SQ);

    // ---- EdgeConv 1 ----
    dist_kernel<256><<<dim3(36, 1, 8), 256>>>(x0, SQ, D);
    topk_kernel<<<NROW / 8, 256>>>(D, IDX);
    gemm_nodes<128, 64, 8, 4, false, false><<<dim3(2, NROW / 128), 256>>>(x0, WCAT, nullptr, PQ, NROW, 128, 256);
    stats_edges_kernel<64><<<128, 256>>>(PQ, IDX, c1b0);
    fold_kernel<<<1, 256>>>(c1g0, c1be0, c1w1, c1b1, NEDGE, WF, BF);
    gemm_edge1<<<NEDGE / 128, 256>>>(PQ, IDX, c1b0, WF, BF, H1);
    fold_kernel<<<1, 256>>>(c1g1, c1be1, c1w2, c1b2, NEDGE, WF, BF);
    gemm_nodes<128, 64, 8, 4, true, true><<<dim3(1, NEDGE / 128), 256>>>(H1, WF, BF, H2, NEDGE, 64, 64);
    finalize_kernel<64><<<1, 128>>>(c1g2, c1be2, NEDGE);
    maxagg1_kernel<<<NROW, 64>>>(H2, HCAT, X1, SQ);

    // ---- EdgeConv 2 ----
    dist_kernel<64><<<dim3(36, 1, 8), 256>>>(X1, SQ, D);
    topk_kernel<<<NROW / 8, 256>>>(D, IDX);
    gemm_nodes<128, 128, 8, 8, false, false><<<dim3(2, NROW / 128), 256>>>(X1, WCAT2, nullptr, PQ2, NROW, 256, 64);
    stats_minmax_edges_kernel<<<128, 256>>>(PQ2, IDX, c2b0, VMAX, VMIN);
    finalize_kernel<128><<<1, 128>>>(c2g0, c2be0, NEDGE);
    apply_minmax_kernel<<<NROW * 128 / 256, 256>>>(VMAX, VMIN, HCAT);

    // ---- Final Linear + BN ----
    gemm_nodes<128, 64, 8, 4, true, true><<<dim3(2, NROW / 128), 256>>>(HCAT, lw, lb, Y0, NROW, 128, 192);
    finalize_kernel<128><<<1, 128>>>(lg, lbe, NROW);
    apply_bn_kernel<<<NROW * 128 / 256, 256>>>(Y0, out);
}

// round 13
// speedup vs baseline: 1.2882x; 1.1726x over previous
#include <cuda_runtime.h>
#include <cstdint>

// ---------------------------------------------------------------------------
// DGCNN: 2x EdgeConv (dynamic kNN) + final MLP, training-mode BatchNorm.
// R13 = R12 + stats gather kernels launched with 512 blocks (was 128, <1
// block/SM) with gridDim-based strides: 4x parallelism on the latency-bound
// kNN gathers.
// ---------------------------------------------------------------------------

typedef unsigned long long ull;

namespace cfg {
constexpr int BB   = 8;
constexpr int NN_  = 1024;
constexpr int KNN  = 20;
constexpr int NROW  = BB * NN_;        // 8192
constexpr int NEDGE = NROW * KNN;      // 163840

constexpr size_t OFF_D    = 0;
constexpr size_t SZ_D     = (size_t)BB * NN_ * NN_;
constexpr size_t OFF_PQ   = OFF_D + SZ_D;
constexpr size_t SZ_PQ    = (size_t)NROW * 128;
constexpr size_t OFF_PQ2  = OFF_PQ + SZ_PQ;
constexpr size_t SZ_PQ2   = (size_t)NROW * 256;
constexpr size_t OFF_H1   = OFF_PQ2 + SZ_PQ2;
constexpr size_t SZ_H64   = (size_t)NEDGE * 64;
constexpr size_t OFF_H2   = OFF_H1 + SZ_H64;
constexpr size_t OFF_HCAT = OFF_H2 + SZ_H64;
constexpr size_t SZ_HCAT  = (size_t)NROW * 192;
constexpr size_t OFF_X1   = OFF_HCAT + SZ_HCAT;
constexpr size_t SZ_X1    = (size_t)NROW * 64;
constexpr size_t OFF_Y0   = OFF_X1 + SZ_X1;
constexpr size_t SZ_Y0    = (size_t)NROW * 128;
constexpr size_t OFF_SQ   = OFF_Y0 + SZ_Y0;
constexpr size_t SZ_SQ    = (size_t)NROW;
constexpr size_t OFF_WCAT = OFF_SQ + SZ_SQ;
constexpr size_t SZ_WCAT  = 256 * 128;
constexpr size_t OFF_WCAT2= OFF_WCAT + SZ_WCAT;
constexpr size_t SZ_WCAT2 = 64 * 256;
constexpr size_t OFF_WF   = OFF_WCAT2 + SZ_WCAT2;
constexpr size_t SZ_WF    = 64 * 64;
constexpr size_t OFF_BF   = OFF_WF + SZ_WF;
constexpr size_t SZ_BF    = 128;
constexpr size_t SCRATCH_TOTAL = OFF_BF + SZ_BF;
}  // namespace cfg
using namespace cfg;

__device__ float  g_scratch[SCRATCH_TOTAL];
__device__ int    g_knn_idx[NEDGE];
__device__ double g_sum[128];
__device__ double g_sumsq[128];
__device__ float  g_sc[128];
__device__ float  g_cc[128];

// ---------------------------------------------------------------------------
__device__ __forceinline__ ull pack2(float x, float y) {
    ull r; asm("mov.b64 %0, {%1, %2};" : "=l"(r) : "f"(x), "f"(y)); return r;
}
__device__ __forceinline__ void fma2(ull& d, ull a, ull b) {
    asm("fma.rn.f32x2 %0, %1, %2, %0;" : "+l"(d) : "l"(a), "l"(b));
}
__device__ __forceinline__ float2 unpack2(ull v) {
    float2 f; asm("mov.b64 {%0, %1}, %2;" : "=f"(f.x), "=f"(f.y) : "l"(v)); return f;
}

// ---------------------------------------------------------------------------
__global__ void build_wcat1(const float* __restrict__ W0, float* __restrict__ Wcat) {
    int e = blockIdx.x * 256 + threadIdx.x;    // 256*128
    int kk = e >> 7, n = e & 127;
    float v;
    if (n < 64) v = W0[kk * 64 + n] - W0[(kk + 256) * 64 + n];
    else        v = W0[(kk + 256) * 64 + (n - 64)];
    Wcat[e] = v;
}
__global__ void build_wcat2(const float* __restrict__ W0, float* __restrict__ Wcat) {
    int e = blockIdx.x * 256 + threadIdx.x;    // 64*256
    int kk = e >> 8, n = e & 255;
    float v;
    if (n < 128) v = W0[kk * 128 + n] - W0[(kk + 64) * 128 + n];
    else         v = W0[(kk + 64) * 128 + (n - 128)];
    Wcat[e] = v;
}

// ---------------------------------------------------------------------------
template <int C>
__global__ void rowsq_kernel(const float* __restrict__ X, float* __restrict__ sq) {
    int row = blockIdx.x;
    const float* x = X + (size_t)row * C;
    float a = 0.f;
    #pragma unroll
    for (int c = threadIdx.x; c < C; c += 32) { float v = x[c]; a = fmaf(v, v, a); }
    #pragma unroll
    for (int o = 16; o; o >>= 1) a += __shfl_xor_sync(0xffffffffu, a, o);
    if (threadIdx.x == 0) sq[row] = a;
}

// ---------------------------------------------------------------------------
// Distance matrix: symmetric triangular tiles, split-half B cols,
// double-buffered smem pipeline (1 barrier per K-step).
// ---------------------------------------------------------------------------
template <int C>
__global__ void __launch_bounds__(256, 2)
dist_kernel(const float* __restrict__ X, const float* __restrict__ sq,
            float* __restrict__ D) {
    __shared__ float As[2][16][128];
    __shared__ float Bs[2][16][128];
    int b  = blockIdx.z;
    const float* Xb  = X  + (size_t)b * NN_ * C;
    const float* sqb = sq + (size_t)b * NN_;
    float* Db = D + (size_t)b * NN_ * NN_;

    int rem = blockIdx.x, bi = 0;
    while (rem >= 8 - bi) { rem -= 8 - bi; bi++; }
    int bj = bi + rem;
    int i0 = bi * 128, j0 = bj * 128;

    int t  = threadIdx.x;
    int tx = t & 15, ty = t >> 4;
    int c0 = tx * 4;
    int c1 = 64 + tx * 4;

    int lr0 = (t >> 2), lr1 = lr0 + 64;
    int lkk = (t & 3) * 4;

    ull acc[8][4];
    #pragma unroll
    for (int i = 0; i < 8; i++)
        #pragma unroll
        for (int j = 0; j < 4; j++) acc[i][j] = 0ull;

    {
        float4 va0 = *reinterpret_cast<const float4*>(&Xb[(size_t)(i0 + lr0) * C + lkk]);
        float4 va1 = *reinterpret_cast<const float4*>(&Xb[(size_t)(i0 + lr1) * C + lkk]);
        float4 vb0 = *reinterpret_cast<const float4*>(&Xb[(size_t)(j0 + lr0) * C + lkk]);
        float4 vb1 = *reinterpret_cast<const float4*>(&Xb[(size_t)(j0 + lr1) * C + lkk]);
        As[0][lkk + 0][lr0] = va0.x; As[0][lkk + 1][lr0] = va0.y;
        As[0][lkk + 2][lr0] = va0.z; As[0][lkk + 3][lr0] = va0.w;
        As[0][lkk + 0][lr1] = va1.x; As[0][lkk + 1][lr1] = va1.y;
        As[0][lkk + 2][lr1] = va1.z; As[0][lkk + 3][lr1] = va1.w;
        Bs[0][lkk + 0][lr0] = vb0.x; Bs[0][lkk + 1][lr0] = vb0.y;
        Bs[0][lkk + 2][lr0] = vb0.z; Bs[0][lkk + 3][lr0] = vb0.w;
        Bs[0][lkk + 0][lr1] = vb1.x; Bs[0][lkk + 1][lr1] = vb1.y;
        Bs[0][lkk + 2][lr1] = vb1.z; Bs[0][lkk + 3][lr1] = vb1.w;
    }
    __syncthreads();

    constexpr int NT = C / 16;
    for (int kt = 0; kt < NT; kt++) {
        int cur = kt & 1;
        float4 pa0, pa1, pb0, pb1;
        if (kt + 1 < NT) {
            int k0n = (kt + 1) * 16;
            pa0 = *reinterpret_cast<const float4*>(&Xb[(size_t)(i0 + lr0) * C + k0n + lkk]);
            pa1 = *reinterpret_cast<const float4*>(&Xb[(size_t)(i0 + lr1) * C + k0n + lkk]);
            pb0 = *reinterpret_cast<const float4*>(&Xb[(size_t)(j0 + lr0) * C + k0n + lkk]);
            pb1 = *reinterpret_cast<const float4*>(&Xb[(size_t)(j0 + lr1) * C + k0n + lkk]);
        }
        #pragma unroll
        for (int kk = 0; kk < 16; kk++) {
            float4 a0 = *reinterpret_cast<const float4*>(&As[cur][kk][ty * 8]);
            float4 a1 = *reinterpret_cast<const float4*>(&As[cur][kk][ty * 8 + 4]);
            float4 b0 = *reinterpret_cast<const float4*>(&Bs[cur][kk][c0]);
            float4 b1 = *reinterpret_cast<const float4*>(&Bs[cur][kk][c1]);
            ull rb[4] = {pack2(b0.x, b0.y), pack2(b0.z, b0.w),
                         pack2(b1.x, b1.y), pack2(b1.z, b1.w)};
            float ra[8] = {a0.x, a0.y, a0.z, a0.w, a1.x, a1.y, a1.z, a1.w};
            #pragma unroll
            for (int i = 0; i < 8; i++) {
                ull ai = pack2(ra[i], ra[i]);
                #pragma unroll
                for (int j = 0; j < 4; j++) fma2(acc[i][j], ai, rb[j]);
            }
        }
        if (kt + 1 < NT) {
            int nxt = cur ^ 1;
            As[nxt][lkk + 0][lr0] = pa0.x; As[nxt][lkk + 1][lr0] = pa0.y;
            As[nxt][lkk + 2][lr0] = pa0.z; As[nxt][lkk + 3][lr0] = pa0.w;
            As[nxt][lkk + 0][lr1] = pa1.x; As[nxt][lkk + 1][lr1] = pa1.y;
            As[nxt][lkk + 2][lr1] = pa1.z; As[nxt][lkk + 3][lr1] = pa1.w;
            Bs[nxt][lkk + 0][lr0] = pb0.x; Bs[nxt][lkk + 1][lr0] = pb0.y;
            Bs[nxt][lkk + 2][lr0] = pb0.z; Bs[nxt][lkk + 3][lr0] = pb0.w;
            Bs[nxt][lkk + 0][lr1] = pb1.x; Bs[nxt][lkk + 1][lr1] = pb1.y;
            Bs[nxt][lkk + 2][lr1] = pb1.z; Bs[nxt][lkk + 3][lr1] = pb1.w;
        }
        __syncthreads();
    }

    float sj[8];
    #pragma unroll
    for (int j = 0; j < 4; j++) { sj[j] = sqb[j0 + c0 + j]; sj[4 + j] = sqb[j0 + c1 + j]; }

    float o[8][8];
    #pragma unroll
    for (int i = 0; i < 8; i++) {
        float si = sqb[i0 + ty * 8 + i];
        #pragma unroll
        for (int j = 0; j < 4; j++) {
            float2 u = unpack2(acc[i][j]);
            o[i][j * 2]     = si + sj[j * 2]     - 2.f * u.x;
            o[i][j * 2 + 1] = si + sj[j * 2 + 1] - 2.f * u.y;
        }
    }
    #pragma unroll
    for (int i = 0; i < 8; i++) {
        int gi = i0 + ty * 8 + i;
        *reinterpret_cast<float4*>(&Db[(size_t)gi * NN_ + j0 + c0]) =
            make_float4(o[i][0], o[i][1], o[i][2], o[i][3]);
        *reinterpret_cast<float4*>(&Db[(size_t)gi * NN_ + j0 + c1]) =
            make_float4(o[i][4], o[i][5], o[i][6], o[i][7]);
    }
    if (bi != bj) {
        #pragma unroll
        for (int j = 0; j < 8; j++) {
            int gj = j0 + ((j < 4) ? (c0 + j) : (c1 + j - 4));
            float4* dst = reinterpret_cast<float4*>(&Db[(size_t)gj * NN_ + i0 + ty * 8]);
            dst[0] = make_float4(o[0][j], o[1][j], o[2][j], o[3][j]);
            dst[1] = make_float4(o[4][j], o[5][j], o[6][j], o[7][j]);
        }
    }
}

// ---------------------------------------------------------------------------
// Top-20 smallest per row; one warp per row; tree-min + equality mask.
// ---------------------------------------------------------------------------
__global__ void topk_kernel(const float* __restrict__ D, int* __restrict__ idx) {
    int row  = blockIdx.x * 8 + (threadIdx.x >> 5);
    int lane = threadIdx.x & 31;
    const float4* d4 = reinterpret_cast<const float4*>(D + (size_t)row * NN_);
    float v[32];
    #pragma unroll
    for (int q = 0; q < 8; q++) {
        float4 x = d4[lane + 32 * q];
        v[4 * q + 0] = x.x; v[4 * q + 1] = x.y;
        v[4 * q + 2] = x.z; v[4 * q + 3] = x.w;
    }

    for (int s = 0; s < KNN; s++) {
        float m16[16];
        #pragma unroll
        for (int q = 0; q < 16; q++) m16[q] = fminf(v[q], v[q + 16]);
        float m8[8];
        #pragma unroll
        for (int q = 0; q < 8; q++) m8[q] = fminf(m16[q], m16[q + 8]);
        float m4[4];
        #pragma unroll
        for (int q = 0; q < 4; q++) m4[q] = fminf(m8[q], m8[q + 4]);
        float m2a = fminf(m4[0], m4[2]), m2b = fminf(m4[1], m4[3]);
        float m = fminf(m2a, m2b);
        unsigned mask = 0u;
        #pragma unroll
        for (int q = 0; q < 32; q++) mask |= (v[q] == m) ? (1u << q) : 0u;
        int slot = __ffs(mask) - 1;
        int gidx = 4 * lane + 128 * (slot >> 2) + (slot & 3);

        float bm = m; int bidx = gidx;
        #pragma unroll
        for (int o = 16; o; o >>= 1) {
            float om = __shfl_xor_sync(0xffffffffu, bm, o);
            int   oi = __shfl_xor_sync(0xffffffffu, bidx, o);
            if (om < bm || (om == bm && oi < bidx)) { bm = om; bidx = oi; }
        }
        if (lane == 0) idx[row * KNN + s] = bidx;
        int wl = (bidx >> 2) & 31;
        if (lane == wl) {
            int ws = 4 * (bidx >> 7) + (bidx & 3);
            #pragma unroll
            for (int q = 0; q < 32; q++) if (q == ws) v[q] = 3.4e38f;
        }
    }
}

// ---------------------------------------------------------------------------
// Generic fp32 GEMM (f32x2, split-half cols for TN==8), double-buffered smem.
// ---------------------------------------------------------------------------
template <int BM, int BN, int TM, int TN, bool BIAS_RELU, bool STATS>
__global__ void __launch_bounds__(256, 2)
gemm_nodes(const float* __restrict__ A, const float* __restrict__ Bm,
           const float* __restrict__ bias, float* __restrict__ Cmat,
           int M, int N, int K) {
    constexpr int BK = 16;
    constexpr int TX = BN / TN;
    static_assert(TX == 16 && (256 / TX) * TM == BM, "layout");
    constexpr int N4A = BM / 64;
    constexpr int N4B = BN / 64;
    __shared__ float smem[2 * BK * (BM + BN)];
    int block_m = blockIdx.y * BM, block_n = blockIdx.x * BN;
    int t  = threadIdx.x;
    int tx = t % TX, ty = t / TX;
    int c0 = tx * 4;
    int c1 = BN / 2 + tx * 4;

    int ar  = t >> 2;
    int akk = (t & 3) * 4;
    int bkk = t >> 4;
    int bcc = (t & 15) * 4;

    ull acc[TM][TN / 2];
    #pragma unroll
    for (int i = 0; i < TM; i++)
        #pragma unroll
        for (int j = 0; j < TN / 2; j++) acc[i][j] = 0ull;

    {
        float* As0 = smem;
        float* Bs0 = smem + 2 * BK * BM;
        #pragma unroll
        for (int it = 0; it < N4A; it++) {
            int r = ar + it * 64;
            float4 v = *reinterpret_cast<const float4*>(&A[(size_t)(block_m + r) * K + akk]);
            As0[(akk + 0) * BM + r] = v.x; As0[(akk + 1) * BM + r] = v.y;
            As0[(akk + 2) * BM + r] = v.z; As0[(akk + 3) * BM + r] = v.w;
        }
        #pragma unroll
        for (int it = 0; it < N4B; it++) {
            int cc = bcc + it * 64;
            *reinterpret_cast<float4*>(&Bs0[bkk * BN + cc]) =
                *reinterpret_cast<const float4*>(&Bm[(size_t)bkk * N + block_n + cc]);
        }
    }
    __syncthreads();

    int NT = K / BK;
    for (int kt = 0; kt < NT; kt++) {
        int cur = kt & 1;
        float* Asb = smem + cur * BK * BM;
        float* Bsb = smem + 2 * BK * BM + cur * BK * BN;
        float4 pa[N4A], pb[N4B];
        if (kt + 1 < NT) {
            int k0n = (kt + 1) * BK;
            #pragma unroll
            for (int it = 0; it < N4A; it++) {
                int r = ar + it * 64;
                pa[it] = *reinterpret_cast<const float4*>(&A[(size_t)(block_m + r) * K + k0n + akk]);
            }
            #pragma unroll
            for (int it = 0; it < N4B; it++) {
                int cc = bcc + it * 64;
                pb[it] = *reinterpret_cast<const float4*>(&Bm[(size_t)(k0n + bkk) * N + block_n + cc]);
            }
        }
        #pragma unroll
        for (int kk = 0; kk < BK; kk++) {
            float ra[TM];
            #pragma unroll
            for (int i4 = 0; i4 < TM / 4; i4++) {
                float4 a = *reinterpret_cast<const float4*>(&Asb[kk * BM + ty * TM + i4 * 4]);
                ra[i4 * 4 + 0] = a.x; ra[i4 * 4 + 1] = a.y;
                ra[i4 * 4 + 2] = a.z; ra[i4 * 4 + 3] = a.w;
            }
            ull rb[TN / 2];
            {
                float4 bq0 = *reinterpret_cast<const float4*>(&Bsb[kk * BN + c0]);
                rb[0] = pack2(bq0.x, bq0.y);
                rb[1] = pack2(bq0.z, bq0.w);
                if (TN == 8) {
                    float4 bq1 = *reinterpret_cast<const float4*>(&Bsb[kk * BN + c1]);
                    rb[2] = pack2(bq1.x, bq1.y);
                    rb[3] = pack2(bq1.z, bq1.w);
                }
            }
            #pragma unroll
            for (int i = 0; i < TM; i++) {
                ull ai = pack2(ra[i], ra[i]);
                #pragma unroll
                for (int j = 0; j < TN / 2; j++) fma2(acc[i][j], ai, rb[j]);
            }
        }
        if (kt + 1 < NT) {
            float* Asn = smem + (cur ^ 1) * BK * BM;
            float* Bsn = smem + 2 * BK * BM + (cur ^ 1) * BK * BN;
            #pragma unroll
            for (int it = 0; it < N4A; it++) {
                int r = ar + it * 64;
                Asn[(akk + 0) * BM + r] = pa[it].x; Asn[(akk + 1) * BM + r] = pa[it].y;
                Asn[(akk + 2) * BM + r] = pa[it].z; Asn[(akk + 3) * BM + r] = pa[it].w;
            }
            #pragma unroll
            for (int it = 0; it < N4B; it++) {
                int cc = bcc + it * 64;
                *reinterpret_cast<float4*>(&Bsn[bkk * BN + cc]) = pb[it];
            }
        }
        __syncthreads();
    }

    float bb[TN];
    if (BIAS_RELU) {
        #pragma unroll
        for (int j = 0; j < TN; j++)
            bb[j] = bias[block_n + ((j < 4) ? (c0 + j) : (c1 + j - 4))];
    }
    float ps[TN], ps2[TN];
    #pragma unroll
    for (int j = 0; j < TN; j++) { ps[j] = 0.f; ps2[j] = 0.f; }

    #pragma unroll
    for (int i = 0; i < TM; i++) {
        float v[TN];
        #pragma unroll
        for (int j = 0; j < TN / 2; j++) {
            float2 u = unpack2(acc[i][j]);
            v[j * 2] = u.x; v[j * 2 + 1] = u.y;
        }
        #pragma unroll
        for (int j = 0; j < TN; j++) {
            if (BIAS_RELU) v[j] = fmaxf(v[j] + bb[j], 0.f);
            if (STATS) { ps[j] += v[j]; ps2[j] = fmaf(v[j], v[j], ps2[j]); }
        }
        int r = block_m + ty * TM + i;
        *reinterpret_cast<float4*>(&Cmat[(size_t)r * N + block_n + c0]) =
            make_float4(v[0], v[1], v[2], v[3]);
        if (TN == 8)
            *reinterpret_cast<float4*>(&Cmat[(size_t)r * N + block_n + c1]) =
                make_float4(v[4], v[5], v[6], v[7]);
    }

    if (STATS) {
        #pragma unroll
        for (int j = 0; j < TN; j++) {
            int col = (j < 4) ? (c0 + j) : (c1 + j - 4);
            smem[ty * BN + col]           = ps[j];
            smem[16 * BN + ty * BN + col] = ps2[j];
        }
        __syncthreads();
        if (t < BN) {
            float s = 0.f, s2 = 0.f;
            #pragma unroll
            for (int g = 0; g < 16; g++) { s += smem[g * BN + t]; s2 += smem[16 * BN + g * BN + t]; }
            atomicAdd(&g_sum[block_n + t],   (double)s);
            atomicAdd(&g_sumsq[block_n + t], (double)s2);
        }
    }
}

// ---------------------------------------------------------------------------
// Layer-1 edge GEMM: A recomputed on the fly (conflict-free B).
// ---------------------------------------------------------------------------
__global__ void __launch_bounds__(256)
gemm_edge1(const float* __restrict__ PQ, const int* __restrict__ IDXp,
           const float* __restrict__ abias, const float* __restrict__ W,
           const float* __restrict__ obias, float* __restrict__ H) {
    __shared__ float As[16 * 128];
    __shared__ float Bs[16 * 64];
    __shared__ int   s_bi[128], s_qo[128];
    __shared__ float s_ab[64];
    int t = threadIdx.x;
    int block_m = blockIdx.x * 128;
    if (t < 128) {
        int e = block_m + t;
        int bi = e / KNN;
        s_bi[t] = bi;
        s_qo[t] = ((bi >> 10) << 10) + IDXp[e];
    }
    if (t < 64) s_ab[t] = abias[t];
    __syncthreads();

    int tx = t & 15, ty = t >> 4;
    ull acc[8][2];
    #pragma unroll
    for (int i = 0; i < 8; i++) { acc[i][0] = 0ull; acc[i][1] = 0ull; }

    for (int k0 = 0; k0 < 64; k0 += 16) {
        {
            int r  = t >> 1;
            int co = (t & 1) * 8;
            int bi = s_bi[r], qo = s_qo[r];
            const float* Pp = PQ + (size_t)bi * 128 + k0 + co;
            const float* Qp = PQ + (size_t)qo * 128 + 64 + k0 + co;
            float4 p0 = *reinterpret_cast<const float4*>(Pp);
            float4 p1 = *reinterpret_cast<const float4*>(Pp + 4);
            float4 q0 = *reinterpret_cast<const float4*>(Qp);
            float4 q1 = *reinterpret_cast<const float4*>(Qp + 4);
            As[(co + 0) * 128 + r] = fmaxf(p0.x + q0.x + s_ab[k0 + co + 0], 0.f);
            As[(co + 1) * 128 + r] = fmaxf(p0.y + q0.y + s_ab[k0 + co + 1], 0.f);
            As[(co + 2) * 128 + r] = fmaxf(p0.z + q0.z + s_ab[k0 + co + 2], 0.f);
            As[(co + 3) * 128 + r] = fmaxf(p0.w + q0.w + s_ab[k0 + co + 3], 0.f);
            As[(co + 4) * 128 + r] = fmaxf(p1.x + q1.x + s_ab[k0 + co + 4], 0.f);
            As[(co + 5) * 128 + r] = fmaxf(p1.y + q1.y + s_ab[k0 + co + 5], 0.f);
            As[(co + 6) * 128 + r] = fmaxf(p1.z + q1.z + s_ab[k0 + co + 6], 0.f);
            As[(co + 7) * 128 + r] = fmaxf(p1.w + q1.w + s_ab[k0 + co + 7], 0.f);
        }
        {
            int kk = t >> 4, cc = (t & 15) * 4;
            *reinterpret_cast<float4*>(&Bs[kk * 64 + cc]) =
                *reinterpret_cast<const float4*>(&W[(size_t)(k0 + kk) * 64 + cc]);
        }
        __syncthreads();
        #pragma unroll
        for (int kk = 0; kk < 16; kk++) {
            float4 a0 = *reinterpret_cast<const float4*>(&As[kk * 128 + ty * 8]);
            float4 a1 = *reinterpret_cast<const float4*>(&As[kk * 128 + ty * 8 + 4]);
            float4 b0 = *reinterpret_cast<const float4*>(&Bs[kk * 64 + tx * 4]);
            ull rb0 = pack2(b0.x, b0.y), rb1 = pack2(b0.z, b0.w);
            float ra[8] = {a0.x, a0.y, a0.z, a0.w, a1.x, a1.y, a1.z, a1.w};
            #pragma unroll
            for (int i = 0; i < 8; i++) {
                ull ai = pack2(ra[i], ra[i]);
                fma2(acc[i][0], ai, rb0);
                fma2(acc[i][1], ai, rb1);
            }
        }
        __syncthreads();
    }
    float ob[4];
    #pragma unroll
    for (int j = 0; j < 4; j++) ob[j] = obias[tx * 4 + j];
    float ps[4] = {0, 0, 0, 0}, ps2[4] = {0, 0, 0, 0};
    #pragma unroll
    for (int i = 0; i < 8; i++) {
        float2 u0 = unpack2(acc[i][0]), u1 = unpack2(acc[i][1]);
        float v[4] = {u0.x, u0.y, u1.x, u1.y};
        #pragma unroll
        for (int j = 0; j < 4; j++) {
            v[j] = fmaxf(v[j] + ob[j], 0.f);
            ps[j] += v[j]; ps2[j] = fmaf(v[j], v[j], ps2[j]);
        }
        int r = block_m + ty * 8 + i;
        *reinterpret_cast<float4*>(&H[(size_t)r * 64 + tx * 4]) =
            make_float4(v[0], v[1], v[2], v[3]);
    }
    #pragma unroll
    for (int j = 0; j < 4; j++) {
        As[ty * 64 + tx * 4 + j]        = ps[j];
        As[1024 + ty * 64 + tx * 4 + j] = ps2[j];
    }
    __syncthreads();
    if (t < 64) {
        float s = 0.f, s2 = 0.f;
        #pragma unroll
        for (int g = 0; g < 16; g++) { s += As[g * 64 + t]; s2 += As[1024 + g * 64 + t]; }
        atomicAdd(&g_sum[t],   (double)s);
        atomicAdd(&g_sumsq[t], (double)s2);
    }
}

// ---------------------------------------------------------------------------
// Conv1: stats of recomputed edge features relu(P+Q+b). Grid-stride loop.
// ---------------------------------------------------------------------------
template <int CH>
__global__ void stats_edges_kernel(const float* __restrict__ PQ,
                                   const int* __restrict__ IDXp,
                                   const float* __restrict__ bias) {
    constexpr int G = 256 / CH;
    int c = threadIdx.x % CH;
    int g = threadIdx.x / CH;
    int stride = gridDim.x * G;
    float bb = bias[c];
    float s = 0.f, s2 = 0.f;
    for (int node = blockIdx.x * G + g; node < NROW; node += stride) {
        float p = PQ[(size_t)node * (2 * CH) + c] + bb;
        int base = (node >> 10) << 10;
        const int* ix = IDXp + node * KNN;
        #pragma unroll 5
        for (int kk = 0; kk < KNN; kk++) {
            int j = base + ix[kk];
            float v = fmaxf(p + PQ[(size_t)j * (2 * CH) + CH + c], 0.f);
            s += v; s2 = fmaf(v, v, s2);
        }
    }
    __shared__ float sh[2][256];
    sh[0][threadIdx.x] = s; sh[1][threadIdx.x] = s2;
    __syncthreads();
    if (g == 0) {
        #pragma unroll
        for (int gg = 1; gg < G; gg++) { s += sh[0][gg * CH + c]; s2 += sh[1][gg * CH + c]; }
        atomicAdd(&g_sum[c],   (double)s);
        atomicAdd(&g_sumsq[c], (double)s2);
    }
}

// ---------------------------------------------------------------------------
// Conv2: fused stats + per-node max/min (1 pass). Grid-stride loop.
// ---------------------------------------------------------------------------
__global__ void stats_minmax_edges_kernel(const float* __restrict__ PQ2,
                                          const int* __restrict__ IDXp,
                                          const float* __restrict__ bias,
                                          float* __restrict__ vmax,
                                          float* __restrict__ vmin) {
    int c = threadIdx.x & 127;
    int g = threadIdx.x >> 7;          // 0..1
    int stride = gridDim.x * 2;
    float bb = bias[c];
    float s = 0.f, s2 = 0.f;
    for (int node = blockIdx.x * 2 + g; node < NROW; node += stride) {
        float p = PQ2[(size_t)node * 256 + c] + bb;
        int base = (node >> 10) << 10;
        const int* ix = IDXp + node * KNN;
        float mx = -3.4e38f, mn = 3.4e38f;
        #pragma unroll 5
        for (int kk = 0; kk < KNN; kk++) {
            int j = base + ix[kk];
            float v = fmaxf(p + PQ2[(size_t)j * 256 + 128 + c], 0.f);
            s += v; s2 = fmaf(v, v, s2);
            mx = fmaxf(mx, v); mn = fminf(mn, v);
        }
        vmax[(size_t)node * 128 + c] = mx;
        vmin[(size_t)node * 128 + c] = mn;
    }
    __shared__ float sh[2][256];
    sh[0][threadIdx.x] = s; sh[1][threadIdx.x] = s2;
    __syncthreads();
    if (g == 0) {
        s  += sh[0][128 + c];
        s2 += sh[1][128 + c];
        atomicAdd(&g_sum[c],   (double)s);
        atomicAdd(&g_sumsq[c], (double)s2);
    }
}

// hcat[bi,64+c] = s>=0 ? s*vmax+cc : s*vmin+cc
__global__ void apply_minmax_kernel(const float* __restrict__ vmax,
                                    const float* __restrict__ vmin,
                                    float* __restrict__ hcat) {
    int i = blockIdx.x * 256 + threadIdx.x;   // NROW*128
    int c = i & 127, bi = i >> 7;
    float s = g_sc[c], cc = g_cc[c];
    float v = (s >= 0.f) ? vmax[i] : vmin[i];
    hcat[(size_t)bi * 192 + 64 + c] = fmaf(s, v, cc);
}

// ---------------------------------------------------------------------------
template <int CH>
__global__ void finalize_kernel(const float* __restrict__ gam,
                                const float* __restrict__ bet, int E) {
    int c = threadIdx.x;   // 128
    if (c < CH) {
        double mu  = g_sum[c] / (double)E;
        double var = g_sumsq[c] / (double)E - mu * mu;
        float s = gam[c] * rsqrtf((float)var + 1e-5f);
        g_sc[c] = s;
        g_cc[c] = bet[c] - (float)mu * s;
    }
    g_sum[c] = 0.0; g_sumsq[c] = 0.0;
}

__global__ void fold_kernel(const float* __restrict__ gam, const float* __restrict__ bet,
                            const float* __restrict__ W, const float* __restrict__ bias,
                            int E, float* __restrict__ Wf, float* __restrict__ bf) {
    __shared__ float s_s[64], s_c[64];
    int t = threadIdx.x;   // 256
    if (t < 64) {
        double mu  = g_sum[t] / (double)E;
        double var = g_sumsq[t] / (double)E - mu * mu;
        float s = gam[t] * rsqrtf((float)var + 1e-5f);
        s_s[t] = s;
        s_c[t] = bet[t] - (float)mu * s;
        g_sum[t] = 0.0; g_sumsq[t] = 0.0;
    } else if (t < 128) {
        g_sum[t] = 0.0; g_sumsq[t] = 0.0;
    }
    __syncthreads();
    for (int e = t; e < 64 * 64; e += 256) Wf[e] = s_s[e >> 6] * W[e];
    if (t < 64) {
        float acc = bias[t];
        #pragma unroll 4
        for (int kk = 0; kk < 64; kk++) acc = fmaf(s_c[kk], W[kk * 64 + t], acc);
        bf[t] = acc;
    }
}

// ---------------------------------------------------------------------------
__global__ void maxagg1_kernel(const float* __restrict__ H, float* __restrict__ hcat,
                               float* __restrict__ x1, float* __restrict__ sq) {
    int bi = blockIdx.x;
    int c  = threadIdx.x;   // 64
    const float* h = H + (size_t)bi * (KNN * 64) + c;
    float s = g_sc[c], cc = g_cc[c];
    float m = -3.4e38f;
    #pragma unroll
    for (int kk = 0; kk < KNN; kk++) m = fmaxf(m, fmaf(s, h[kk * 64], cc));
    hcat[(size_t)bi * 192 + c] = m;
    x1[(size_t)bi * 64 + c]    = m;
    float q = m * m;
    #pragma unroll
    for (int o = 16; o; o >>= 1) q += __shfl_xor_sync(0xffffffffu, q, o);
    __shared__ float sh[2];
    if ((c & 31) == 0) sh[c >> 5] = q;
    __syncthreads();
    if (c == 0) sq[bi] = sh[0] + sh[1];
}

__global__ void apply_bn_kernel(const float* __restrict__ Y, float* __restrict__ out) {
    int i = blockIdx.x * 256 + threadIdx.x;
    int c = i & 127;
    out[i] = fmaf(g_sc[c], Y[i], g_cc[c]);
}

// ---------------------------------------------------------------------------
extern "C" void kernel_launch(void* const* d_in, const int* in_sizes, int n_in,
                              void* d_out, int out_size) {
    const float* x0    = (const float*)d_in[1];
    const float* c1w0  = (const float*)d_in[2];
    const float* c1b0  = (const float*)d_in[3];
    const float* c1g0  = (const float*)d_in[4];
    const float* c1be0 = (const float*)d_in[5];
    const float* c1w1  = (const float*)d_in[6];
    const float* c1b1  = (const float*)d_in[7];
    const float* c1g1  = (const float*)d_in[8];
    const float* c1be1 = (const float*)d_in[9];
    const float* c1w2  = (const float*)d_in[10];
    const float* c1b2  = (const float*)d_in[11];
    const float* c1g2  = (const float*)d_in[12];
    const float* c1be2 = (const float*)d_in[13];
    const float* c2w0  = (const float*)d_in[14];
    const float* c2b0  = (const float*)d_in[15];
    const float* c2g0  = (const float*)d_in[16];
    const float* c2be0 = (const float*)d_in[17];
    const float* lw    = (const float*)d_in[18];
    const float* lb    = (const float*)d_in[19];
    const float* lg    = (const float*)d_in[20];
    const float* lbe   = (const float*)d_in[21];
    float* out = (float*)d_out;

    void* sp = nullptr; cudaGetSymbolAddress(&sp, g_scratch);
    float* S = (float*)sp;
    void* ip = nullptr; cudaGetSymbolAddress(&ip, g_knn_idx);
    int* IDX = (int*)ip;

    float* D     = S + OFF_D;
    float* PQ    = S + OFF_PQ;
    float* PQ2   = S + OFF_PQ2;
    float* H1    = S + OFF_H1;
    float* H2    = S + OFF_H2;
    float* HCAT  = S + OFF_HCAT;
    float* X1    = S + OFF_X1;
    float* Y0    = S + OFF_Y0;
    float* SQ    = S + OFF_SQ;
    float* WCAT  = S + OFF_WCAT;
    float* WCAT2 = S + OFF_WCAT2;
    float* WF    = S + OFF_WF;
    float* BF    = S + OFF_BF;
    float* VMAX  = S + OFF_H1;                       // H1 dead by conv2
    float* VMIN  = S + OFF_H1 + (size_t)NROW * 128;

    // dependency-free weight prep first => ncu capture slot lands on dist1
    build_wcat1<<<128, 256>>>(c1w0, WCAT);
    build_wcat2<<<64, 256>>>(c2w0, WCAT2);
    rowsq_kernel<256><<<NROW, 32>>>(x0, SQ);

    // ---- EdgeConv 1 ----
    dist_kernel<256><<<dim3(36, 1, 8), 256>>>(x0, SQ, D);
    topk_kernel<<<NROW / 8, 256>>>(D, IDX);
    gemm_nodes<128, 64, 8, 4, false, false><<<dim3(2, NROW / 128), 256>>>(x0, WCAT, nullptr, PQ, NROW, 128, 256);
    stats_edges_kernel<64><<<512, 256>>>(PQ, IDX, c1b0);
    fold_kernel<<<1, 256>>>(c1g0, c1be0, c1w1, c1b1, NEDGE, WF, BF);
    gemm_edge1<<<NEDGE / 128, 256>>>(PQ, IDX, c1b0, WF, BF, H1);
    fold_kernel<<<1, 256>>>(c1g1, c1be1, c1w2, c1b2, NEDGE, WF, BF);
    gemm_nodes<128, 64, 8, 4, true, true><<<dim3(1, NEDGE / 128), 256>>>(H1, WF, BF, H2, NEDGE, 64, 64);
    finalize_kernel<64><<<1, 128>>>(c1g2, c1be2, NEDGE);
    maxagg1_kernel<<<NROW, 64>>>(H2, HCAT, X1, SQ);

    // ---- EdgeConv 2 ----
    dist_kernel<64><<<dim3(36, 1, 8), 256>>>(X1, SQ, D);
    topk_kernel<<<NROW / 8, 256>>>(D, IDX);
    gemm_nodes<128, 128, 8, 8, false, false><<<dim3(2, NROW / 128), 256>>>(X1, WCAT2, nullptr, PQ2, NROW, 256, 64);
    stats_minmax_edges_kernel<<<512, 256>>>(PQ2, IDX, c2b0, VMAX, VMIN);
    finalize_kernel<128><<<1, 128>>>(c2g0, c2be0, NEDGE);
    apply_minmax_kernel<<<NROW * 128 / 256, 256>>>(VMAX, VMIN, HCAT);

    // ---- Final Linear + BN ----
    gemm_nodes<128, 64, 8, 4, true, true><<<dim3(2, NROW / 128), 256>>>(HCAT, lw, lb, Y0, NROW, 128, 192);
    finalize_kernel<128><<<1, 128>>>(lg, lbe, NROW);
    apply_bn_kernel<<<NROW * 128 / 256, 256>>>(Y0, out);
}

// round 14
// speedup vs baseline: 1.3658x; 1.0602x over previous
#include <cuda_runtime.h>
#include <cstdint>

// ---------------------------------------------------------------------------
// DGCNN: 2x EdgeConv (dynamic kNN) + final MLP, training-mode BatchNorm.
// R14 = R13 + (a) gemm_edge1 holds full A(128x64)+B(64x64) in smem: 2 barriers
// (was 8), gather MLP 16; (b) topk cross-lane reduce via redux.sync.min.u32;
// (c) wcat1/wcat2/rowsq merged into one prep kernel.
// ---------------------------------------------------------------------------

typedef unsigned long long ull;

namespace cfg {
constexpr int BB   = 8;
constexpr int NN_  = 1024;
constexpr int KNN  = 20;
constexpr int NROW  = BB * NN_;        // 8192
constexpr int NEDGE = NROW * KNN;      // 163840

constexpr size_t OFF_D    = 0;
constexpr size_t SZ_D     = (size_t)BB * NN_ * NN_;
constexpr size_t OFF_PQ   = OFF_D + SZ_D;
constexpr size_t SZ_PQ    = (size_t)NROW * 128;
constexpr size_t OFF_PQ2  = OFF_PQ + SZ_PQ;
constexpr size_t SZ_PQ2   = (size_t)NROW * 256;
constexpr size_t OFF_H1   = OFF_PQ2 + SZ_PQ2;
constexpr size_t SZ_H64   = (size_t)NEDGE * 64;
constexpr size_t OFF_H2   = OFF_H1 + SZ_H64;
constexpr size_t OFF_HCAT = OFF_H2 + SZ_H64;
constexpr size_t SZ_HCAT  = (size_t)NROW * 192;
constexpr size_t OFF_X1   = OFF_HCAT + SZ_HCAT;
constexpr size_t SZ_X1    = (size_t)NROW * 64;
constexpr size_t OFF_Y0   = OFF_X1 + SZ_X1;
constexpr size_t SZ_Y0    = (size_t)NROW * 128;
constexpr size_t OFF_SQ   = OFF_Y0 + SZ_Y0;
constexpr size_t SZ_SQ    = (size_t)NROW;
constexpr size_t OFF_WCAT = OFF_SQ + SZ_SQ;
constexpr size_t SZ_WCAT  = 256 * 128;
constexpr size_t OFF_WCAT2= OFF_WCAT + SZ_WCAT;
constexpr size_t SZ_WCAT2 = 64 * 256;
constexpr size_t OFF_WF   = OFF_WCAT2 + SZ_WCAT2;
constexpr size_t SZ_WF    = 64 * 64;
constexpr size_t OFF_BF   = OFF_WF + SZ_WF;
constexpr size_t SZ_BF    = 128;
constexpr size_t SCRATCH_TOTAL = OFF_BF + SZ_BF;
}  // namespace cfg
using namespace cfg;

__device__ float  g_scratch[SCRATCH_TOTAL];
__device__ int    g_knn_idx[NEDGE];
__device__ double g_sum[128];
__device__ double g_sumsq[128];
__device__ float  g_sc[128];
__device__ float  g_cc[128];

// ---------------------------------------------------------------------------
__device__ __forceinline__ ull pack2(float x, float y) {
    ull r; asm("mov.b64 %0, {%1, %2};" : "=l"(r) : "f"(x), "f"(y)); return r;
}
__device__ __forceinline__ void fma2(ull& d, ull a, ull b) {
    asm("fma.rn.f32x2 %0, %1, %2, %0;" : "+l"(d) : "l"(a), "l"(b));
}
__device__ __forceinline__ float2 unpack2(ull v) {
    float2 f; asm("mov.b64 {%0, %1}, %2;" : "=f"(f.x), "=f"(f.y) : "l"(v)); return f;
}

// ---------------------------------------------------------------------------
// Merged prep: blocks [0,128) wcat1, [128,192) wcat2, [192,1216) rowsq(C=256)
// ---------------------------------------------------------------------------
__global__ void prep_kernel(const float* __restrict__ c1w0, float* __restrict__ Wcat1,
                            const float* __restrict__ c2w0, float* __restrict__ Wcat2,
                            const float* __restrict__ X0, float* __restrict__ sq) {
    int b = blockIdx.x;
    int t = threadIdx.x;
    if (b < 128) {
        int e = b * 256 + t;                 // 256*128
        int kk = e >> 7, n = e & 127;
        float v;
        if (n < 64) v = c1w0[kk * 64 + n] - c1w0[(kk + 256) * 64 + n];
        else        v = c1w0[(kk + 256) * 64 + (n - 64)];
        Wcat1[e] = v;
    } else if (b < 192) {
        int e = (b - 128) * 256 + t;         // 64*256
        int kk = e >> 8, n = e & 255;
        float v;
        if (n < 128) v = c2w0[kk * 128 + n] - c2w0[(kk + 64) * 128 + n];
        else         v = c2w0[(kk + 64) * 128 + (n - 128)];
        Wcat2[e] = v;
    } else {
        int row  = (b - 192) * 8 + (t >> 5);
        int lane = t & 31;
        const float* x = X0 + (size_t)row * 256;
        float a = 0.f;
        #pragma unroll
        for (int c = lane; c < 256; c += 32) { float v = x[c]; a = fmaf(v, v, a); }
        #pragma unroll
        for (int o = 16; o; o >>= 1) a += __shfl_xor_sync(0xffffffffu, a, o);
        if (lane == 0) sq[row] = a;
    }
}

// ---------------------------------------------------------------------------
// Distance matrix: symmetric triangular tiles, split-half B cols,
// double-buffered smem pipeline (1 barrier per K-step).
// ---------------------------------------------------------------------------
template <int C>
__global__ void __launch_bounds__(256, 2)
dist_kernel(const float* __restrict__ X, const float* __restrict__ sq,
            float* __restrict__ D) {
    __shared__ float As[2][16][128];
    __shared__ float Bs[2][16][128];
    int b  = blockIdx.z;
    const float* Xb  = X  + (size_t)b * NN_ * C;
    const float* sqb = sq + (size_t)b * NN_;
    float* Db = D + (size_t)b * NN_ * NN_;

    int rem = blockIdx.x, bi = 0;
    while (rem >= 8 - bi) { rem -= 8 - bi; bi++; }
    int bj = bi + rem;
    int i0 = bi * 128, j0 = bj * 128;

    int t  = threadIdx.x;
    int tx = t & 15, ty = t >> 4;
    int c0 = tx * 4;
    int c1 = 64 + tx * 4;

    int lr0 = (t >> 2), lr1 = lr0 + 64;
    int lkk = (t & 3) * 4;

    ull acc[8][4];
    #pragma unroll
    for (int i = 0; i < 8; i++)
        #pragma unroll
        for (int j = 0; j < 4; j++) acc[i][j] = 0ull;

    {
        float4 va0 = *reinterpret_cast<const float4*>(&Xb[(size_t)(i0 + lr0) * C + lkk]);
        float4 va1 = *reinterpret_cast<const float4*>(&Xb[(size_t)(i0 + lr1) * C + lkk]);
        float4 vb0 = *reinterpret_cast<const float4*>(&Xb[(size_t)(j0 + lr0) * C + lkk]);
        float4 vb1 = *reinterpret_cast<const float4*>(&Xb[(size_t)(j0 + lr1) * C + lkk]);
        As[0][lkk + 0][lr0] = va0.x; As[0][lkk + 1][lr0] = va0.y;
        As[0][lkk + 2][lr0] = va0.z; As[0][lkk + 3][lr0] = va0.w;
        As[0][lkk + 0][lr1] = va1.x; As[0][lkk + 1][lr1] = va1.y;
        As[0][lkk + 2][lr1] = va1.z; As[0][lkk + 3][lr1] = va1.w;
        Bs[0][lkk + 0][lr0] = vb0.x; Bs[0][lkk + 1][lr0] = vb0.y;
        Bs[0][lkk + 2][lr0] = vb0.z; Bs[0][lkk + 3][lr0] = vb0.w;
        Bs[0][lkk + 0][lr1] = vb1.x; Bs[0][lkk + 1][lr1] = vb1.y;
        Bs[0][lkk + 2][lr1] = vb1.z; Bs[0][lkk + 3][lr1] = vb1.w;
    }
    __syncthreads();

    constexpr int NT = C / 16;
    for (int kt = 0; kt < NT; kt++) {
        int cur = kt & 1;
        float4 pa0, pa1, pb0, pb1;
        if (kt + 1 < NT) {
            int k0n = (kt + 1) * 16;
            pa0 = *reinterpret_cast<const float4*>(&Xb[(size_t)(i0 + lr0) * C + k0n + lkk]);
            pa1 = *reinterpret_cast<const float4*>(&Xb[(size_t)(i0 + lr1) * C + k0n + lkk]);
            pb0 = *reinterpret_cast<const float4*>(&Xb[(size_t)(j0 + lr0) * C + k0n + lkk]);
            pb1 = *reinterpret_cast<const float4*>(&Xb[(size_t)(j0 + lr1) * C + k0n + lkk]);
        }
        #pragma unroll
        for (int kk = 0; kk < 16; kk++) {
            float4 a0 = *reinterpret_cast<const float4*>(&As[cur][kk][ty * 8]);
            float4 a1 = *reinterpret_cast<const float4*>(&As[cur][kk][ty * 8 + 4]);
            float4 b0 = *reinterpret_cast<const float4*>(&Bs[cur][kk][c0]);
            float4 b1 = *reinterpret_cast<const float4*>(&Bs[cur][kk][c1]);
            ull rb[4] = {pack2(b0.x, b0.y), pack2(b0.z, b0.w),
                         pack2(b1.x, b1.y), pack2(b1.z, b1.w)};
            float ra[8] = {a0.x, a0.y, a0.z, a0.w, a1.x, a1.y, a1.z, a1.w};
            #pragma unroll
            for (int i = 0; i < 8; i++) {
                ull ai = pack2(ra[i], ra[i]);
                #pragma unroll
                for (int j = 0; j < 4; j++) fma2(acc[i][j], ai, rb[j]);
            }
        }
        if (kt + 1 < NT) {
            int nxt = cur ^ 1;
            As[nxt][lkk + 0][lr0] = pa0.x; As[nxt][lkk + 1][lr0] = pa0.y;
            As[nxt][lkk + 2][lr0] = pa0.z; As[nxt][lkk + 3][lr0] = pa0.w;
            As[nxt][lkk + 0][lr1] = pa1.x; As[nxt][lkk + 1][lr1] = pa1.y;
            As[nxt][lkk + 2][lr1] = pa1.z; As[nxt][lkk + 3][lr1] = pa1.w;
            Bs[nxt][lkk + 0][lr0] = pb0.x; Bs[nxt][lkk + 1][lr0] = pb0.y;
            Bs[nxt][lkk + 2][lr0] = pb0.z; Bs[nxt][lkk + 3][lr0] = pb0.w;
            Bs[nxt][lkk + 0][lr1] = pb1.x; Bs[nxt][lkk + 1][lr1] = pb1.y;
            Bs[nxt][lkk + 2][lr1] = pb1.z; Bs[nxt][lkk + 3][lr1] = pb1.w;
        }
        __syncthreads();
    }

    float sj[8];
    #pragma unroll
    for (int j = 0; j < 4; j++) { sj[j] = sqb[j0 + c0 + j]; sj[4 + j] = sqb[j0 + c1 + j]; }

    float o[8][8];
    #pragma unroll
    for (int i = 0; i < 8; i++) {
        float si = sqb[i0 + ty * 8 + i];
        #pragma unroll
        for (int j = 0; j < 4; j++) {
            float2 u = unpack2(acc[i][j]);
            o[i][j * 2]     = si + sj[j * 2]     - 2.f * u.x;
            o[i][j * 2 + 1] = si + sj[j * 2 + 1] - 2.f * u.y;
        }
    }
    #pragma unroll
    for (int i = 0; i < 8; i++) {
        int gi = i0 + ty * 8 + i;
        *reinterpret_cast<float4*>(&Db[(size_t)gi * NN_ + j0 + c0]) =
            make_float4(o[i][0], o[i][1], o[i][2], o[i][3]);
        *reinterpret_cast<float4*>(&Db[(size_t)gi * NN_ + j0 + c1]) =
            make_float4(o[i][4], o[i][5], o[i][6], o[i][7]);
    }
    if (bi != bj) {
        #pragma unroll
        for (int j = 0; j < 8; j++) {
            int gj = j0 + ((j < 4) ? (c0 + j) : (c1 + j - 4));
            float4* dst = reinterpret_cast<float4*>(&Db[(size_t)gj * NN_ + i0 + ty * 8]);
            dst[0] = make_float4(o[0][j], o[1][j], o[2][j], o[3][j]);
            dst[1] = make_float4(o[4][j], o[5][j], o[6][j], o[7][j]);
        }
    }
}

// ---------------------------------------------------------------------------
// Top-20 smallest per row; one warp per row. Tree-min for own slot, then
// redux.sync.min.u32 on order-preserving key + ballot/ffs + 1 shfl.
// ---------------------------------------------------------------------------
__global__ void topk_kernel(const float* __restrict__ D, int* __restrict__ idx) {
    int row  = blockIdx.x * 8 + (threadIdx.x >> 5);
    int lane = threadIdx.x & 31;
    const float4* d4 = reinterpret_cast<const float4*>(D + (size_t)row * NN_);
    float v[32];
    #pragma unroll
    for (int q = 0; q < 8; q++) {
        float4 x = d4[lane + 32 * q];
        v[4 * q + 0] = x.x; v[4 * q + 1] = x.y;
        v[4 * q + 2] = x.z; v[4 * q + 3] = x.w;
    }

    for (int s = 0; s < KNN; s++) {
        // depth-5 min tree over own 32 values
        float m16[16];
        #pragma unroll
        for (int q = 0; q < 16; q++) m16[q] = fminf(v[q], v[q + 16]);
        float m8[8];
        #pragma unroll
        for (int q = 0; q < 8; q++) m8[q] = fminf(m16[q], m16[q + 8]);
        float m4[4];
        #pragma unroll
        for (int q = 0; q < 4; q++) m4[q] = fminf(m8[q], m8[q + 4]);
        float m = fminf(fminf(m4[0], m4[2]), fminf(m4[1], m4[3]));
        unsigned mask = 0u;
        #pragma unroll
        for (int q = 0; q < 32; q++) mask |= (v[q] == m) ? (1u << q) : 0u;
        int slot = __ffs(mask) - 1;
        int gidx = 4 * lane + 128 * (slot >> 2) + (slot & 3);

        // cross-lane argmin via orderable-uint redux
        unsigned kb = __float_as_uint(m);
        kb = (kb & 0x80000000u) ? ~kb : (kb | 0x80000000u);
        unsigned mk;
        asm("redux.sync.min.u32 %0, %1, 0xffffffff;" : "=r"(mk) : "r"(kb));
        unsigned ball = __ballot_sync(0xffffffffu, kb == mk);
        int src = __ffs(ball) - 1;
        int bidx = __shfl_sync(0xffffffffu, gidx, src);
        if (lane == 0) idx[row * KNN + s] = bidx;
        if (lane == src) {
            #pragma unroll
            for (int q = 0; q < 32; q++) if (q == slot) v[q] = 3.4e38f;
        }
    }
}

// ---------------------------------------------------------------------------
// Generic fp32 GEMM (f32x2, split-half cols for TN==8), double-buffered smem.
// ---------------------------------------------------------------------------
template <int BM, int BN, int TM, int TN, bool BIAS_RELU, bool STATS>
__global__ void __launch_bounds__(256, 2)
gemm_nodes(const float* __restrict__ A, const float* __restrict__ Bm,
           const float* __restrict__ bias, float* __restrict__ Cmat,
           int M, int N, int K) {
    constexpr int BK = 16;
    constexpr int TX = BN / TN;
    static_assert(TX == 16 && (256 / TX) * TM == BM, "layout");
    constexpr int N4A = BM / 64;
    constexpr int N4B = BN / 64;
    __shared__ float smem[2 * BK * (BM + BN)];
    int block_m = blockIdx.y * BM, block_n = blockIdx.x * BN;
    int t  = threadIdx.x;
    int tx = t % TX, ty = t / TX;
    int c0 = tx * 4;
    int c1 = BN / 2 + tx * 4;

    int ar  = t >> 2;
    int akk = (t & 3) * 4;
    int bkk = t >> 4;
    int bcc = (t & 15) * 4;

    ull acc[TM][TN / 2];
    #pragma unroll
    for (int i = 0; i < TM; i++)
        #pragma unroll
        for (int j = 0; j < TN / 2; j++) acc[i][j] = 0ull;

    {
        float* As0 = smem;
        float* Bs0 = smem + 2 * BK * BM;
        #pragma unroll
        for (int it = 0; it < N4A; it++) {
            int r = ar + it * 64;
            float4 v = *reinterpret_cast<const float4*>(&A[(size_t)(block_m + r) * K + akk]);
            As0[(akk + 0) * BM + r] = v.x; As0[(akk + 1) * BM + r] = v.y;
            As0[(akk + 2) * BM + r] = v.z; As0[(akk + 3) * BM + r] = v.w;
        }
        #pragma unroll
        for (int it = 0; it < N4B; it++) {
            int cc = bcc + it * 64;
            *reinterpret_cast<float4*>(&Bs0[bkk * BN + cc]) =
                *reinterpret_cast<const float4*>(&Bm[(size_t)bkk * N + block_n + cc]);
        }
    }
    __syncthreads();

    int NT = K / BK;
    for (int kt = 0; kt < NT; kt++) {
        int cur = kt & 1;
        float* Asb = smem + cur * BK * BM;
        float* Bsb = smem + 2 * BK * BM + cur * BK * BN;
        float4 pa[N4A], pb[N4B];
        if (kt + 1 < NT) {
            int k0n = (kt + 1) * BK;
            #pragma unroll
            for (int it = 0; it < N4A; it++) {
                int r = ar + it * 64;
                pa[it] = *reinterpret_cast<const float4*>(&A[(size_t)(block_m + r) * K + k0n + akk]);
            }
            #pragma unroll
            for (int it = 0; it < N4B; it++) {
                int cc = bcc + it * 64;
                pb[it] = *reinterpret_cast<const float4*>(&Bm[(size_t)(k0n + bkk) * N + block_n + cc]);
            }
        }
        #pragma unroll
        for (int kk = 0; kk < BK; kk++) {
            float ra[TM];
            #pragma unroll
            for (int i4 = 0; i4 < TM / 4; i4++) {
                float4 a = *reinterpret_cast<const float4*>(&Asb[kk * BM + ty * TM + i4 * 4]);
                ra[i4 * 4 + 0] = a.x; ra[i4 * 4 + 1] = a.y;
                ra[i4 * 4 + 2] = a.z; ra[i4 * 4 + 3] = a.w;
            }
            ull rb[TN / 2];
            {
                float4 bq0 = *reinterpret_cast<const float4*>(&Bsb[kk * BN + c0]);
                rb[0] = pack2(bq0.x, bq0.y);
                rb[1] = pack2(bq0.z, bq0.w);
                if (TN == 8) {
                    float4 bq1 = *reinterpret_cast<const float4*>(&Bsb[kk * BN + c1]);
                    rb[2] = pack2(bq1.x, bq1.y);
                    rb[3] = pack2(bq1.z, bq1.w);
                }
            }
            #pragma unroll
            for (int i = 0; i < TM; i++) {
                ull ai = pack2(ra[i], ra[i]);
                #pragma unroll
                for (int j = 0; j < TN / 2; j++) fma2(acc[i][j], ai, rb[j]);
            }
        }
        if (kt + 1 < NT) {
            float* Asn = smem + (cur ^ 1) * BK * BM;
            float* Bsn = smem + 2 * BK * BM + (cur ^ 1) * BK * BN;
            #pragma unroll
            for (int it = 0; it < N4A; it++) {
                int r = ar + it * 64;
                Asn[(akk + 0) * BM + r] = pa[it].x; Asn[(akk + 1) * BM + r] = pa[it].y;
                Asn[(akk + 2) * BM + r] = pa[it].z; Asn[(akk + 3) * BM + r] = pa[it].w;
            }
            #pragma unroll
            for (int it = 0; it < N4B; it++) {
                int cc = bcc + it * 64;
                *reinterpret_cast<float4*>(&Bsn[bkk * BN + cc]) = pb[it];
            }
        }
        __syncthreads();
    }

    float bb[TN];
    if (BIAS_RELU) {
        #pragma unroll
        for (int j = 0; j < TN; j++)
            bb[j] = bias[block_n + ((j < 4) ? (c0 + j) : (c1 + j - 4))];
    }
    float ps[TN], ps2[TN];
    #pragma unroll
    for (int j = 0; j < TN; j++) { ps[j] = 0.f; ps2[j] = 0.f; }

    #pragma unroll
    for (int i = 0; i < TM; i++) {
        float v[TN];
        #pragma unroll
        for (int j = 0; j < TN / 2; j++) {
            float2 u = unpack2(acc[i][j]);
            v[j * 2] = u.x; v[j * 2 + 1] = u.y;
        }
        #pragma unroll
        for (int j = 0; j < TN; j++) {
            if (BIAS_RELU) v[j] = fmaxf(v[j] + bb[j], 0.f);
            if (STATS) { ps[j] += v[j]; ps2[j] = fmaf(v[j], v[j], ps2[j]); }
        }
        int r = block_m + ty * TM + i;
        *reinterpret_cast<float4*>(&Cmat[(size_t)r * N + block_n + c0]) =
            make_float4(v[0], v[1], v[2], v[3]);
        if (TN == 8)
            *reinterpret_cast<float4*>(&Cmat[(size_t)r * N + block_n + c1]) =
                make_float4(v[4], v[5], v[6], v[7]);
    }

    if (STATS) {
        #pragma unroll
        for (int j = 0; j < TN; j++) {
            int col = (j < 4) ? (c0 + j) : (c1 + j - 4);
            smem[ty * BN + col]           = ps[j];
            smem[16 * BN + ty * BN + col] = ps2[j];
        }
        __syncthreads();
        if (t < BN) {
            float s = 0.f, s2 = 0.f;
            #pragma unroll
            for (int g = 0; g < 16; g++) { s += smem[g * BN + t]; s2 += smem[16 * BN + g * BN + t]; }
            atomicAdd(&g_sum[block_n + t],   (double)s);
            atomicAdd(&g_sumsq[block_n + t], (double)s2);
        }
    }
}

// ---------------------------------------------------------------------------
// Layer-1 edge GEMM: full A(128x64) built in smem from gathers (MLP 16),
// full B(64x64) resident; 2 barriers total, single 64-kk compute loop.
// ---------------------------------------------------------------------------
__global__ void __launch_bounds__(256, 2)
gemm_edge1(const float* __restrict__ PQ, const int* __restrict__ IDXp,
           const float* __restrict__ abias, const float* __restrict__ W,
           const float* __restrict__ obias, float* __restrict__ H) {
    __shared__ float As[64 * 128];   // [c][r]
    __shared__ float Bs[64 * 64];    // [k][n]
    __shared__ float s_ab[64];
    int t = threadIdx.x;
    int block_m = blockIdx.x * 128;
    if (t < 64) s_ab[t] = abias[t];
    // B: 4096 floats, 4 float4/thread (coalesced)
    #pragma unroll
    for (int i = 0; i < 4; i++)
        *reinterpret_cast<float4*>(&Bs[i * 1024 + t * 4]) =
            *reinterpret_cast<const float4*>(&W[i * 1024 + t * 4]);
    // A: row r = t>>1, cols co..co+31; 16 independent float4 gathers
    int r  = t >> 1;
    int co = (t & 1) * 32;
    {
        int e  = block_m + r;
        int bi = e / KNN;
        int qo = ((bi >> 10) << 10) + IDXp[e];
        const float* Pp = PQ + (size_t)bi * 128 + co;
        const float* Qp = PQ + (size_t)qo * 128 + 64 + co;
        float4 pv[8], qv[8];
        #pragma unroll
        for (int q = 0; q < 8; q++) {
            pv[q] = *reinterpret_cast<const float4*>(Pp + q * 4);
            qv[q] = *reinterpret_cast<const float4*>(Qp + q * 4);
        }
        __syncthreads();   // s_ab visible (loads above don't need it)
        #pragma unroll
        for (int q = 0; q < 8; q++) {
            int c = co + q * 4;
            As[(c + 0) * 128 + r] = fmaxf(pv[q].x + qv[q].x + s_ab[c + 0], 0.f);
            As[(c + 1) * 128 + r] = fmaxf(pv[q].y + qv[q].y + s_ab[c + 1], 0.f);
            As[(c + 2) * 128 + r] = fmaxf(pv[q].z + qv[q].z + s_ab[c + 2], 0.f);
            As[(c + 3) * 128 + r] = fmaxf(pv[q].w + qv[q].w + s_ab[c + 3], 0.f);
        }
    }
    __syncthreads();

    int tx = t & 15, ty = t >> 4;
    ull acc[8][2];
    #pragma unroll
    for (int i = 0; i < 8; i++) { acc[i][0] = 0ull; acc[i][1] = 0ull; }

    #pragma unroll 16
    for (int kk = 0; kk < 64; kk++) {
        float4 a0 = *reinterpret_cast<const float4*>(&As[kk * 128 + ty * 8]);
        float4 a1 = *reinterpret_cast<const float4*>(&As[kk * 128 + ty * 8 + 4]);
        float4 b0 = *reinterpret_cast<const float4*>(&Bs[kk * 64 + tx * 4]);
        ull rb0 = pack2(b0.x, b0.y), rb1 = pack2(b0.z, b0.w);
        float ra[8] = {a0.x, a0.y, a0.z, a0.w, a1.x, a1.y, a1.z, a1.w};
        #pragma unroll
        for (int i = 0; i < 8; i++) {
            ull ai = pack2(ra[i], ra[i]);
            fma2(acc[i][0], ai, rb0);
            fma2(acc[i][1], ai, rb1);
        }
    }

    float ob[4];
    #pragma unroll
    for (int j = 0; j < 4; j++) ob[j] = obias[tx * 4 + j];
    float ps[4] = {0, 0, 0, 0}, ps2[4] = {0, 0, 0, 0};
    #pragma unroll
    for (int i = 0; i < 8; i++) {
        float2 u0 = unpack2(acc[i][0]), u1 = unpack2(acc[i][1]);
        float v[4] = {u0.x, u0.y, u1.x, u1.y};
        #pragma unroll
        for (int j = 0; j < 4; j++) {
            v[j] = fmaxf(v[j] + ob[j], 0.f);
            ps[j] += v[j]; ps2[j] = fmaf(v[j], v[j], ps2[j]);
        }
        int rr = block_m + ty * 8 + i;
        *reinterpret_cast<float4*>(&H[(size_t)rr * 64 + tx * 4]) =
            make_float4(v[0], v[1], v[2], v[3]);
    }
    __syncthreads();   // all reads of As done before stats reuse
    #pragma unroll
    for (int j = 0; j < 4; j++) {
        As[ty * 64 + tx * 4 + j]        = ps[j];
        As[1024 + ty * 64 + tx * 4 + j] = ps2[j];
    }
    __syncthreads();
    if (t < 64) {
        float s = 0.f, s2 = 0.f;
        #pragma unroll
        for (int g = 0; g < 16; g++) { s += As[g * 64 + t]; s2 += As[1024 + g * 64 + t]; }
        atomicAdd(&g_sum[t],   (double)s);
        atomicAdd(&g_sumsq[t], (double)s2);
    }
}

// ---------------------------------------------------------------------------
// Conv1: stats of recomputed edge features relu(P+Q+b). Grid-stride loop.
// ---------------------------------------------------------------------------
template <int CH>
__global__ void stats_edges_kernel(const float* __restrict__ PQ,
                                   const int* __restrict__ IDXp,
                                   const float* __restrict__ bias) {
    constexpr int G = 256 / CH;
    int c = threadIdx.x % CH;
    int g = threadIdx.x / CH;
    int stride = gridDim.x * G;
    float bb = bias[c];
    float s = 0.f, s2 = 0.f;
    for (int node = blockIdx.x * G + g; node < NROW; node += stride) {
        float p = PQ[(size_t)node * (2 * CH) + c] + bb;
        int base = (node >> 10) << 10;
        const int* ix = IDXp + node * KNN;
        #pragma unroll 5
        for (int kk = 0; kk < KNN; kk++) {
            int j = base + ix[kk];
            float v = fmaxf(p + PQ[(size_t)j * (2 * CH) + CH + c], 0.f);
            s += v; s2 = fmaf(v, v, s2);
        }
    }
    __shared__ float sh[2][256];
    sh[0][threadIdx.x] = s; sh[1][threadIdx.x] = s2;
    __syncthreads();
    if (g == 0) {
        #pragma unroll
        for (int gg = 1; gg < G; gg++) { s += sh[0][gg * CH + c]; s2 += sh[1][gg * CH + c]; }
        atomicAdd(&g_sum[c],   (double)s);
        atomicAdd(&g_sumsq[c], (double)s2);
    }
}

// ---------------------------------------------------------------------------
// Conv2: fused stats + per-node max/min (1 pass). Grid-stride loop.
// ---------------------------------------------------------------------------
__global__ void stats_minmax_edges_kernel(const float* __restrict__ PQ2,
                                          const int* __restrict__ IDXp,
                                          const float* __restrict__ bias,
                                          float* __restrict__ vmax,
                                          float* __restrict__ vmin) {
    int c = threadIdx.x & 127;
    int g = threadIdx.x >> 7;          // 0..1
    int stride = gridDim.x * 2;
    float bb = bias[c];
    float s = 0.f, s2 = 0.f;
    for (int node = blockIdx.x * 2 + g; node < NROW; node += stride) {
        float p = PQ2[(size_t)node * 256 + c] + bb;
        int base = (node >> 10) << 10;
        const int* ix = IDXp + node * KNN;
        float mx = -3.4e38f, mn = 3.4e38f;
        #pragma unroll 5
        for (int kk = 0; kk < KNN; kk++) {
            int j = base + ix[kk];
            float v = fmaxf(p + PQ2[(size_t)j * 256 + 128 + c], 0.f);
            s += v; s2 = fmaf(v, v, s2);
            mx = fmaxf(mx, v); mn = fminf(mn, v);
        }
        vmax[(size_t)node * 128 + c] = mx;
        vmin[(size_t)node * 128 + c] = mn;
    }
    __shared__ float sh[2][256];
    sh[0][threadIdx.x] = s; sh[1][threadIdx.x] = s2;
    __syncthreads();
    if (g == 0) {
        s  += sh[0][128 + c];
        s2 += sh[1][128 + c];
        atomicAdd(&g_sum[c],   (double)s);
        atomicAdd(&g_sumsq[c], (double)s2);
    }
}

// hcat[bi,64+c] = s>=0 ? s*vmax+cc : s*vmin+cc
__global__ void apply_minmax_kernel(const float* __restrict__ vmax,
                                    const float* __restrict__ vmin,
                                    float* __restrict__ hcat) {
    int i = blockIdx.x * 256 + threadIdx.x;   // NROW*128
    int c = i & 127, bi = i >> 7;
    float s = g_sc[c], cc = g_cc[c];
    float v = (s >= 0.f) ? vmax[i] : vmin[i];
    hcat[(size_t)bi * 192 + 64 + c] = fmaf(s, v, cc);
}

// ---------------------------------------------------------------------------
template <int CH>
__global__ void finalize_kernel(const float* __restrict__ gam,
                                const float* __restrict__ bet, int E) {
    int c = threadIdx.x;   // 128
    if (c < CH) {
        double mu  = g_sum[c] / (double)E;
        double var = g_sumsq[c] / (double)E - mu * mu;
        float s = gam[c] * rsqrtf((float)var + 1e-5f);
        g_sc[c] = s;
        g_cc[c] = bet[c] - (float)mu * s;
    }
    g_sum[c] = 0.0; g_sumsq[c] = 0.0;
}

__global__ void fold_kernel(const float* __restrict__ gam, const float* __restrict__ bet,
                            const float* __restrict__ W, const float* __restrict__ bias,
                            int E, float* __restrict__ Wf, float* __restrict__ bf) {
    __shared__ float s_s[64], s_c[64];
    int t = threadIdx.x;   // 256
    if (t < 64) {
        double mu  = g_sum[t] / (double)E;
        double var = g_sumsq[t] / (double)E - mu * mu;
        float s = gam[t] * rsqrtf((float)var + 1e-5f);
        s_s[t] = s;
        s_c[t] = bet[t] - (float)mu * s;
        g_sum[t] = 0.0; g_sumsq[t] = 0.0;
    } else if (t < 128) {
        g_sum[t] = 0.0; g_sumsq[t] = 0.0;
    }
    __syncthreads();
    for (int e = t; e < 64 * 64; e += 256) Wf[e] = s_s[e >> 6] * W[e];
    if (t < 64) {
        float acc = bias[t];
        #pragma unroll 4
        for (int kk = 0; kk < 64; kk++) acc = fmaf(s_c[kk], W[kk * 64 + t], acc);
        bf[t] = acc;
    }
}

// ---------------------------------------------------------------------------
__global__ void maxagg1_kernel(const float* __restrict__ H, float* __restrict__ hcat,
                               float* __restrict__ x1, float* __restrict__ sq) {
    int bi = blockIdx.x;
    int c  = threadIdx.x;   // 64
    const float* h = H + (size_t)bi * (KNN * 64) + c;
    float s = g_sc[c], cc = g_cc[c];
    float m = -3.4e38f;
    #pragma unroll
    for (int kk = 0; kk < KNN; kk++) m = fmaxf(m, fmaf(s, h[kk * 64], cc));
    hcat[(size_t)bi * 192 + c] = m;
    x1[(size_t)bi * 64 + c]    = m;
    float q = m * m;
    #pragma unroll
    for (int o = 16; o; o >>= 1) q += __shfl_xor_sync(0xffffffffu, q, o);
    __shared__ float sh[2];
    if ((c & 31) == 0) sh[c >> 5] = q;
    __syncthreads();
    if (c == 0) sq[bi] = sh[0] + sh[1];
}

__global__ void apply_bn_kernel(const float* __restrict__ Y, float* __restrict__ out) {
    int i = blockIdx.x * 256 + threadIdx.x;
    int c = i & 127;
    out[i] = fmaf(g_sc[c], Y[i], g_cc[c]);
}

// ---------------------------------------------------------------------------
extern "C" void kernel_launch(void* const* d_in, const int* in_sizes, int n_in,
                              void* d_out, int out_size) {
    const float* x0    = (const float*)d_in[1];
    const float* c1w0  = (const float*)d_in[2];
    const float* c1b0  = (const float*)d_in[3];
    const float* c1g0  = (const float*)d_in[4];
    const float* c1be0 = (const float*)d_in[5];
    const float* c1w1  = (const float*)d_in[6];
    const float* c1b1  = (const float*)d_in[7];
    const float* c1g1  = (const float*)d_in[8];
    const float* c1be1 = (const float*)d_in[9];
    const float* c1w2  = (const float*)d_in[10];
    const float* c1b2  = (const float*)d_in[11];
    const float* c1g2  = (const float*)d_in[12];
    const float* c1be2 = (const float*)d_in[13];
    const float* c2w0  = (const float*)d_in[14];
    const float* c2b0  = (const float*)d_in[15];
    const float* c2g0  = (const float*)d_in[16];
    const float* c2be0 = (const float*)d_in[17];
    const float* lw    = (const float*)d_in[18];
    const float* lb    = (const float*)d_in[19];
    const float* lg    = (const float*)d_in[20];
    const float* lbe   = (const float*)d_in[21];
    float* out = (float*)d_out;

    void* sp = nullptr; cudaGetSymbolAddress(&sp, g_scratch);
    float* S = (float*)sp;
    void* ip = nullptr; cudaGetSymbolAddress(&ip, g_knn_idx);
    int* IDX = (int*)ip;

    float* D     = S + OFF_D;
    float* PQ    = S + OFF_PQ;
    float* PQ2   = S + OFF_PQ2;
    float* H1    = S + OFF_H1;
    float* H2    = S + OFF_H2;
    float* HCAT  = S + OFF_HCAT;
    float* X1    = S + OFF_X1;
    float* Y0    = S + OFF_Y0;
    float* SQ    = S + OFF_SQ;
    float* WCAT  = S + OFF_WCAT;
    float* WCAT2 = S + OFF_WCAT2;
    float* WF    = S + OFF_WF;
    float* BF    = S + OFF_BF;
    float* VMAX  = S + OFF_H1;                       // H1 dead by conv2
    float* VMIN  = S + OFF_H1 + (size_t)NROW * 128;

    // merged prep (wcat1 | wcat2 | rowsq) — keeps dist1 in the ncu slot range
    prep_kernel<<<192 + NROW / 8, 256>>>(c1w0, WCAT, c2w0, WCAT2, x0, SQ);

    // ---- EdgeConv 1 ----
    dist_kernel<256><<<dim3(36, 1, 8), 256>>>(x0, SQ, D);
    topk_kernel<<<NROW / 8, 256>>>(D, IDX);
    gemm_nodes<128, 64, 8, 4, false, false><<<dim3(2, NROW / 128), 256>>>(x0, WCAT, nullptr, PQ, NROW, 128, 256);
    stats_edges_kernel<64><<<512, 256>>>(PQ, IDX, c1b0);
    fold_kernel<<<1, 256>>>(c1g0, c1be0, c1w1, c1b1, NEDGE, WF, BF);
    gemm_edge1<<<NEDGE / 128, 256>>>(PQ, IDX, c1b0, WF, BF, H1);
    fold_kernel<<<1, 256>>>(c1g1, c1be1, c1w2, c1b2, NEDGE, WF, BF);
    gemm_nodes<128, 64, 8, 4, true, true><<<dim3(1, NEDGE / 128), 256>>>(H1, WF, BF, H2, NEDGE, 64, 64);
    finalize_kernel<64><<<1, 128>>>(c1g2, c1be2, NEDGE);
    maxagg1_kernel<<<NROW, 64>>>(H2, HCAT, X1, SQ);

    // ---- EdgeConv 2 ----
    dist_kernel<64><<<dim3(36, 1, 8), 256>>>(X1, SQ, D);
    topk_kernel<<<NROW / 8, 256>>>(D, IDX);
    gemm_nodes<128, 128, 8, 8, false, false><<<dim3(2, NROW / 128), 256>>>(X1, WCAT2, nullptr, PQ2, NROW, 256, 64);
    stats_minmax_edges_kernel<<<512, 256>>>(PQ2, IDX, c2b0, VMAX, VMIN);
    finalize_kernel<128><<<1, 128>>>(c2g0, c2be0, NEDGE);
    apply_minmax_kernel<<<NROW * 128 / 256, 256>>>(VMAX, VMIN, HCAT);

    // ---- Final Linear + BN ----
    gemm_nodes<128, 64, 8, 4, true, true><<<dim3(2, NROW / 128), 256>>>(HCAT, lw, lb, Y0, NROW, 128, 192);
    finalize_kernel<128><<<1, 128>>>(lg, lbe, NROW);
    apply_bn_kernel<<<NROW * 128 / 256, 256>>>(Y0, out);
}

// round 15
// speedup vs baseline: 1.3753x; 1.0070x over previous
#include <cuda_runtime.h>
#include <cstdint>

// ---------------------------------------------------------------------------
// DGCNN: 2x EdgeConv (dynamic kNN) + final MLP, training-mode BatchNorm.
// R15 = R14 + the three 128-block GEMMs (PQ1, PQ2, final) switched to BM=64
// (TM=4) -> 256 blocks, ~2 blocks/SM instead of <=1 (they were latency-starved
// at occ 12.6%). Hot kernels (dist, edge1, H2 gemm) untouched.
// ---------------------------------------------------------------------------

typedef unsigned long long ull;

namespace cfg {
constexpr int BB   = 8;
constexpr int NN_  = 1024;
constexpr int KNN  = 20;
constexpr int NROW  = BB * NN_;        // 8192
constexpr int NEDGE = NROW * KNN;      // 163840

constexpr size_t OFF_D    = 0;
constexpr size_t SZ_D     = (size_t)BB * NN_ * NN_;
constexpr size_t OFF_PQ   = OFF_D + SZ_D;
constexpr size_t SZ_PQ    = (size_t)NROW * 128;
constexpr size_t OFF_PQ2  = OFF_PQ + SZ_PQ;
constexpr size_t SZ_PQ2   = (size_t)NROW * 256;
constexpr size_t OFF_H1   = OFF_PQ2 + SZ_PQ2;
constexpr size_t SZ_H64   = (size_t)NEDGE * 64;
constexpr size_t OFF_H2   = OFF_H1 + SZ_H64;
constexpr size_t OFF_HCAT = OFF_H2 + SZ_H64;
constexpr size_t SZ_HCAT  = (size_t)NROW * 192;
constexpr size_t OFF_X1   = OFF_HCAT + SZ_HCAT;
constexpr size_t SZ_X1    = (size_t)NROW * 64;
constexpr size_t OFF_Y0   = OFF_X1 + SZ_X1;
constexpr size_t SZ_Y0    = (size_t)NROW * 128;
constexpr size_t OFF_SQ   = OFF_Y0 + SZ_Y0;
constexpr size_t SZ_SQ    = (size_t)NROW;
constexpr size_t OFF_WCAT = OFF_SQ + SZ_SQ;
constexpr size_t SZ_WCAT  = 256 * 128;
constexpr size_t OFF_WCAT2= OFF_WCAT + SZ_WCAT;
constexpr size_t SZ_WCAT2 = 64 * 256;
constexpr size_t OFF_WF   = OFF_WCAT2 + SZ_WCAT2;
constexpr size_t SZ_WF    = 64 * 64;
constexpr size_t OFF_BF   = OFF_WF + SZ_WF;
constexpr size_t SZ_BF    = 128;
constexpr size_t SCRATCH_TOTAL = OFF_BF + SZ_BF;
}  // namespace cfg
using namespace cfg;

__device__ float  g_scratch[SCRATCH_TOTAL];
__device__ int    g_knn_idx[NEDGE];
__device__ double g_sum[128];
__device__ double g_sumsq[128];
__device__ float  g_sc[128];
__device__ float  g_cc[128];

// ---------------------------------------------------------------------------
__device__ __forceinline__ ull pack2(float x, float y) {
    ull r; asm("mov.b64 %0, {%1, %2};" : "=l"(r) : "f"(x), "f"(y)); return r;
}
__device__ __forceinline__ void fma2(ull& d, ull a, ull b) {
    asm("fma.rn.f32x2 %0, %1, %2, %0;" : "+l"(d) : "l"(a), "l"(b));
}
__device__ __forceinline__ float2 unpack2(ull v) {
    float2 f; asm("mov.b64 {%0, %1}, %2;" : "=f"(f.x), "=f"(f.y) : "l"(v)); return f;
}

// ---------------------------------------------------------------------------
// Merged prep: blocks [0,128) wcat1, [128,192) wcat2, [192,1216) rowsq(C=256)
// ---------------------------------------------------------------------------
__global__ void prep_kernel(const float* __restrict__ c1w0, float* __restrict__ Wcat1,
                            const float* __restrict__ c2w0, float* __restrict__ Wcat2,
                            const float* __restrict__ X0, float* __restrict__ sq) {
    int b = blockIdx.x;
    int t = threadIdx.x;
    if (b < 128) {
        int e = b * 256 + t;
        int kk = e >> 7, n = e & 127;
        float v;
        if (n < 64) v = c1w0[kk * 64 + n] - c1w0[(kk + 256) * 64 + n];
        else        v = c1w0[(kk + 256) * 64 + (n - 64)];
        Wcat1[e] = v;
    } else if (b < 192) {
        int e = (b - 128) * 256 + t;
        int kk = e >> 8, n = e & 255;
        float v;
        if (n < 128) v = c2w0[kk * 128 + n] - c2w0[(kk + 64) * 128 + n];
        else         v = c2w0[(kk + 64) * 128 + (n - 128)];
        Wcat2[e] = v;
    } else {
        int row  = (b - 192) * 8 + (t >> 5);
        int lane = t & 31;
        const float* x = X0 + (size_t)row * 256;
        float a = 0.f;
        #pragma unroll
        for (int c = lane; c < 256; c += 32) { float v = x[c]; a = fmaf(v, v, a); }
        #pragma unroll
        for (int o = 16; o; o >>= 1) a += __shfl_xor_sync(0xffffffffu, a, o);
        if (lane == 0) sq[row] = a;
    }
}

// ---------------------------------------------------------------------------
// Distance matrix: symmetric triangular tiles, split-half B cols,
// double-buffered smem pipeline (1 barrier per K-step).
// ---------------------------------------------------------------------------
template <int C>
__global__ void __launch_bounds__(256, 2)
dist_kernel(const float* __restrict__ X, const float* __restrict__ sq,
            float* __restrict__ D) {
    __shared__ float As[2][16][128];
    __shared__ float Bs[2][16][128];
    int b  = blockIdx.z;
    const float* Xb  = X  + (size_t)b * NN_ * C;
    const float* sqb = sq + (size_t)b * NN_;
    float* Db = D + (size_t)b * NN_ * NN_;

    int rem = blockIdx.x, bi = 0;
    while (rem >= 8 - bi) { rem -= 8 - bi; bi++; }
    int bj = bi + rem;
    int i0 = bi * 128, j0 = bj * 128;

    int t  = threadIdx.x;
    int tx = t & 15, ty = t >> 4;
    int c0 = tx * 4;
    int c1 = 64 + tx * 4;

    int lr0 = (t >> 2), lr1 = lr0 + 64;
    int lkk = (t & 3) * 4;

    ull acc[8][4];
    #pragma unroll
    for (int i = 0; i < 8; i++)
        #pragma unroll
        for (int j = 0; j < 4; j++) acc[i][j] = 0ull;

    {
        float4 va0 = *reinterpret_cast<const float4*>(&Xb[(size_t)(i0 + lr0) * C + lkk]);
        float4 va1 = *reinterpret_cast<const float4*>(&Xb[(size_t)(i0 + lr1) * C + lkk]);
        float4 vb0 = *reinterpret_cast<const float4*>(&Xb[(size_t)(j0 + lr0) * C + lkk]);
        float4 vb1 = *reinterpret_cast<const float4*>(&Xb[(size_t)(j0 + lr1) * C + lkk]);
        As[0][lkk + 0][lr0] = va0.x; As[0][lkk + 1][lr0] = va0.y;
        As[0][lkk + 2][lr0] = va0.z; As[0][lkk + 3][lr0] = va0.w;
        As[0][lkk + 0][lr1] = va1.x; As[0][lkk + 1][lr1] = va1.y;
        As[0][lkk + 2][lr1] = va1.z; As[0][lkk + 3][lr1] = va1.w;
        Bs[0][lkk + 0][lr0] = vb0.x; Bs[0][lkk + 1][lr0] = vb0.y;
        Bs[0][lkk + 2][lr0] = vb0.z; Bs[0][lkk + 3][lr0] = vb0.w;
        Bs[0][lkk + 0][lr1] = vb1.x; Bs[0][lkk + 1][lr1] = vb1.y;
        Bs[0][lkk + 2][lr1] = vb1.z; Bs[0][lkk + 3][lr1] = vb1.w;
    }
    __syncthreads();

    constexpr int NT = C / 16;
    for (int kt = 0; kt < NT; kt++) {
        int cur = kt & 1;
        float4 pa0, pa1, pb0, pb1;
        if (kt + 1 < NT) {
            int k0n = (kt + 1) * 16;
            pa0 = *reinterpret_cast<const float4*>(&Xb[(size_t)(i0 + lr0) * C + k0n + lkk]);
            pa1 = *reinterpret_cast<const float4*>(&Xb[(size_t)(i0 + lr1) * C + k0n + lkk]);
            pb0 = *reinterpret_cast<const float4*>(&Xb[(size_t)(j0 + lr0) * C + k0n + lkk]);
            pb1 = *reinterpret_cast<const float4*>(&Xb[(size_t)(j0 + lr1) * C + k0n + lkk]);
        }
        #pragma unroll
        for (int kk = 0; kk < 16; kk++) {
            float4 a0 = *reinterpret_cast<const float4*>(&As[cur][kk][ty * 8]);
            float4 a1 = *reinterpret_cast<const float4*>(&As[cur][kk][ty * 8 + 4]);
            float4 b0 = *reinterpret_cast<const float4*>(&Bs[cur][kk][c0]);
            float4 b1 = *reinterpret_cast<const float4*>(&Bs[cur][kk][c1]);
            ull rb[4] = {pack2(b0.x, b0.y), pack2(b0.z, b0.w),
                         pack2(b1.x, b1.y), pack2(b1.z, b1.w)};
            float ra[8] = {a0.x, a0.y, a0.z, a0.w, a1.x, a1.y, a1.z, a1.w};
            #pragma unroll
            for (int i = 0; i < 8; i++) {
                ull ai = pack2(ra[i], ra[i]);
                #pragma unroll
                for (int j = 0; j < 4; j++) fma2(acc[i][j], ai, rb[j]);
            }
        }
        if (kt + 1 < NT) {
            int nxt = cur ^ 1;
            As[nxt][lkk + 0][lr0] = pa0.x; As[nxt][lkk + 1][lr0] = pa0.y;
            As[nxt][lkk + 2][lr0] = pa0.z; As[nxt][lkk + 3][lr0] = pa0.w;
            As[nxt][lkk + 0][lr1] = pa1.x; As[nxt][lkk + 1][lr1] = pa1.y;
            As[nxt][lkk + 2][lr1] = pa1.z; As[nxt][lkk + 3][lr1] = pa1.w;
            Bs[nxt][lkk + 0][lr0] = pb0.x; Bs[nxt][lkk + 1][lr0] = pb0.y;
            Bs[nxt][lkk + 2][lr0] = pb0.z; Bs[nxt][lkk + 3][lr0] = pb0.w;
            Bs[nxt][lkk + 0][lr1] = pb1.x; Bs[nxt][lkk + 1][lr1] = pb1.y;
            Bs[nxt][lkk + 2][lr1] = pb1.z; Bs[nxt][lkk + 3][lr1] = pb1.w;
        }
        __syncthreads();
    }

    float sj[8];
    #pragma unroll
    for (int j = 0; j < 4; j++) { sj[j] = sqb[j0 + c0 + j]; sj[4 + j] = sqb[j0 + c1 + j]; }

    float o[8][8];
    #pragma unroll
    for (int i = 0; i < 8; i++) {
        float si = sqb[i0 + ty * 8 + i];
        #pragma unroll
        for (int j = 0; j < 4; j++) {
            float2 u = unpack2(acc[i][j]);
            o[i][j * 2]     = si + sj[j * 2]     - 2.f * u.x;
            o[i][j * 2 + 1] = si + sj[j * 2 + 1] - 2.f * u.y;
        }
    }
    #pragma unroll
    for (int i = 0; i < 8; i++) {
        int gi = i0 + ty * 8 + i;
        *reinterpret_cast<float4*>(&Db[(size_t)gi * NN_ + j0 + c0]) =
            make_float4(o[i][0], o[i][1], o[i][2], o[i][3]);
        *reinterpret_cast<float4*>(&Db[(size_t)gi * NN_ + j0 + c1]) =
            make_float4(o[i][4], o[i][5], o[i][6], o[i][7]);
    }
    if (bi != bj) {
        #pragma unroll
        for (int j = 0; j < 8; j++) {
            int gj = j0 + ((j < 4) ? (c0 + j) : (c1 + j - 4));
            float4* dst = reinterpret_cast<float4*>(&Db[(size_t)gj * NN_ + i0 + ty * 8]);
            dst[0] = make_float4(o[0][j], o[1][j], o[2][j], o[3][j]);
            dst[1] = make_float4(o[4][j], o[5][j], o[6][j], o[7][j]);
        }
    }
}

// ---------------------------------------------------------------------------
// Top-20 smallest per row; one warp per row; tree-min + redux argmin.
// ---------------------------------------------------------------------------
__global__ void topk_kernel(const float* __restrict__ D, int* __restrict__ idx) {
    int row  = blockIdx.x * 8 + (threadIdx.x >> 5);
    int lane = threadIdx.x & 31;
    const float4* d4 = reinterpret_cast<const float4*>(D + (size_t)row * NN_);
    float v[32];
    #pragma unroll
    for (int q = 0; q < 8; q++) {
        float4 x = d4[lane + 32 * q];
        v[4 * q + 0] = x.x; v[4 * q + 1] = x.y;
        v[4 * q + 2] = x.z; v[4 * q + 3] = x.w;
    }

    for (int s = 0; s < KNN; s++) {
        float m16[16];
        #pragma unroll
        for (int q = 0; q < 16; q++) m16[q] = fminf(v[q], v[q + 16]);
        float m8[8];
        #pragma unroll
        for (int q = 0; q < 8; q++) m8[q] = fminf(m16[q], m16[q + 8]);
        float m4[4];
        #pragma unroll
        for (int q = 0; q < 4; q++) m4[q] = fminf(m8[q], m8[q + 4]);
        float m = fminf(fminf(m4[0], m4[2]), fminf(m4[1], m4[3]));
        unsigned mask = 0u;
        #pragma unroll
        for (int q = 0; q < 32; q++) mask |= (v[q] == m) ? (1u << q) : 0u;
        int slot = __ffs(mask) - 1;
        int gidx = 4 * lane + 128 * (slot >> 2) + (slot & 3);

        unsigned kb = __float_as_uint(m);
        kb = (kb & 0x80000000u) ? ~kb : (kb | 0x80000000u);
        unsigned mk;
        asm("redux.sync.min.u32 %0, %1, 0xffffffff;" : "=r"(mk) : "r"(kb));
        unsigned ball = __ballot_sync(0xffffffffu, kb == mk);
        int src = __ffs(ball) - 1;
        int bidx = __shfl_sync(0xffffffffu, gidx, src);
        if (lane == 0) idx[row * KNN + s] = bidx;
        if (lane == src) {
            #pragma unroll
            for (int q = 0; q < 32; q++) if (q == slot) v[q] = 3.4e38f;
        }
    }
}

// ---------------------------------------------------------------------------
// Generic fp32 GEMM (f32x2, split-half cols for TN==8), double-buffered smem.
// ---------------------------------------------------------------------------
template <int BM, int BN, int TM, int TN, bool BIAS_RELU, bool STATS>
__global__ void __launch_bounds__(256, 2)
gemm_nodes(const float* __restrict__ A, const float* __restrict__ Bm,
           const float* __restrict__ bias, float* __restrict__ Cmat,
           int M, int N, int K) {
    constexpr int BK = 16;
    constexpr int TX = BN / TN;
    static_assert(TX == 16 && (256 / TX) * TM == BM, "layout");
    constexpr int N4A = BM / 64;
    constexpr int N4B = BN / 64;
    __shared__ float smem[2 * BK * (BM + BN)];
    int block_m = blockIdx.y * BM, block_n = blockIdx.x * BN;
    int t  = threadIdx.x;
    int tx = t % TX, ty = t / TX;
    int c0 = tx * 4;
    int c1 = BN / 2 + tx * 4;

    int ar  = t >> 2;                     // rows 0..63
    int akk = (t & 3) * 4;
    int bkk = t >> 4;
    int bcc = (t & 15) * 4;

    ull acc[TM][TN / 2];
    #pragma unroll
    for (int i = 0; i < TM; i++)
        #pragma unroll
        for (int j = 0; j < TN / 2; j++) acc[i][j] = 0ull;

    {
        float* As0 = smem;
        float* Bs0 = smem + 2 * BK * BM;
        #pragma unroll
        for (int it = 0; it < N4A; it++) {
            int r = ar + it * 64;
            float4 v = *reinterpret_cast<const float4*>(&A[(size_t)(block_m + r) * K + akk]);
            As0[(akk + 0) * BM + r] = v.x; As0[(akk + 1) * BM + r] = v.y;
            As0[(akk + 2) * BM + r] = v.z; As0[(akk + 3) * BM + r] = v.w;
        }
        #pragma unroll
        for (int it = 0; it < N4B; it++) {
            int cc = bcc + it * 64;
            *reinterpret_cast<float4*>(&Bs0[bkk * BN + cc]) =
                *reinterpret_cast<const float4*>(&Bm[(size_t)bkk * N + block_n + cc]);
        }
    }
    __syncthreads();

    int NT = K / BK;
    for (int kt = 0; kt < NT; kt++) {
        int cur = kt & 1;
        float* Asb = smem + cur * BK * BM;
        float* Bsb = smem + 2 * BK * BM + cur * BK * BN;
        float4 pa[N4A], pb[N4B];
        if (kt + 1 < NT) {
            int k0n = (kt + 1) * BK;
            #pragma unroll
            for (int it = 0; it < N4A; it++) {
                int r = ar + it * 64;
                pa[it] = *reinterpret_cast<const float4*>(&A[(size_t)(block_m + r) * K + k0n + akk]);
            }
            #pragma unroll
            for (int it = 0; it < N4B; it++) {
                int cc = bcc + it * 64;
                pb[it] = *reinterpret_cast<const float4*>(&Bm[(size_t)(k0n + bkk) * N + block_n + cc]);
            }
        }
        #pragma unroll
        for (int kk = 0; kk < BK; kk++) {
            float ra[TM];
            #pragma unroll
            for (int i4 = 0; i4 < TM / 4; i4++) {
                float4 a = *reinterpret_cast<const float4*>(&Asb[kk * BM + ty * TM + i4 * 4]);
                ra[i4 * 4 + 0] = a.x; ra[i4 * 4 + 1] = a.y;
                ra[i4 * 4 + 2] = a.z; ra[i4 * 4 + 3] = a.w;
            }
            ull rb[TN / 2];
            {
                float4 bq0 = *reinterpret_cast<const float4*>(&Bsb[kk * BN + c0]);
                rb[0] = pack2(bq0.x, bq0.y);
                rb[1] = pack2(bq0.z, bq0.w);
                if (TN == 8) {
                    float4 bq1 = *reinterpret_cast<const float4*>(&Bsb[kk * BN + c1]);
                    rb[2] = pack2(bq1.x, bq1.y);
                    rb[3] = pack2(bq1.z, bq1.w);
                }
            }
            #pragma unroll
            for (int i = 0; i < TM; i++) {
                ull ai = pack2(ra[i], ra[i]);
                #pragma unroll
                for (int j = 0; j < TN / 2; j++) fma2(acc[i][j], ai, rb[j]);
            }
        }
        if (kt + 1 < NT) {
            float* Asn = smem + (cur ^ 1) * BK * BM;
            float* Bsn = smem + 2 * BK * BM + (cur ^ 1) * BK * BN;
            #pragma unroll
            for (int it = 0; it < N4A; it++) {
                int r = ar + it * 64;
                Asn[(akk + 0) * BM + r] = pa[it].x; Asn[(akk + 1) * BM + r] = pa[it].y;
                Asn[(akk + 2) * BM + r] = pa[it].z; Asn[(akk + 3) * BM + r] = pa[it].w;
            }
            #pragma unroll
            for (int it = 0; it < N4B; it++) {
                int cc = bcc + it * 64;
                *reinterpret_cast<float4*>(&Bsn[bkk * BN + cc]) = pb[it];
            }
        }
        __syncthreads();
    }

    float bb[TN];
    if (BIAS_RELU) {
        #pragma unroll
        for (int j = 0; j < TN; j++)
            bb[j] = bias[block_n + ((j < 4) ? (c0 + j) : (c1 + j - 4))];
    }
    float ps[TN], ps2[TN];
    #pragma unroll
    for (int j = 0; j < TN; j++) { ps[j] = 0.f; ps2[j] = 0.f; }

    #pragma unroll
    for (int i = 0; i < TM; i++) {
        float v[TN];
        #pragma unroll
        for (int j = 0; j < TN / 2; j++) {
            float2 u = unpack2(acc[i][j]);
            v[j * 2] = u.x; v[j * 2 + 1] = u.y;
        }
        #pragma unroll
        for (int j = 0; j < TN; j++) {
            if (BIAS_RELU) v[j] = fmaxf(v[j] + bb[j], 0.f);
            if (STATS) { ps[j] += v[j]; ps2[j] = fmaf(v[j], v[j], ps2[j]); }
        }
        int r = block_m + ty * TM + i;
        *reinterpret_cast<float4*>(&Cmat[(size_t)r * N + block_n + c0]) =
            make_float4(v[0], v[1], v[2], v[3]);
        if (TN == 8)
            *reinterpret_cast<float4*>(&Cmat[(size_t)r * N + block_n + c1]) =
                make_float4(v[4], v[5], v[6], v[7]);
    }

    if (STATS) {
        // 16 groups x BN sums + 16 x BN sumsq <= 2*BK*(BM+BN) floats always
        #pragma unroll
        for (int j = 0; j < TN; j++) {
            int col = (j < 4) ? (c0 + j) : (c1 + j - 4);
            smem[ty * BN + col]           = ps[j];
            smem[16 * BN + ty * BN + col] = ps2[j];
        }
        __syncthreads();
        if (t < BN) {
            float s = 0.f, s2 = 0.f;
            #pragma unroll
            for (int g = 0; g < 16; g++) { s += smem[g * BN + t]; s2 += smem[16 * BN + g * BN + t]; }
            atomicAdd(&g_sum[block_n + t],   (double)s);
            atomicAdd(&g_sumsq[block_n + t], (double)s2);
        }
    }
}

// ---------------------------------------------------------------------------
// Layer-1 edge GEMM: full A(128x64)+B(64x64) in smem, 2 barriers.
// ---------------------------------------------------------------------------
__global__ void __launch_bounds__(256, 2)
gemm_edge1(const float* __restrict__ PQ, const int* __restrict__ IDXp,
           const float* __restrict__ abias, const float* __restrict__ W,
           const float* __restrict__ obias, float* __restrict__ H) {
    __shared__ float As[64 * 128];
    __shared__ float Bs[64 * 64];
    __shared__ float s_ab[64];
    int t = threadIdx.x;
    int block_m = blockIdx.x * 128;
    if (t < 64) s_ab[t] = abias[t];
    #pragma unroll
    for (int i = 0; i < 4; i++)
        *reinterpret_cast<float4*>(&Bs[i * 1024 + t * 4]) =
            *reinterpret_cast<const float4*>(&W[i * 1024 + t * 4]);
    int r  = t >> 1;
    int co = (t & 1) * 32;
    {
        int e  = block_m + r;
        int bi = e / KNN;
        int qo = ((bi >> 10) << 10) + IDXp[e];
        const float* Pp = PQ + (size_t)bi * 128 + co;
        const float* Qp = PQ + (size_t)qo * 128 + 64 + co;
        float4 pv[8], qv[8];
        #pragma unroll
        for (int q = 0; q < 8; q++) {
            pv[q] = *reinterpret_cast<const float4*>(Pp + q * 4);
            qv[q] = *reinterpret_cast<const float4*>(Qp + q * 4);
        }
        __syncthreads();
        #pragma unroll
        for (int q = 0; q < 8; q++) {
            int c = co + q * 4;
            As[(c + 0) * 128 + r] = fmaxf(pv[q].x + qv[q].x + s_ab[c + 0], 0.f);
            As[(c + 1) * 128 + r] = fmaxf(pv[q].y + qv[q].y + s_ab[c + 1], 0.f);
            As[(c + 2) * 128 + r] = fmaxf(pv[q].z + qv[q].z + s_ab[c + 2], 0.f);
            As[(c + 3) * 128 + r] = fmaxf(pv[q].w + qv[q].w + s_ab[c + 3], 0.f);
        }
    }
    __syncthreads();

    int tx = t & 15, ty = t >> 4;
    ull acc[8][2];
    #pragma unroll
    for (int i = 0; i < 8; i++) { acc[i][0] = 0ull; acc[i][1] = 0ull; }

    #pragma unroll 16
    for (int kk = 0; kk < 64; kk++) {
        float4 a0 = *reinterpret_cast<const float4*>(&As[kk * 128 + ty * 8]);
        float4 a1 = *reinterpret_cast<const float4*>(&As[kk * 128 + ty * 8 + 4]);
        float4 b0 = *reinterpret_cast<const float4*>(&Bs[kk * 64 + tx * 4]);
        ull rb0 = pack2(b0.x, b0.y), rb1 = pack2(b0.z, b0.w);
        float ra[8] = {a0.x, a0.y, a0.z, a0.w, a1.x, a1.y, a1.z, a1.w};
        #pragma unroll
        for (int i = 0; i < 8; i++) {
            ull ai = pack2(ra[i], ra[i]);
            fma2(acc[i][0], ai, rb0);
            fma2(acc[i][1], ai, rb1);
        }
    }

    float ob[4];
    #pragma unroll
    for (int j = 0; j < 4; j++) ob[j] = obias[tx * 4 + j];
    float ps[4] = {0, 0, 0, 0}, ps2[4] = {0, 0, 0, 0};
    #pragma unroll
    for (int i = 0; i < 8; i++) {
        float2 u0 = unpack2(acc[i][0]), u1 = unpack2(acc[i][1]);
        float v[4] = {u0.x, u0.y, u1.x, u1.y};
        #pragma unroll
        for (int j = 0; j < 4; j++) {
            v[j] = fmaxf(v[j] + ob[j], 0.f);
            ps[j] += v[j]; ps2[j] = fmaf(v[j], v[j], ps2[j]);
        }
        int rr = block_m + ty * 8 + i;
        *reinterpret_cast<float4*>(&H[(size_t)rr * 64 + tx * 4]) =
            make_float4(v[0], v[1], v[2], v[3]);
    }
    __syncthreads();
    #pragma unroll
    for (int j = 0; j < 4; j++) {
        As[ty * 64 + tx * 4 + j]        = ps[j];
        As[1024 + ty * 64 + tx * 4 + j] = ps2[j];
    }
    __syncthreads();
    if (t < 64) {
        float s = 0.f, s2 = 0.f;
        #pragma unroll
        for (int g = 0; g < 16; g++) { s += As[g * 64 + t]; s2 += As[1024 + g * 64 + t]; }
        atomicAdd(&g_sum[t],   (double)s);
        atomicAdd(&g_sumsq[t], (double)s2);
    }
}

// ---------------------------------------------------------------------------
// Conv1: stats of recomputed edge features relu(P+Q+b). Grid-stride loop.
// ---------------------------------------------------------------------------
template <int CH>
__global__ void stats_edges_kernel(const float* __restrict__ PQ,
                                   const int* __restrict__ IDXp,
                                   const float* __restrict__ bias) {
    constexpr int G = 256 / CH;
    int c = threadIdx.x % CH;
    int g = threadIdx.x / CH;
    int stride = gridDim.x * G;
    float bb = bias[c];
    float s = 0.f, s2 = 0.f;
    for (int node = blockIdx.x * G + g; node < NROW; node += stride) {
        float p = PQ[(size_t)node * (2 * CH) + c] + bb;
        int base = (node >> 10) << 10;
        const int* ix = IDXp + node * KNN;
        #pragma unroll 5
        for (int kk = 0; kk < KNN; kk++) {
            int j = base + ix[kk];
            float v = fmaxf(p + PQ[(size_t)j * (2 * CH) + CH + c], 0.f);
            s += v; s2 = fmaf(v, v, s2);
        }
    }
    __shared__ float sh[2][256];
    sh[0][threadIdx.x] = s; sh[1][threadIdx.x] = s2;
    __syncthreads();
    if (g == 0) {
        #pragma unroll
        for (int gg = 1; gg < G; gg++) { s += sh[0][gg * CH + c]; s2 += sh[1][gg * CH + c]; }
        atomicAdd(&g_sum[c],   (double)s);
        atomicAdd(&g_sumsq[c], (double)s2);
    }
}

// ---------------------------------------------------------------------------
// Conv2: fused stats + per-node max/min (1 pass). Grid-stride loop.
// ---------------------------------------------------------------------------
__global__ void stats_minmax_edges_kernel(const float* __restrict__ PQ2,
                                          const int* __restrict__ IDXp,
                                          const float* __restrict__ bias,
                                          float* __restrict__ vmax,
                                          float* __restrict__ vmin) {
    int c = threadIdx.x & 127;
    int g = threadIdx.x >> 7;
    int stride = gridDim.x * 2;
    float bb = bias[c];
    float s = 0.f, s2 = 0.f;
    for (int node = blockIdx.x * 2 + g; node < NROW; node += stride) {
        float p = PQ2[(size_t)node * 256 + c] + bb;
        int base = (node >> 10) << 10;
        const int* ix = IDXp + node * KNN;
        float mx = -3.4e38f, mn = 3.4e38f;
        #pragma unroll 5
        for (int kk = 0; kk < KNN; kk++) {
            int j = base + ix[kk];
            float v = fmaxf(p + PQ2[(size_t)j * 256 + 128 + c], 0.f);
            s += v; s2 = fmaf(v, v, s2);
            mx = fmaxf(mx, v); mn = fminf(mn, v);
        }
        vmax[(size_t)node * 128 + c] = mx;
        vmin[(size_t)node * 128 + c] = mn;
    }
    __shared__ float sh[2][256];
    sh[0][threadIdx.x] = s; sh[1][threadIdx.x] = s2;
    __syncthreads();
    if (g == 0) {
        s  += sh[0][128 + c];
        s2 += sh[1][128 + c];
        atomicAdd(&g_sum[c],   (double)s);
        atomicAdd(&g_sumsq[c], (double)s2);
    }
}

// hcat[bi,64+c] = s>=0 ? s*vmax+cc : s*vmin+cc
__global__ void apply_minmax_kernel(const float* __restrict__ vmax,
                                    const float* __restrict__ vmin,
                                    float* __restrict__ hcat) {
    int i = blockIdx.x * 256 + threadIdx.x;
    int c = i & 127, bi = i >> 7;
    float s = g_sc[c], cc = g_cc[c];
    float v = (s >= 0.f) ? vmax[i] : vmin[i];
    hcat[(size_t)bi * 192 + 64 + c] = fmaf(s, v, cc);
}

// ---------------------------------------------------------------------------
template <int CH>
__global__ void finalize_kernel(const float* __restrict__ gam,
                                const float* __restrict__ bet, int E) {
    int c = threadIdx.x;
    if (c < CH) {
        double mu  = g_sum[c] / (double)E;
        double var = g_sumsq[c] / (double)E - mu * mu;
        float s = gam[c] * rsqrtf((float)var + 1e-5f);
        g_sc[c] = s;
        g_cc[c] = bet[c] - (float)mu * s;
    }
    g_sum[c] = 0.0; g_sumsq[c] = 0.0;
}

__global__ void fold_kernel(const float* __restrict__ gam, const float* __restrict__ bet,
                            const float* __restrict__ W, const float* __restrict__ bias,
                            int E, float* __restrict__ Wf, float* __restrict__ bf) {
    __shared__ float s_s[64], s_c[64];
    int t = threadIdx.x;
    if (t < 64) {
        double mu  = g_sum[t] / (double)E;
        double var = g_sumsq[t] / (double)E - mu * mu;
        float s = gam[t] * rsqrtf((float)var + 1e-5f);
        s_s[t] = s;
        s_c[t] = bet[t] - (float)mu * s;
        g_sum[t] = 0.0; g_sumsq[t] = 0.0;
    } else if (t < 128) {
        g_sum[t] = 0.0; g_sumsq[t] = 0.0;
    }
    __syncthreads();
    for (int e = t; e < 64 * 64; e += 256) Wf[e] = s_s[e >> 6] * W[e];
    if (t < 64) {
        float acc = bias[t];
        #pragma unroll 4
        for (int kk = 0; kk < 64; kk++) acc = fmaf(s_c[kk], W[kk * 64 + t], acc);
        bf[t] = acc;
    }
}

// ---------------------------------------------------------------------------
__global__ void maxagg1_kernel(const float* __restrict__ H, float* __restrict__ hcat,
                               float* __restrict__ x1, float* __restrict__ sq) {
    int bi = blockIdx.x;
    int c  = threadIdx.x;
    const float* h = H + (size_t)bi * (KNN * 64) + c;
    float s = g_sc[c], cc = g_cc[c];
    float m = -3.4e38f;
    #pragma unroll
    for (int kk = 0; kk < KNN; kk++) m = fmaxf(m, fmaf(s, h[kk * 64], cc));
    hcat[(size_t)bi * 192 + c] = m;
    x1[(size_t)bi * 64 + c]    = m;
    float q = m * m;
    #pragma unroll
    for (int o = 16; o; o >>= 1) q += __shfl_xor_sync(0xffffffffu, q, o);
    __shared__ float sh[2];
    if ((c & 31) == 0) sh[c >> 5] = q;
    __syncthreads();
    if (c == 0) sq[bi] = sh[0] + sh[1];
}

__global__ void apply_bn_kernel(const float* __restrict__ Y, float* __restrict__ out) {
    int i = blockIdx.x * 256 + threadIdx.x;
    int c = i & 127;
    out[i] = fmaf(g_sc[c], Y[i], g_cc[c]);
}

// ---------------------------------------------------------------------------
extern "C" void kernel_launch(void* const* d_in, const int* in_sizes, int n_in,
                              void* d_out, int out_size) {
    const float* x0    = (const float*)d_in[1];
    const float* c1w0  = (const float*)d_in[2];
    const float* c1b0  = (const float*)d_in[3];
    const float* c1g0  = (const float*)d_in[4];
    const float* c1be0 = (const float*)d_in[5];
    const float* c1w1  = (const float*)d_in[6];
    const float* c1b1  = (const float*)d_in[7];
    const float* c1g1  = (const float*)d_in[8];
    const float* c1be1 = (const float*)d_in[9];
    const float* c1w2  = (const float*)d_in[10];
    const float* c1b2  = (const float*)d_in[11];
    const float* c1g2  = (const float*)d_in[12];
    const float* c1be2 = (const float*)d_in[13];
    const float* c2w0  = (const float*)d_in[14];
    const float* c2b0  = (const float*)d_in[15];
    const float* c2g0  = (const float*)d_in[16];
    const float* c2be0 = (const float*)d_in[17];
    const float* lw    = (const float*)d_in[18];
    const float* lb    = (const float*)d_in[19];
    const float* lg    = (const float*)d_in[20];
    const float* lbe   = (const float*)d_in[21];
    float* out = (float*)d_out;

    void* sp = nullptr; cudaGetSymbolAddress(&sp, g_scratch);
    float* S = (float*)sp;
    void* ip = nullptr; cudaGetSymbolAddress(&ip, g_knn_idx);
    int* IDX = (int*)ip;

    float* D     = S + OFF_D;
    float* PQ    = S + OFF_PQ;
    float* PQ2   = S + OFF_PQ2;
    float* H1    = S + OFF_H1;
    float* H2    = S + OFF_H2;
    float* HCAT  = S + OFF_HCAT;
    float* X1    = S + OFF_X1;
    float* Y0    = S + OFF_Y0;
    float* SQ    = S + OFF_SQ;
    float* WCAT  = S + OFF_WCAT;
    float* WCAT2 = S + OFF_WCAT2;
    float* WF    = S + OFF_WF;
    float* BF    = S + OFF_BF;
    float* VMAX  = S + OFF_H1;
    float* VMIN  = S + OFF_H1 + (size_t)NROW * 128;

    prep_kernel<<<192 + NROW / 8, 256>>>(c1w0, WCAT, c2w0, WCAT2, x0, SQ);

    // ---- EdgeConv 1 ----
    dist_kernel<256><<<dim3(36, 1, 8), 256>>>(x0, SQ, D);
    topk_kernel<<<NROW / 8, 256>>>(D, IDX);
    gemm_nodes<64, 64, 4, 4, false, false><<<dim3(2, NROW / 64), 256>>>(x0, WCAT, nullptr, PQ, NROW, 128, 256);
    stats_edges_kernel<64><<<512, 256>>>(PQ, IDX, c1b0);
    fold_kernel<<<1, 256>>>(c1g0, c1be0, c1w1, c1b1, NEDGE, WF, BF);
    gemm_edge1<<<NEDGE / 128, 256>>>(PQ, IDX, c1b0, WF, BF, H1);
    fold_kernel<<<1, 256>>>(c1g1, c1be1, c1w2, c1b2, NEDGE, WF, BF);
    gemm_nodes<128, 64, 8, 4, true, true><<<dim3(1, NEDGE / 128), 256>>>(H1, WF, BF, H2, NEDGE, 64, 64);
    finalize_kernel<64><<<1, 128>>>(c1g2, c1be2, NEDGE);
    maxagg1_kernel<<<NROW, 64>>>(H2, HCAT, X1, SQ);

    // ---- EdgeConv 2 ----
    dist_kernel<64><<<dim3(36, 1, 8), 256>>>(X1, SQ, D);
    topk_kernel<<<NROW / 8, 256>>>(D, IDX);
    gemm_nodes<64, 128, 4, 8, false, false><<<dim3(2, NROW / 64), 256>>>(X1, WCAT2, nullptr, PQ2, NROW, 256, 64);
    stats_minmax_edges_kernel<<<512, 256>>>(PQ2, IDX, c2b0, VMAX, VMIN);
    finalize_kernel<128><<<1, 128>>>(c2g0, c2be0, NEDGE);
    apply_minmax_kernel<<<NROW * 128 / 256, 256>>>(VMAX, VMIN, HCAT);

    // ---- Final Linear + BN ----
    gemm_nodes<64, 64, 4, 4, true, true><<<dim3(2, NROW / 64), 256>>>(HCAT, lw, lb, Y0, NROW, 128, 192);
    finalize_kernel<128><<<1, 128>>>(lg, lbe, NROW);
    apply_bn_kernel<<<NROW * 128 / 256, 256>>>(Y0, out);
}

// round 16
// speedup vs baseline: 1.3780x; 1.0019x over previous
#include <cuda_runtime.h>
#include <cstdint>

// ---------------------------------------------------------------------------
// DGCNN: 2x EdgeConv (dynamic kNN) + final MLP, training-mode BatchNorm.
// R16 = R15 kernels unchanged + stream-level overlap: PQ gemms run on a
// second stream concurrently with dist/topk (event fork/join, capture-legal).
// ---------------------------------------------------------------------------

typedef unsigned long long ull;

namespace cfg {
constexpr int BB   = 8;
constexpr int NN_  = 1024;
constexpr int KNN  = 20;
constexpr int NROW  = BB * NN_;        // 8192
constexpr int NEDGE = NROW * KNN;      // 163840

constexpr size_t OFF_D    = 0;
constexpr size_t SZ_D     = (size_t)BB * NN_ * NN_;
constexpr size_t OFF_PQ   = OFF_D + SZ_D;
constexpr size_t SZ_PQ    = (size_t)NROW * 128;
constexpr size_t OFF_PQ2  = OFF_PQ + SZ_PQ;
constexpr size_t SZ_PQ2   = (size_t)NROW * 256;
constexpr size_t OFF_H1   = OFF_PQ2 + SZ_PQ2;
constexpr size_t SZ_H64   = (size_t)NEDGE * 64;
constexpr size_t OFF_H2   = OFF_H1 + SZ_H64;
constexpr size_t OFF_HCAT = OFF_H2 + SZ_H64;
constexpr size_t SZ_HCAT  = (size_t)NROW * 192;
constexpr size_t OFF_X1   = OFF_HCAT + SZ_HCAT;
constexpr size_t SZ_X1    = (size_t)NROW * 64;
constexpr size_t OFF_Y0   = OFF_X1 + SZ_X1;
constexpr size_t SZ_Y0    = (size_t)NROW * 128;
constexpr size_t OFF_SQ   = OFF_Y0 + SZ_Y0;
constexpr size_t SZ_SQ    = (size_t)NROW;
constexpr size_t OFF_WCAT = OFF_SQ + SZ_SQ;
constexpr size_t SZ_WCAT  = 256 * 128;
constexpr size_t OFF_WCAT2= OFF_WCAT + SZ_WCAT;
constexpr size_t SZ_WCAT2 = 64 * 256;
constexpr size_t OFF_WF   = OFF_WCAT2 + SZ_WCAT2;
constexpr size_t SZ_WF    = 64 * 64;
constexpr size_t OFF_BF   = OFF_WF + SZ_WF;
constexpr size_t SZ_BF    = 128;
constexpr size_t SCRATCH_TOTAL = OFF_BF + SZ_BF;
}  // namespace cfg
using namespace cfg;

__device__ float  g_scratch[SCRATCH_TOTAL];
__device__ int    g_knn_idx[NEDGE];
__device__ double g_sum[128];
__device__ double g_sumsq[128];
__device__ float  g_sc[128];
__device__ float  g_cc[128];

// ---------------------------------------------------------------------------
__device__ __forceinline__ ull pack2(float x, float y) {
    ull r; asm("mov.b64 %0, {%1, %2};" : "=l"(r) : "f"(x), "f"(y)); return r;
}
__device__ __forceinline__ void fma2(ull& d, ull a, ull b) {
    asm("fma.rn.f32x2 %0, %1, %2, %0;" : "+l"(d) : "l"(a), "l"(b));
}
__device__ __forceinline__ float2 unpack2(ull v) {
    float2 f; asm("mov.b64 {%0, %1}, %2;" : "=f"(f.x), "=f"(f.y) : "l"(v)); return f;
}

// ---------------------------------------------------------------------------
// Merged prep: blocks [0,128) wcat1, [128,192) wcat2, [192,1216) rowsq(C=256)
// ---------------------------------------------------------------------------
__global__ void prep_kernel(const float* __restrict__ c1w0, float* __restrict__ Wcat1,
                            const float* __restrict__ c2w0, float* __restrict__ Wcat2,
                            const float* __restrict__ X0, float* __restrict__ sq) {
    int b = blockIdx.x;
    int t = threadIdx.x;
    if (b < 128) {
        int e = b * 256 + t;
        int kk = e >> 7, n = e & 127;
        float v;
        if (n < 64) v = c1w0[kk * 64 + n] - c1w0[(kk + 256) * 64 + n];
        else        v = c1w0[(kk + 256) * 64 + (n - 64)];
        Wcat1[e] = v;
    } else if (b < 192) {
        int e = (b - 128) * 256 + t;
        int kk = e >> 8, n = e & 255;
        float v;
        if (n < 128) v = c2w0[kk * 128 + n] - c2w0[(kk + 64) * 128 + n];
        else         v = c2w0[(kk + 64) * 128 + (n - 128)];
        Wcat2[e] = v;
    } else {
        int row  = (b - 192) * 8 + (t >> 5);
        int lane = t & 31;
        const float* x = X0 + (size_t)row * 256;
        float a = 0.f;
        #pragma unroll
        for (int c = lane; c < 256; c += 32) { float v = x[c]; a = fmaf(v, v, a); }
        #pragma unroll
        for (int o = 16; o; o >>= 1) a += __shfl_xor_sync(0xffffffffu, a, o);
        if (lane == 0) sq[row] = a;
    }
}

// ---------------------------------------------------------------------------
// Distance matrix: symmetric triangular tiles, split-half B cols,
// double-buffered smem pipeline (1 barrier per K-step).
// ---------------------------------------------------------------------------
template <int C>
__global__ void __launch_bounds__(256, 2)
dist_kernel(const float* __restrict__ X, const float* __restrict__ sq,
            float* __restrict__ D) {
    __shared__ float As[2][16][128];
    __shared__ float Bs[2][16][128];
    int b  = blockIdx.z;
    const float* Xb  = X  + (size_t)b * NN_ * C;
    const float* sqb = sq + (size_t)b * NN_;
    float* Db = D + (size_t)b * NN_ * NN_;

    int rem = blockIdx.x, bi = 0;
    while (rem >= 8 - bi) { rem -= 8 - bi; bi++; }
    int bj = bi + rem;
    int i0 = bi * 128, j0 = bj * 128;

    int t  = threadIdx.x;
    int tx = t & 15, ty = t >> 4;
    int c0 = tx * 4;
    int c1 = 64 + tx * 4;

    int lr0 = (t >> 2), lr1 = lr0 + 64;
    int lkk = (t & 3) * 4;

    ull acc[8][4];
    #pragma unroll
    for (int i = 0; i < 8; i++)
        #pragma unroll
        for (int j = 0; j < 4; j++) acc[i][j] = 0ull;

    {
        float4 va0 = *reinterpret_cast<const float4*>(&Xb[(size_t)(i0 + lr0) * C + lkk]);
        float4 va1 = *reinterpret_cast<const float4*>(&Xb[(size_t)(i0 + lr1) * C + lkk]);
        float4 vb0 = *reinterpret_cast<const float4*>(&Xb[(size_t)(j0 + lr0) * C + lkk]);
        float4 vb1 = *reinterpret_cast<const float4*>(&Xb[(size_t)(j0 + lr1) * C + lkk]);
        As[0][lkk + 0][lr0] = va0.x; As[0][lkk + 1][lr0] = va0.y;
        As[0][lkk + 2][lr0] = va0.z; As[0][lkk + 3][lr0] = va0.w;
        As[0][lkk + 0][lr1] = va1.x; As[0][lkk + 1][lr1] = va1.y;
        As[0][lkk + 2][lr1] = va1.z; As[0][lkk + 3][lr1] = va1.w;
        Bs[0][lkk + 0][lr0] = vb0.x; Bs[0][lkk + 1][lr0] = vb0.y;
        Bs[0][lkk + 2][lr0] = vb0.z; Bs[0][lkk + 3][lr0] = vb0.w;
        Bs[0][lkk + 0][lr1] = vb1.x; Bs[0][lkk + 1][lr1] = vb1.y;
        Bs[0][lkk + 2][lr1] = vb1.z; Bs[0][lkk + 3][lr1] = vb1.w;
    }
    __syncthreads();

    constexpr int NT = C / 16;
    for (int kt = 0; kt < NT; kt++) {
        int cur = kt & 1;
        float4 pa0, pa1, pb0, pb1;
        if (kt + 1 < NT) {
            int k0n = (kt + 1) * 16;
            pa0 = *reinterpret_cast<const float4*>(&Xb[(size_t)(i0 + lr0) * C + k0n + lkk]);
            pa1 = *reinterpret_cast<const float4*>(&Xb[(size_t)(i0 + lr1) * C + k0n + lkk]);
            pb0 = *reinterpret_cast<const float4*>(&Xb[(size_t)(j0 + lr0) * C + k0n + lkk]);
            pb1 = *reinterpret_cast<const float4*>(&Xb[(size_t)(j0 + lr1) * C + k0n + lkk]);
        }
        #pragma unroll
        for (int kk = 0; kk < 16; kk++) {
            float4 a0 = *reinterpret_cast<const float4*>(&As[cur][kk][ty * 8]);
            float4 a1 = *reinterpret_cast<const float4*>(&As[cur][kk][ty * 8 + 4]);
            float4 b0 = *reinterpret_cast<const float4*>(&Bs[cur][kk][c0]);
            float4 b1 = *reinterpret_cast<const float4*>(&Bs[cur][kk][c1]);
            ull rb[4] = {pack2(b0.x, b0.y), pack2(b0.z, b0.w),
                         pack2(b1.x, b1.y), pack2(b1.z, b1.w)};
            float ra[8] = {a0.x, a0.y, a0.z, a0.w, a1.x, a1.y, a1.z, a1.w};
            #pragma unroll
            for (int i = 0; i < 8; i++) {
                ull ai = pack2(ra[i], ra[i]);
                #pragma unroll
                for (int j = 0; j < 4; j++) fma2(acc[i][j], ai, rb[j]);
            }
        }
        if (kt + 1 < NT) {
            int nxt = cur ^ 1;
            As[nxt][lkk + 0][lr0] = pa0.x; As[nxt][lkk + 1][lr0] = pa0.y;
            As[nxt][lkk + 2][lr0] = pa0.z; As[nxt][lkk + 3][lr0] = pa0.w;
            As[nxt][lkk + 0][lr1] = pa1.x; As[nxt][lkk + 1][lr1] = pa1.y;
            As[nxt][lkk + 2][lr1] = pa1.z; As[nxt][lkk + 3][lr1] = pa1.w;
            Bs[nxt][lkk + 0][lr0] = pb0.x; Bs[nxt][lkk + 1][lr0] = pb0.y;
            Bs[nxt][lkk + 2][lr0] = pb0.z; Bs[nxt][lkk + 3][lr0] = pb0.w;
            Bs[nxt][lkk + 0][lr1] = pb1.x; Bs[nxt][lkk + 1][lr1] = pb1.y;
            Bs[nxt][lkk + 2][lr1] = pb1.z; Bs[nxt][lkk + 3][lr1] = pb1.w;
        }
        __syncthreads();
    }

    float sj[8];
    #pragma unroll
    for (int j = 0; j < 4; j++) { sj[j] = sqb[j0 + c0 + j]; sj[4 + j] = sqb[j0 + c1 + j]; }

    float o[8][8];
    #pragma unroll
    for (int i = 0; i < 8; i++) {
        float si = sqb[i0 + ty * 8 + i];
        #pragma unroll
        for (int j = 0; j < 4; j++) {
            float2 u = unpack2(acc[i][j]);
            o[i][j * 2]     = si + sj[j * 2]     - 2.f * u.x;
            o[i][j * 2 + 1] = si + sj[j * 2 + 1] - 2.f * u.y;
        }
    }
    #pragma unroll
    for (int i = 0; i < 8; i++) {
        int gi = i0 + ty * 8 + i;
        *reinterpret_cast<float4*>(&Db[(size_t)gi * NN_ + j0 + c0]) =
            make_float4(o[i][0], o[i][1], o[i][2], o[i][3]);
        *reinterpret_cast<float4*>(&Db[(size_t)gi * NN_ + j0 + c1]) =
            make_float4(o[i][4], o[i][5], o[i][6], o[i][7]);
    }
    if (bi != bj) {
        #pragma unroll
        for (int j = 0; j < 8; j++) {
            int gj = j0 + ((j < 4) ? (c0 + j) : (c1 + j - 4));
            float4* dst = reinterpret_cast<float4*>(&Db[(size_t)gj * NN_ + i0 + ty * 8]);
            dst[0] = make_float4(o[0][j], o[1][j], o[2][j], o[3][j]);
            dst[1] = make_float4(o[4][j], o[5][j], o[6][j], o[7][j]);
        }
    }
}

// ---------------------------------------------------------------------------
// Top-20 smallest per row; one warp per row; tree-min + redux argmin.
// ---------------------------------------------------------------------------
__global__ void topk_kernel(const float* __restrict__ D, int* __restrict__ idx) {
    int row  = blockIdx.x * 8 + (threadIdx.x >> 5);
    int lane = threadIdx.x & 31;
    const float4* d4 = reinterpret_cast<const float4*>(D + (size_t)row * NN_);
    float v[32];
    #pragma unroll
    for (int q = 0; q < 8; q++) {
        float4 x = d4[lane + 32 * q];
        v[4 * q + 0] = x.x; v[4 * q + 1] = x.y;
        v[4 * q + 2] = x.z; v[4 * q + 3] = x.w;
    }

    for (int s = 0; s < KNN; s++) {
        float m16[16];
        #pragma unroll
        for (int q = 0; q < 16; q++) m16[q] = fminf(v[q], v[q + 16]);
        float m8[8];
        #pragma unroll
        for (int q = 0; q < 8; q++) m8[q] = fminf(m16[q], m16[q + 8]);
        float m4[4];
        #pragma unroll
        for (int q = 0; q < 4; q++) m4[q] = fminf(m8[q], m8[q + 4]);
        float m = fminf(fminf(m4[0], m4[2]), fminf(m4[1], m4[3]));
        unsigned mask = 0u;
        #pragma unroll
        for (int q = 0; q < 32; q++) mask |= (v[q] == m) ? (1u << q) : 0u;
        int slot = __ffs(mask) - 1;
        int gidx = 4 * lane + 128 * (slot >> 2) + (slot & 3);

        unsigned kb = __float_as_uint(m);
        kb = (kb & 0x80000000u) ? ~kb : (kb | 0x80000000u);
        unsigned mk;
        asm("redux.sync.min.u32 %0, %1, 0xffffffff;" : "=r"(mk) : "r"(kb));
        unsigned ball = __ballot_sync(0xffffffffu, kb == mk);
        int src = __ffs(ball) - 1;
        int bidx = __shfl_sync(0xffffffffu, gidx, src);
        if (lane == 0) idx[row * KNN + s] = bidx;
        if (lane == src) {
            #pragma unroll
            for (int q = 0; q < 32; q++) if (q == slot) v[q] = 3.4e38f;
        }
    }
}

// ---------------------------------------------------------------------------
// Generic fp32 GEMM (f32x2, split-half cols for TN==8), double-buffered smem.
// ---------------------------------------------------------------------------
template <int BM, int BN, int TM, int TN, bool BIAS_RELU, bool STATS>
__global__ void __launch_bounds__(256, 2)
gemm_nodes(const float* __restrict__ A, const float* __restrict__ Bm,
           const float* __restrict__ bias, float* __restrict__ Cmat,
           int M, int N, int K) {
    constexpr int BK = 16;
    constexpr int TX = BN / TN;
    static_assert(TX == 16 && (256 / TX) * TM == BM, "layout");
    constexpr int N4A = BM / 64;
    constexpr int N4B = BN / 64;
    __shared__ float smem[2 * BK * (BM + BN)];
    int block_m = blockIdx.y * BM, block_n = blockIdx.x * BN;
    int t  = threadIdx.x;
    int tx = t % TX, ty = t / TX;
    int c0 = tx * 4;
    int c1 = BN / 2 + tx * 4;

    int ar  = t >> 2;
    int akk = (t & 3) * 4;
    int bkk = t >> 4;
    int bcc = (t & 15) * 4;

    ull acc[TM][TN / 2];
    #pragma unroll
    for (int i = 0; i < TM; i++)
        #pragma unroll
        for (int j = 0; j < TN / 2; j++) acc[i][j] = 0ull;

    {
        float* As0 = smem;
        float* Bs0 = smem + 2 * BK * BM;
        #pragma unroll
        for (int it = 0; it < N4A; it++) {
            int r = ar + it * 64;
            float4 v = *reinterpret_cast<const float4*>(&A[(size_t)(block_m + r) * K + akk]);
            As0[(akk + 0) * BM + r] = v.x; As0[(akk + 1) * BM + r] = v.y;
            As0[(akk + 2) * BM + r] = v.z; As0[(akk + 3) * BM + r] = v.w;
        }
        #pragma unroll
        for (int it = 0; it < N4B; it++) {
            int cc = bcc + it * 64;
            *reinterpret_cast<float4*>(&Bs0[bkk * BN + cc]) =
                *reinterpret_cast<const float4*>(&Bm[(size_t)bkk * N + block_n + cc]);
        }
    }
    __syncthreads();

    int NT = K / BK;
    for (int kt = 0; kt < NT; kt++) {
        int cur = kt & 1;
        float* Asb = smem + cur * BK * BM;
        float* Bsb = smem + 2 * BK * BM + cur * BK * BN;
        float4 pa[N4A], pb[N4B];
        if (kt + 1 < NT) {
            int k0n = (kt + 1) * BK;
            #pragma unroll
            for (int it = 0; it < N4A; it++) {
                int r = ar + it * 64;
                pa[it] = *reinterpret_cast<const float4*>(&A[(size_t)(block_m + r) * K + k0n + akk]);
            }
            #pragma unroll
            for (int it = 0; it < N4B; it++) {
                int cc = bcc + it * 64;
                pb[it] = *reinterpret_cast<const float4*>(&Bm[(size_t)(k0n + bkk) * N + block_n + cc]);
            }
        }
        #pragma unroll
        for (int kk = 0; kk < BK; kk++) {
            float ra[TM];
            #pragma unroll
            for (int i4 = 0; i4 < TM / 4; i4++) {
                float4 a = *reinterpret_cast<const float4*>(&Asb[kk * BM + ty * TM + i4 * 4]);
                ra[i4 * 4 + 0] = a.x; ra[i4 * 4 + 1] = a.y;
                ra[i4 * 4 + 2] = a.z; ra[i4 * 4 + 3] = a.w;
            }
            ull rb[TN / 2];
            {
                float4 bq0 = *reinterpret_cast<const float4*>(&Bsb[kk * BN + c0]);
                rb[0] = pack2(bq0.x, bq0.y);
                rb[1] = pack2(bq0.z, bq0.w);
                if (TN == 8) {
                    float4 bq1 = *reinterpret_cast<const float4*>(&Bsb[kk * BN + c1]);
                    rb[2] = pack2(bq1.x, bq1.y);
                    rb[3] = pack2(bq1.z, bq1.w);
                }
            }
            #pragma unroll
            for (int i = 0; i < TM; i++) {
                ull ai = pack2(ra[i], ra[i]);
                #pragma unroll
                for (int j = 0; j < TN / 2; j++) fma2(acc[i][j], ai, rb[j]);
            }
        }
        if (kt + 1 < NT) {
            float* Asn = smem + (cur ^ 1) * BK * BM;
            float* Bsn = smem + 2 * BK * BM + (cur ^ 1) * BK * BN;
            #pragma unroll
            for (int it = 0; it < N4A; it++) {
                int r = ar + it * 64;
                Asn[(akk + 0) * BM + r] = pa[it].x; Asn[(akk + 1) * BM + r] = pa[it].y;
                Asn[(akk + 2) * BM + r] = pa[it].z; Asn[(akk + 3) * BM + r] = pa[it].w;
            }
            #pragma unroll
            for (int it = 0; it < N4B; it++) {
                int cc = bcc + it * 64;
                *reinterpret_cast<float4*>(&Bsn[bkk * BN + cc]) = pb[it];
            }
        }
        __syncthreads();
    }

    float bb[TN];
    if (BIAS_RELU) {
        #pragma unroll
        for (int j = 0; j < TN; j++)
            bb[j] = bias[block_n + ((j < 4) ? (c0 + j) : (c1 + j - 4))];
    }
    float ps[TN], ps2[TN];
    #pragma unroll
    for (int j = 0; j < TN; j++) { ps[j] = 0.f; ps2[j] = 0.f; }

    #pragma unroll
    for (int i = 0; i < TM; i++) {
        float v[TN];
        #pragma unroll
        for (int j = 0; j < TN / 2; j++) {
            float2 u = unpack2(acc[i][j]);
            v[j * 2] = u.x; v[j * 2 + 1] = u.y;
        }
        #pragma unroll
        for (int j = 0; j < TN; j++) {
            if (BIAS_RELU) v[j] = fmaxf(v[j] + bb[j], 0.f);
            if (STATS) { ps[j] += v[j]; ps2[j] = fmaf(v[j], v[j], ps2[j]); }
        }
        int r = block_m + ty * TM + i;
        *reinterpret_cast<float4*>(&Cmat[(size_t)r * N + block_n + c0]) =
            make_float4(v[0], v[1], v[2], v[3]);
        if (TN == 8)
            *reinterpret_cast<float4*>(&Cmat[(size_t)r * N + block_n + c1]) =
                make_float4(v[4], v[5], v[6], v[7]);
    }

    if (STATS) {
        #pragma unroll
        for (int j = 0; j < TN; j++) {
            int col = (j < 4) ? (c0 + j) : (c1 + j - 4);
            smem[ty * BN + col]           = ps[j];
            smem[16 * BN + ty * BN + col] = ps2[j];
        }
        __syncthreads();
        if (t < BN) {
            float s = 0.f, s2 = 0.f;
            #pragma unroll
            for (int g = 0; g < 16; g++) { s += smem[g * BN + t]; s2 += smem[16 * BN + g * BN + t]; }
            atomicAdd(&g_sum[block_n + t],   (double)s);
            atomicAdd(&g_sumsq[block_n + t], (double)s2);
        }
    }
}

// ---------------------------------------------------------------------------
// Layer-1 edge GEMM: full A(128x64)+B(64x64) in smem, 2 barriers.
// ---------------------------------------------------------------------------
__global__ void __launch_bounds__(256, 2)
gemm_edge1(const float* __restrict__ PQ, const int* __restrict__ IDXp,
           const float* __restrict__ abias, const float* __restrict__ W,
           const float* __restrict__ obias, float* __restrict__ H) {
    __shared__ float As[64 * 128];
    __shared__ float Bs[64 * 64];
    __shared__ float s_ab[64];
    int t = threadIdx.x;
    int block_m = blockIdx.x * 128;
    if (t < 64) s_ab[t] = abias[t];
    #pragma unroll
    for (int i = 0; i < 4; i++)
        *reinterpret_cast<float4*>(&Bs[i * 1024 + t * 4]) =
            *reinterpret_cast<const float4*>(&W[i * 1024 + t * 4]);
    int r  = t >> 1;
    int co = (t & 1) * 32;
    {
        int e  = block_m + r;
        int bi = e / KNN;
        int qo = ((bi >> 10) << 10) + IDXp[e];
        const float* Pp = PQ + (size_t)bi * 128 + co;
        const float* Qp = PQ + (size_t)qo * 128 + 64 + co;
        float4 pv[8], qv[8];
        #pragma unroll
        for (int q = 0; q < 8; q++) {
            pv[q] = *reinterpret_cast<const float4*>(Pp + q * 4);
            qv[q] = *reinterpret_cast<const float4*>(Qp + q * 4);
        }
        __syncthreads();
        #pragma unroll
        for (int q = 0; q < 8; q++) {
            int c = co + q * 4;
            As[(c + 0) * 128 + r] = fmaxf(pv[q].x + qv[q].x + s_ab[c + 0], 0.f);
            As[(c + 1) * 128 + r] = fmaxf(pv[q].y + qv[q].y + s_ab[c + 1], 0.f);
            As[(c + 2) * 128 + r] = fmaxf(pv[q].z + qv[q].z + s_ab[c + 2], 0.f);
            As[(c + 3) * 128 + r] = fmaxf(pv[q].w + qv[q].w + s_ab[c + 3], 0.f);
        }
    }
    __syncthreads();

    int tx = t & 15, ty = t >> 4;
    ull acc[8][2];
    #pragma unroll
    for (int i = 0; i < 8; i++) { acc[i][0] = 0ull; acc[i][1] = 0ull; }

    #pragma unroll 16
    for (int kk = 0; kk < 64; kk++) {
        float4 a0 = *reinterpret_cast<const float4*>(&As[kk * 128 + ty * 8]);
        float4 a1 = *reinterpret_cast<const float4*>(&As[kk * 128 + ty * 8 + 4]);
        float4 b0 = *reinterpret_cast<const float4*>(&Bs[kk * 64 + tx * 4]);
        ull rb0 = pack2(b0.x, b0.y), rb1 = pack2(b0.z, b0.w);
        float ra[8] = {a0.x, a0.y, a0.z, a0.w, a1.x, a1.y, a1.z, a1.w};
        #pragma unroll
        for (int i = 0; i < 8; i++) {
            ull ai = pack2(ra[i], ra[i]);
            fma2(acc[i][0], ai, rb0);
            fma2(acc[i][1], ai, rb1);
        }
    }

    float ob[4];
    #pragma unroll
    for (int j = 0; j < 4; j++) ob[j] = obias[tx * 4 + j];
    float ps[4] = {0, 0, 0, 0}, ps2[4] = {0, 0, 0, 0};
    #pragma unroll
    for (int i = 0; i < 8; i++) {
        float2 u0 = unpack2(acc[i][0]), u1 = unpack2(acc[i][1]);
        float v[4] = {u0.x, u0.y, u1.x, u1.y};
        #pragma unroll
        for (int j = 0; j < 4; j++) {
            v[j] = fmaxf(v[j] + ob[j], 0.f);
            ps[j] += v[j]; ps2[j] = fmaf(v[j], v[j], ps2[j]);
        }
        int rr = block_m + ty * 8 + i;
        *reinterpret_cast<float4*>(&H[(size_t)rr * 64 + tx * 4]) =
            make_float4(v[0], v[1], v[2], v[3]);
    }
    __syncthreads();
    #pragma unroll
    for (int j = 0; j < 4; j++) {
        As[ty * 64 + tx * 4 + j]        = ps[j];
        As[1024 + ty * 64 + tx * 4 + j] = ps2[j];
    }
    __syncthreads();
    if (t < 64) {
        float s = 0.f, s2 = 0.f;
        #pragma unroll
        for (int g = 0; g < 16; g++) { s += As[g * 64 + t]; s2 += As[1024 + g * 64 + t]; }
        atomicAdd(&g_sum[t],   (double)s);
        atomicAdd(&g_sumsq[t], (double)s2);
    }
}

// ---------------------------------------------------------------------------
template <int CH>
__global__ void stats_edges_kernel(const float* __restrict__ PQ,
                                   const int* __restrict__ IDXp,
                                   const float* __restrict__ bias) {
    constexpr int G = 256 / CH;
    int c = threadIdx.x % CH;
    int g = threadIdx.x / CH;
    int stride = gridDim.x * G;
    float bb = bias[c];
    float s = 0.f, s2 = 0.f;
    for (int node = blockIdx.x * G + g; node < NROW; node += stride) {
        float p = PQ[(size_t)node * (2 * CH) + c] + bb;
        int base = (node >> 10) << 10;
        const int* ix = IDXp + node * KNN;
        #pragma unroll 5
        for (int kk = 0; kk < KNN; kk++) {
            int j = base + ix[kk];
            float v = fmaxf(p + PQ[(size_t)j * (2 * CH) + CH + c], 0.f);
            s += v; s2 = fmaf(v, v, s2);
        }
    }
    __shared__ float sh[2][256];
    sh[0][threadIdx.x] = s; sh[1][threadIdx.x] = s2;
    __syncthreads();
    if (g == 0) {
        #pragma unroll
        for (int gg = 1; gg < G; gg++) { s += sh[0][gg * CH + c]; s2 += sh[1][gg * CH + c]; }
        atomicAdd(&g_sum[c],   (double)s);
        atomicAdd(&g_sumsq[c], (double)s2);
    }
}

// ---------------------------------------------------------------------------
__global__ void stats_minmax_edges_kernel(const float* __restrict__ PQ2,
                                          const int* __restrict__ IDXp,
                                          const float* __restrict__ bias,
                                          float* __restrict__ vmax,
                                          float* __restrict__ vmin) {
    int c = threadIdx.x & 127;
    int g = threadIdx.x >> 7;
    int stride = gridDim.x * 2;
    float bb = bias[c];
    float s = 0.f, s2 = 0.f;
    for (int node = blockIdx.x * 2 + g; node < NROW; node += stride) {
        float p = PQ2[(size_t)node * 256 + c] + bb;
        int base = (node >> 10) << 10;
        const int* ix = IDXp + node * KNN;
        float mx = -3.4e38f, mn = 3.4e38f;
        #pragma unroll 5
        for (int kk = 0; kk < KNN; kk++) {
            int j = base + ix[kk];
            float v = fmaxf(p + PQ2[(size_t)j * 256 + 128 + c], 0.f);
            s += v; s2 = fmaf(v, v, s2);
            mx = fmaxf(mx, v); mn = fminf(mn, v);
        }
        vmax[(size_t)node * 128 + c] = mx;
        vmin[(size_t)node * 128 + c] = mn;
    }
    __shared__ float sh[2][256];
    sh[0][threadIdx.x] = s; sh[1][threadIdx.x] = s2;
    __syncthreads();
    if (g == 0) {
        s  += sh[0][128 + c];
        s2 += sh[1][128 + c];
        atomicAdd(&g_sum[c],   (double)s);
        atomicAdd(&g_sumsq[c], (double)s2);
    }
}

__global__ void apply_minmax_kernel(const float* __restrict__ vmax,
                                    const float* __restrict__ vmin,
                                    float* __restrict__ hcat) {
    int i = blockIdx.x * 256 + threadIdx.x;
    int c = i & 127, bi = i >> 7;
    float s = g_sc[c], cc = g_cc[c];
    float v = (s >= 0.f) ? vmax[i] : vmin[i];
    hcat[(size_t)bi * 192 + 64 + c] = fmaf(s, v, cc);
}

// ---------------------------------------------------------------------------
template <int CH>
__global__ void finalize_kernel(const float* __restrict__ gam,
                                const float* __restrict__ bet, int E) {
    int c = threadIdx.x;
    if (c < CH) {
        double mu  = g_sum[c] / (double)E;
        double var = g_sumsq[c] / (double)E - mu * mu;
        float s = gam[c] * rsqrtf((float)var + 1e-5f);
        g_sc[c] = s;
        g_cc[c] = bet[c] - (float)mu * s;
    }
    g_sum[c] = 0.0; g_sumsq[c] = 0.0;
}

__global__ void fold_kernel(const float* __restrict__ gam, const float* __restrict__ bet,
                            const float* __restrict__ W, const float* __restrict__ bias,
                            int E, float* __restrict__ Wf, float* __restrict__ bf) {
    __shared__ float s_s[64], s_c[64];
    int t = threadIdx.x;
    if (t < 64) {
        double mu  = g_sum[t] / (double)E;
        double var = g_sumsq[t] / (double)E - mu * mu;
        float s = gam[t] * rsqrtf((float)var + 1e-5f);
        s_s[t] = s;
        s_c[t] = bet[t] - (float)mu * s;
        g_sum[t] = 0.0; g_sumsq[t] = 0.0;
    } else if (t < 128) {
        g_sum[t] = 0.0; g_sumsq[t] = 0.0;
    }
    __syncthreads();
    for (int e = t; e < 64 * 64; e += 256) Wf[e] = s_s[e >> 6] * W[e];
    if (t < 64) {
        float acc = bias[t];
        #pragma unroll 4
        for (int kk = 0; kk < 64; kk++) acc = fmaf(s_c[kk], W[kk * 64 + t], acc);
        bf[t] = acc;
    }
}

// ---------------------------------------------------------------------------
__global__ void maxagg1_kernel(const float* __restrict__ H, float* __restrict__ hcat,
                               float* __restrict__ x1, float* __restrict__ sq) {
    int bi = blockIdx.x;
    int c  = threadIdx.x;
    const float* h = H + (size_t)bi * (KNN * 64) + c;
    float s = g_sc[c], cc = g_cc[c];
    float m = -3.4e38f;
    #pragma unroll
    for (int kk = 0; kk < KNN; kk++) m = fmaxf(m, fmaf(s, h[kk * 64], cc));
    hcat[(size_t)bi * 192 + c] = m;
    x1[(size_t)bi * 64 + c]    = m;
    float q = m * m;
    #pragma unroll
    for (int o = 16; o; o >>= 1) q += __shfl_xor_sync(0xffffffffu, q, o);
    __shared__ float sh[2];
    if ((c & 31) == 0) sh[c >> 5] = q;
    __syncthreads();
    if (c == 0) sq[bi] = sh[0] + sh[1];
}

__global__ void apply_bn_kernel(const float* __restrict__ Y, float* __restrict__ out) {
    int i = blockIdx.x * 256 + threadIdx.x;
    int c = i & 127;
    out[i] = fmaf(g_sc[c], Y[i], g_cc[c]);
}

// ---------------------------------------------------------------------------
extern "C" void kernel_launch(void* const* d_in, const int* in_sizes, int n_in,
                              void* d_out, int out_size) {
    const float* x0    = (const float*)d_in[1];
    const float* c1w0  = (const float*)d_in[2];
    const float* c1b0  = (const float*)d_in[3];
    const float* c1g0  = (const float*)d_in[4];
    const float* c1be0 = (const float*)d_in[5];
    const float* c1w1  = (const float*)d_in[6];
    const float* c1b1  = (const float*)d_in[7];
    const float* c1g1  = (const float*)d_in[8];
    const float* c1be1 = (const float*)d_in[9];
    const float* c1w2  = (const float*)d_in[10];
    const float* c1b2  = (const float*)d_in[11];
    const float* c1g2  = (const float*)d_in[12];
    const float* c1be2 = (const float*)d_in[13];
    const float* c2w0  = (const float*)d_in[14];
    const float* c2b0  = (const float*)d_in[15];
    const float* c2g0  = (const float*)d_in[16];
    const float* c2be0 = (const float*)d_in[17];
    const float* lw    = (const float*)d_in[18];
    const float* lb    = (const float*)d_in[19];
    const float* lg    = (const float*)d_in[20];
    const float* lbe   = (const float*)d_in[21];
    float* out = (float*)d_out;

    void* sp = nullptr; cudaGetSymbolAddress(&sp, g_scratch);
    float* S = (float*)sp;
    void* ip = nullptr; cudaGetSymbolAddress(&ip, g_knn_idx);
    int* IDX = (int*)ip;

    float* D     = S + OFF_D;
    float* PQ    = S + OFF_PQ;
    float* PQ2   = S + OFF_PQ2;
    float* H1    = S + OFF_H1;
    float* H2    = S + OFF_H2;
    float* HCAT  = S + OFF_HCAT;
    float* X1    = S + OFF_X1;
    float* Y0    = S + OFF_Y0;
    float* SQ    = S + OFF_SQ;
    float* WCAT  = S + OFF_WCAT;
    float* WCAT2 = S + OFF_WCAT2;
    float* WF    = S + OFF_WF;
    float* BF    = S + OFF_BF;
    float* VMAX  = S + OFF_H1;
    float* VMIN  = S + OFF_H1 + (size_t)NROW * 128;

    // side stream + events for fork/join under graph capture
    cudaStream_t s2;
    cudaStreamCreateWithFlags(&s2, cudaStreamNonBlocking);
    cudaEvent_t evFork1, evJoin1, evFork2, evJoin2;
    cudaEventCreateWithFlags(&evFork1, cudaEventDisableTiming);
    cudaEventCreateWithFlags(&evJoin1, cudaEventDisableTiming);
    cudaEventCreateWithFlags(&evFork2, cudaEventDisableTiming);
    cudaEventCreateWithFlags(&evJoin2, cudaEventDisableTiming);

    prep_kernel<<<192 + NROW / 8, 256>>>(c1w0, WCAT, c2w0, WCAT2, x0, SQ);

    // ---- EdgeConv 1: fork PQ1 gemm (x0,WCAT) || dist1->topk1 ----
    cudaEventRecord(evFork1, 0);
    cudaStreamWaitEvent(s2, evFork1, 0);
    gemm_nodes<64, 64, 4, 4, false, false><<<dim3(2, NROW / 64), 256, 0, s2>>>(x0, WCAT, nullptr, PQ, NROW, 128, 256);
    cudaEventRecord(evJoin1, s2);

    dist_kernel<256><<<dim3(36, 1, 8), 256>>>(x0, SQ, D);
    topk_kernel<<<NROW / 8, 256>>>(D, IDX);
    cudaStreamWaitEvent(0, evJoin1, 0);

    stats_edges_kernel<64><<<512, 256>>>(PQ, IDX, c1b0);
    fold_kernel<<<1, 256>>>(c1g0, c1be0, c1w1, c1b1, NEDGE, WF, BF);
    gemm_edge1<<<NEDGE / 128, 256>>>(PQ, IDX, c1b0, WF, BF, H1);
    fold_kernel<<<1, 256>>>(c1g1, c1be1, c1w2, c1b2, NEDGE, WF, BF);
    gemm_nodes<128, 64, 8, 4, true, true><<<dim3(1, NEDGE / 128), 256>>>(H1, WF, BF, H2, NEDGE, 64, 64);
    finalize_kernel<64><<<1, 128>>>(c1g2, c1be2, NEDGE);
    maxagg1_kernel<<<NROW, 64>>>(H2, HCAT, X1, SQ);

    // ---- EdgeConv 2: fork PQ2 gemm (X1,WCAT2) || dist2->topk2 ----
    cudaEventRecord(evFork2, 0);
    cudaStreamWaitEvent(s2, evFork2, 0);
    gemm_nodes<64, 128, 4, 8, false, false><<<dim3(2, NROW / 64), 256, 0, s2>>>(X1, WCAT2, nullptr, PQ2, NROW, 256, 64);
    cudaEventRecord(evJoin2, s2);

    dist_kernel<64><<<dim3(36, 1, 8), 256>>>(X1, SQ, D);
    topk_kernel<<<NROW / 8, 256>>>(D, IDX);
    cudaStreamWaitEvent(0, evJoin2, 0);

    stats_minmax_edges_kernel<<<512, 256>>>(PQ2, IDX, c2b0, VMAX, VMIN);
    finalize_kernel<128><<<1, 128>>>(c2g0, c2be0, NEDGE);
    apply_minmax_kernel<<<NROW * 128 / 256, 256>>>(VMAX, VMIN, HCAT);

    // ---- Final Linear + BN ----
    gemm_nodes<64, 64, 4, 4, true, true><<<dim3(2, NROW / 64), 256>>>(HCAT, lw, lb, Y0, NROW, 128, 192);
    finalize_kernel<128><<<1, 128>>>(lg, lbe, NROW);
    apply_bn_kernel<<<NROW * 128 / 256, 256>>>(Y0, out);

    cudaEventDestroy(evFork1); cudaEventDestroy(evJoin1);
    cudaEventDestroy(evFork2); cudaEventDestroy(evJoin2);
    cudaStreamDestroy(s2);
}

// round 17
// speedup vs baseline: 1.4017x; 1.0172x over previous
#include <cuda_runtime.h>
#include <cstdint>

// ---------------------------------------------------------------------------
// DGCNN: 2x EdgeConv (dynamic kNN) + final MLP, training-mode BatchNorm.
// R17 = R16 + topk rewritten around smem-resident orderable-u32 keys:
// dynamic-indexed removal (1 STS) + winner-only rescan kills the per-round
// equality-mask / SEL-chain ALU work (~200 -> ~110 issues/round).
// ---------------------------------------------------------------------------

typedef unsigned long long ull;

namespace cfg {
constexpr int BB   = 8;
constexpr int NN_  = 1024;
constexpr int KNN  = 20;
constexpr int NROW  = BB * NN_;        // 8192
constexpr int NEDGE = NROW * KNN;      // 163840

constexpr size_t OFF_D    = 0;
constexpr size_t SZ_D     = (size_t)BB * NN_ * NN_;
constexpr size_t OFF_PQ   = OFF_D + SZ_D;
constexpr size_t SZ_PQ    = (size_t)NROW * 128;
constexpr size_t OFF_PQ2  = OFF_PQ + SZ_PQ;
constexpr size_t SZ_PQ2   = (size_t)NROW * 256;
constexpr size_t OFF_H1   = OFF_PQ2 + SZ_PQ2;
constexpr size_t SZ_H64   = (size_t)NEDGE * 64;
constexpr size_t OFF_H2   = OFF_H1 + SZ_H64;
constexpr size_t OFF_HCAT = OFF_H2 + SZ_H64;
constexpr size_t SZ_HCAT  = (size_t)NROW * 192;
constexpr size_t OFF_X1   = OFF_HCAT + SZ_HCAT;
constexpr size_t SZ_X1    = (size_t)NROW * 64;
constexpr size_t OFF_Y0   = OFF_X1 + SZ_X1;
constexpr size_t SZ_Y0    = (size_t)NROW * 128;
constexpr size_t OFF_SQ   = OFF_Y0 + SZ_Y0;
constexpr size_t SZ_SQ    = (size_t)NROW;
constexpr size_t OFF_WCAT = OFF_SQ + SZ_SQ;
constexpr size_t SZ_WCAT  = 256 * 128;
constexpr size_t OFF_WCAT2= OFF_WCAT + SZ_WCAT;
constexpr size_t SZ_WCAT2 = 64 * 256;
constexpr size_t OFF_WF   = OFF_WCAT2 + SZ_WCAT2;
constexpr size_t SZ_WF    = 64 * 64;
constexpr size_t OFF_BF   = OFF_WF + SZ_WF;
constexpr size_t SZ_BF    = 128;
constexpr size_t SCRATCH_TOTAL = OFF_BF + SZ_BF;
}  // namespace cfg
using namespace cfg;

__device__ float  g_scratch[SCRATCH_TOTAL];
__device__ int    g_knn_idx[NEDGE];
__device__ double g_sum[128];
__device__ double g_sumsq[128];
__device__ float  g_sc[128];
__device__ float  g_cc[128];

// ---------------------------------------------------------------------------
__device__ __forceinline__ ull pack2(float x, float y) {
    ull r; asm("mov.b64 %0, {%1, %2};" : "=l"(r) : "f"(x), "f"(y)); return r;
}
__device__ __forceinline__ void fma2(ull& d, ull a, ull b) {
    asm("fma.rn.f32x2 %0, %1, %2, %0;" : "+l"(d) : "l"(a), "l"(b));
}
__device__ __forceinline__ float2 unpack2(ull v) {
    float2 f; asm("mov.b64 {%0, %1}, %2;" : "=f"(f.x), "=f"(f.y) : "l"(v)); return f;
}

// ---------------------------------------------------------------------------
// Merged prep: blocks [0,128) wcat1, [128,192) wcat2, [192,1216) rowsq(C=256)
// ---------------------------------------------------------------------------
__global__ void prep_kernel(const float* __restrict__ c1w0, float* __restrict__ Wcat1,
                            const float* __restrict__ c2w0, float* __restrict__ Wcat2,
                            const float* __restrict__ X0, float* __restrict__ sq) {
    int b = blockIdx.x;
    int t = threadIdx.x;
    if (b < 128) {
        int e = b * 256 + t;
        int kk = e >> 7, n = e & 127;
        float v;
        if (n < 64) v = c1w0[kk * 64 + n] - c1w0[(kk + 256) * 64 + n];
        else        v = c1w0[(kk + 256) * 64 + (n - 64)];
        Wcat1[e] = v;
    } else if (b < 192) {
        int e = (b - 128) * 256 + t;
        int kk = e >> 8, n = e & 255;
        float v;
        if (n < 128) v = c2w0[kk * 128 + n] - c2w0[(kk + 64) * 128 + n];
        else         v = c2w0[(kk + 64) * 128 + (n - 128)];
        Wcat2[e] = v;
    } else {
        int row  = (b - 192) * 8 + (t >> 5);
        int lane = t & 31;
        const float* x = X0 + (size_t)row * 256;
        float a = 0.f;
        #pragma unroll
        for (int c = lane; c < 256; c += 32) { float v = x[c]; a = fmaf(v, v, a); }
        #pragma unroll
        for (int o = 16; o; o >>= 1) a += __shfl_xor_sync(0xffffffffu, a, o);
        if (lane == 0) sq[row] = a;
    }
}

// ---------------------------------------------------------------------------
// Distance matrix: symmetric triangular tiles, split-half B cols,
// double-buffered smem pipeline (1 barrier per K-step).
// ---------------------------------------------------------------------------
template <int C>
__global__ void __launch_bounds__(256, 2)
dist_kernel(const float* __restrict__ X, const float* __restrict__ sq,
            float* __restrict__ D) {
    __shared__ float As[2][16][128];
    __shared__ float Bs[2][16][128];
    int b  = blockIdx.z;
    const float* Xb  = X  + (size_t)b * NN_ * C;
    const float* sqb = sq + (size_t)b * NN_;
    float* Db = D + (size_t)b * NN_ * NN_;

    int rem = blockIdx.x, bi = 0;
    while (rem >= 8 - bi) { rem -= 8 - bi; bi++; }
    int bj = bi + rem;
    int i0 = bi * 128, j0 = bj * 128;

    int t  = threadIdx.x;
    int tx = t & 15, ty = t >> 4;
    int c0 = tx * 4;
    int c1 = 64 + tx * 4;

    int lr0 = (t >> 2), lr1 = lr0 + 64;
    int lkk = (t & 3) * 4;

    ull acc[8][4];
    #pragma unroll
    for (int i = 0; i < 8; i++)
        #pragma unroll
        for (int j = 0; j < 4; j++) acc[i][j] = 0ull;

    {
        float4 va0 = *reinterpret_cast<const float4*>(&Xb[(size_t)(i0 + lr0) * C + lkk]);
        float4 va1 = *reinterpret_cast<const float4*>(&Xb[(size_t)(i0 + lr1) * C + lkk]);
        float4 vb0 = *reinterpret_cast<const float4*>(&Xb[(size_t)(j0 + lr0) * C + lkk]);
        float4 vb1 = *reinterpret_cast<const float4*>(&Xb[(size_t)(j0 + lr1) * C + lkk]);
        As[0][lkk + 0][lr0] = va0.x; As[0][lkk + 1][lr0] = va0.y;
        As[0][lkk + 2][lr0] = va0.z; As[0][lkk + 3][lr0] = va0.w;
        As[0][lkk + 0][lr1] = va1.x; As[0][lkk + 1][lr1] = va1.y;
        As[0][lkk + 2][lr1] = va1.z; As[0][lkk + 3][lr1] = va1.w;
        Bs[0][lkk + 0][lr0] = vb0.x; Bs[0][lkk + 1][lr0] = vb0.y;
        Bs[0][lkk + 2][lr0] = vb0.z; Bs[0][lkk + 3][lr0] = vb0.w;
        Bs[0][lkk + 0][lr1] = vb1.x; Bs[0][lkk + 1][lr1] = vb1.y;
        Bs[0][lkk + 2][lr1] = vb1.z; Bs[0][lkk + 3][lr1] = vb1.w;
    }
    __syncthreads();

    constexpr int NT = C / 16;
    for (int kt = 0; kt < NT; kt++) {
        int cur = kt & 1;
        float4 pa0, pa1, pb0, pb1;
        if (kt + 1 < NT) {
            int k0n = (kt + 1) * 16;
            pa0 = *reinterpret_cast<const float4*>(&Xb[(size_t)(i0 + lr0) * C + k0n + lkk]);
            pa1 = *reinterpret_cast<const float4*>(&Xb[(size_t)(i0 + lr1) * C + k0n + lkk]);
            pb0 = *reinterpret_cast<const float4*>(&Xb[(size_t)(j0 + lr0) * C + k0n + lkk]);
            pb1 = *reinterpret_cast<const float4*>(&Xb[(size_t)(j0 + lr1) * C + k0n + lkk]);
        }
        #pragma unroll
        for (int kk = 0; kk < 16; kk++) {
            float4 a0 = *reinterpret_cast<const float4*>(&As[cur][kk][ty * 8]);
            float4 a1 = *reinterpret_cast<const float4*>(&As[cur][kk][ty * 8 + 4]);
            float4 b0 = *reinterpret_cast<const float4*>(&Bs[cur][kk][c0]);
            float4 b1 = *reinterpret_cast<const float4*>(&Bs[cur][kk][c1]);
            ull rb[4] = {pack2(b0.x, b0.y), pack2(b0.z, b0.w),
                         pack2(b1.x, b1.y), pack2(b1.z, b1.w)};
            float ra[8] = {a0.x, a0.y, a0.z, a0.w, a1.x, a1.y, a1.z, a1.w};
            #pragma unroll
            for (int i = 0; i < 8; i++) {
                ull ai = pack2(ra[i], ra[i]);
                #pragma unroll
                for (int j = 0; j < 4; j++) fma2(acc[i][j], ai, rb[j]);
            }
        }
        if (kt + 1 < NT) {
            int nxt = cur ^ 1;
            As[nxt][lkk + 0][lr0] = pa0.x; As[nxt][lkk + 1][lr0] = pa0.y;
            As[nxt][lkk + 2][lr0] = pa0.z; As[nxt][lkk + 3][lr0] = pa0.w;
            As[nxt][lkk + 0][lr1] = pa1.x; As[nxt][lkk + 1][lr1] = pa1.y;
            As[nxt][lkk + 2][lr1] = pa1.z; As[nxt][lkk + 3][lr1] = pa1.w;
            Bs[nxt][lkk + 0][lr0] = pb0.x; Bs[nxt][lkk + 1][lr0] = pb0.y;
            Bs[nxt][lkk + 2][lr0] = pb0.z; Bs[nxt][lkk + 3][lr0] = pb0.w;
            Bs[nxt][lkk + 0][lr1] = pb1.x; Bs[nxt][lkk + 1][lr1] = pb1.y;
            Bs[nxt][lkk + 2][lr1] = pb1.z; Bs[nxt][lkk + 3][lr1] = pb1.w;
        }
        __syncthreads();
    }

    float sj[8];
    #pragma unroll
    for (int j = 0; j < 4; j++) { sj[j] = sqb[j0 + c0 + j]; sj[4 + j] = sqb[j0 + c1 + j]; }

    float o[8][8];
    #pragma unroll
    for (int i = 0; i < 8; i++) {
        float si = sqb[i0 + ty * 8 + i];
        #pragma unroll
        for (int j = 0; j < 4; j++) {
            float2 u = unpack2(acc[i][j]);
            o[i][j * 2]     = si + sj[j * 2]     - 2.f * u.x;
            o[i][j * 2 + 1] = si + sj[j * 2 + 1] - 2.f * u.y;
        }
    }
    #pragma unroll
    for (int i = 0; i < 8; i++) {
        int gi = i0 + ty * 8 + i;
        *reinterpret_cast<float4*>(&Db[(size_t)gi * NN_ + j0 + c0]) =
            make_float4(o[i][0], o[i][1], o[i][2], o[i][3]);
        *reinterpret_cast<float4*>(&Db[(size_t)gi * NN_ + j0 + c1]) =
            make_float4(o[i][4], o[i][5], o[i][6], o[i][7]);
    }
    if (bi != bj) {
        #pragma unroll
        for (int j = 0; j < 8; j++) {
            int gj = j0 + ((j < 4) ? (c0 + j) : (c1 + j - 4));
            float4* dst = reinterpret_cast<float4*>(&Db[(size_t)gj * NN_ + i0 + ty * 8]);
            dst[0] = make_float4(o[0][j], o[1][j], o[2][j], o[3][j]);
            dst[1] = make_float4(o[4][j], o[5][j], o[6][j], o[7][j]);
        }
    }
}

// ---------------------------------------------------------------------------
// Top-20 smallest per row; one warp per row. Keys live in smem as orderable
// u32 (layout [slot][lane]: each lane owns one bank, no syncs). Per round:
// redux.min + ballot + shfl; winner does dynamic-STS removal + 32-elem rescan.
// Tie semantics identical to R14-16 (lowest lane; earliest slot within lane).
// ---------------------------------------------------------------------------
__global__ void __launch_bounds__(256)
topk_kernel(const float* __restrict__ D, int* __restrict__ idx) {
    __shared__ unsigned sk[8][1024];
    int warp = threadIdx.x >> 5;
    int row  = blockIdx.x * 8 + warp;
    int lane = threadIdx.x & 31;
    unsigned* K = sk[warp];
    const float4* d4 = reinterpret_cast<const float4*>(D + (size_t)row * NN_);

    unsigned bm = 0xFFFFFFFFu; int bs = 0;
    #pragma unroll
    for (int q = 0; q < 8; q++) {
        float4 x = d4[lane + 32 * q];
        float f[4] = {x.x, x.y, x.z, x.w};
        #pragma unroll
        for (int r = 0; r < 4; r++) {
            unsigned kb = __float_as_uint(f[r]);
            kb = (kb & 0x80000000u) ? ~kb : (kb | 0x80000000u);
            int slot = 4 * q + r;
            K[slot * 32 + lane] = kb;
            if (kb < bm) { bm = kb; bs = slot; }
        }
    }
    int gidx_c = 4 * lane + 128 * (bs >> 2) + (bs & 3);

    for (int s = 0; s < KNN; s++) {
        unsigned mk;
        asm("redux.sync.min.u32 %0, %1, 0xffffffff;" : "=r"(mk) : "r"(bm));
        unsigned ball = __ballot_sync(0xffffffffu, bm == mk);
        int src = __ffs(ball) - 1;
        int bidx = __shfl_sync(0xffffffffu, gidx_c, src);
        if (lane == 0) idx[row * KNN + s] = bidx;
        if (lane == src) {
            K[bs * 32 + lane] = 0xFFFFFFFFu;
            bm = 0xFFFFFFFFu; bs = 0;
            #pragma unroll
            for (int q = 0; q < 32; q++) {
                unsigned k = K[q * 32 + lane];
                if (k < bm) { bm = k; bs = q; }
            }
            gidx_c = 4 * lane + 128 * (bs >> 2) + (bs & 3);
        }
    }
}

// ---------------------------------------------------------------------------
// Generic fp32 GEMM (f32x2, split-half cols for TN==8), double-buffered smem.
// ---------------------------------------------------------------------------
template <int BM, int BN, int TM, int TN, bool BIAS_RELU, bool STATS>
__global__ void __launch_bounds__(256, 2)
gemm_nodes(const float* __restrict__ A, const float* __restrict__ Bm,
           const float* __restrict__ bias, float* __restrict__ Cmat,
           int M, int N, int K) {
    constexpr int BK = 16;
    constexpr int TX = BN / TN;
    static_assert(TX == 16 && (256 / TX) * TM == BM, "layout");
    constexpr int N4A = BM / 64;
    constexpr int N4B = BN / 64;
    __shared__ float smem[2 * BK * (BM + BN)];
    int block_m = blockIdx.y * BM, block_n = blockIdx.x * BN;
    int t  = threadIdx.x;
    int tx = t % TX, ty = t / TX;
    int c0 = tx * 4;
    int c1 = BN / 2 + tx * 4;

    int ar  = t >> 2;
    int akk = (t & 3) * 4;
    int bkk = t >> 4;
    int bcc = (t & 15) * 4;

    ull acc[TM][TN / 2];
    #pragma unroll
    for (int i = 0; i < TM; i++)
        #pragma unroll
        for (int j = 0; j < TN / 2; j++) acc[i][j] = 0ull;

    {
        float* As0 = smem;
        float* Bs0 = smem + 2 * BK * BM;
        #pragma unroll
        for (int it = 0; it < N4A; it++) {
            int r = ar + it * 64;
            float4 v = *reinterpret_cast<const float4*>(&A[(size_t)(block_m + r) * K + akk]);
            As0[(akk + 0) * BM + r] = v.x; As0[(akk + 1) * BM + r] = v.y;
            As0[(akk + 2) * BM + r] = v.z; As0[(akk + 3) * BM + r] = v.w;
        }
        #pragma unroll
        for (int it = 0; it < N4B; it++) {
            int cc = bcc + it * 64;
            *reinterpret_cast<float4*>(&Bs0[bkk * BN + cc]) =
                *reinterpret_cast<const float4*>(&Bm[(size_t)bkk * N + block_n + cc]);
        }
    }
    __syncthreads();

    int NT = K / BK;
    for (int kt = 0; kt < NT; kt++) {
        int cur = kt & 1;
        float* Asb = smem + cur * BK * BM;
        float* Bsb = smem + 2 * BK * BM + cur * BK * BN;
        float4 pa[N4A], pb[N4B];
        if (kt + 1 < NT) {
            int k0n = (kt + 1) * BK;
            #pragma unroll
            for (int it = 0; it < N4A; it++) {
                int r = ar + it * 64;
                pa[it] = *reinterpret_cast<const float4*>(&A[(size_t)(block_m + r) * K + k0n + akk]);
            }
            #pragma unroll
            for (int it = 0; it < N4B; it++) {
                int cc = bcc + it * 64;
                pb[it] = *reinterpret_cast<const float4*>(&Bm[(size_t)(k0n + bkk) * N + block_n + cc]);
            }
        }
        #pragma unroll
        for (int kk = 0; kk < BK; kk++) {
            float ra[TM];
            #pragma unroll
            for (int i4 = 0; i4 < TM / 4; i4++) {
                float4 a = *reinterpret_cast<const float4*>(&Asb[kk * BM + ty * TM + i4 * 4]);
                ra[i4 * 4 + 0] = a.x; ra[i4 * 4 + 1] = a.y;
                ra[i4 * 4 + 2] = a.z; ra[i4 * 4 + 3] = a.w;
            }
            ull rb[TN / 2];
            {
                float4 bq0 = *reinterpret_cast<const float4*>(&Bsb[kk * BN + c0]);
                rb[0] = pack2(bq0.x, bq0.y);
                rb[1] = pack2(bq0.z, bq0.w);
                if (TN == 8) {
                    float4 bq1 = *reinterpret_cast<const float4*>(&Bsb[kk * BN + c1]);
                    rb[2] = pack2(bq1.x, bq1.y);
                    rb[3] = pack2(bq1.z, bq1.w);
                }
            }
            #pragma unroll
            for (int i = 0; i < TM; i++) {
                ull ai = pack2(ra[i], ra[i]);
                #pragma unroll
                for (int j = 0; j < TN / 2; j++) fma2(acc[i][j], ai, rb[j]);
            }
        }
        if (kt + 1 < NT) {
            float* Asn = smem + (cur ^ 1) * BK * BM;
            float* Bsn = smem + 2 * BK * BM + (cur ^ 1) * BK * BN;
            #pragma unroll
            for (int it = 0; it < N4A; it++) {
                int r = ar + it * 64;
                Asn[(akk + 0) * BM + r] = pa[it].x; Asn[(akk + 1) * BM + r] = pa[it].y;
                Asn[(akk + 2) * BM + r] = pa[it].z; Asn[(akk + 3) * BM + r] = pa[it].w;
            }
            #pragma unroll
            for (int it = 0; it < N4B; it++) {
                int cc = bcc + it * 64;
                *reinterpret_cast<float4*>(&Bsn[bkk * BN + cc]) = pb[it];
            }
        }
        __syncthreads();
    }

    float bb[TN];
    if (BIAS_RELU) {
        #pragma unroll
        for (int j = 0; j < TN; j++)
            bb[j] = bias[block_n + ((j < 4) ? (c0 + j) : (c1 + j - 4))];
    }
    float ps[TN], ps2[TN];
    #pragma unroll
    for (int j = 0; j < TN; j++) { ps[j] = 0.f; ps2[j] = 0.f; }

    #pragma unroll
    for (int i = 0; i < TM; i++) {
        float v[TN];
        #pragma unroll
        for (int j = 0; j < TN / 2; j++) {
            float2 u = unpack2(acc[i][j]);
            v[j * 2] = u.x; v[j * 2 + 1] = u.y;
        }
        #pragma unroll
        for (int j = 0; j < TN; j++) {
            if (BIAS_RELU) v[j] = fmaxf(v[j] + bb[j], 0.f);
            if (STATS) { ps[j] += v[j]; ps2[j] = fmaf(v[j], v[j], ps2[j]); }
        }
        int r = block_m + ty * TM + i;
        *reinterpret_cast<float4*>(&Cmat[(size_t)r * N + block_n + c0]) =
            make_float4(v[0], v[1], v[2], v[3]);
        if (TN == 8)
            *reinterpret_cast<float4*>(&Cmat[(size_t)r * N + block_n + c1]) =
                make_float4(v[4], v[5], v[6], v[7]);
    }

    if (STATS) {
        #pragma unroll
        for (int j = 0; j < TN; j++) {
            int col = (j < 4) ? (c0 + j) : (c1 + j - 4);
            smem[ty * BN + col]           = ps[j];
            smem[16 * BN + ty * BN + col] = ps2[j];
        }
        __syncthreads();
        if (t < BN) {
            float s = 0.f, s2 = 0.f;
            #pragma unroll
            for (int g = 0; g < 16; g++) { s += smem[g * BN + t]; s2 += smem[16 * BN + g * BN + t]; }
            atomicAdd(&g_sum[block_n + t],   (double)s);
            atomicAdd(&g_sumsq[block_n + t], (double)s2);
        }
    }
}

// ---------------------------------------------------------------------------
// Layer-1 edge GEMM: full A(128x64)+B(64x64) in smem, 2 barriers.
// ---------------------------------------------------------------------------
__global__ void __launch_bounds__(256, 2)
gemm_edge1(const float* __restrict__ PQ, const int* __restrict__ IDXp,
           const float* __restrict__ abias, const float* __restrict__ W,
           const float* __restrict__ obias, float* __restrict__ H) {
    __shared__ float As[64 * 128];
    __shared__ float Bs[64 * 64];
    __shared__ float s_ab[64];
    int t = threadIdx.x;
    int block_m = blockIdx.x * 128;
    if (t < 64) s_ab[t] = abias[t];
    #pragma unroll
    for (int i = 0; i < 4; i++)
        *reinterpret_cast<float4*>(&Bs[i * 1024 + t * 4]) =
            *reinterpret_cast<const float4*>(&W[i * 1024 + t * 4]);
    int r  = t >> 1;
    int co = (t & 1) * 32;
    {
        int e  = block_m + r;
        int bi = e / KNN;
        int qo = ((bi >> 10) << 10) + IDXp[e];
        const float* Pp = PQ + (size_t)bi * 128 + co;
        const float* Qp = PQ + (size_t)qo * 128 + 64 + co;
        float4 pv[8], qv[8];
        #pragma unroll
        for (int q = 0; q < 8; q++) {
            pv[q] = *reinterpret_cast<const float4*>(Pp + q * 4);
            qv[q] = *reinterpret_cast<const float4*>(Qp + q * 4);
        }
        __syncthreads();
        #pragma unroll
        for (int q = 0; q < 8; q++) {
            int c = co + q * 4;
            As[(c + 0) * 128 + r] = fmaxf(pv[q].x + qv[q].x + s_ab[c + 0], 0.f);
            As[(c + 1) * 128 + r] = fmaxf(pv[q].y + qv[q].y + s_ab[c + 1], 0.f);
            As[(c + 2) * 128 + r] = fmaxf(pv[q].z + qv[q].z + s_ab[c + 2], 0.f);
            As[(c + 3) * 128 + r] = fmaxf(pv[q].w + qv[q].w + s_ab[c + 3], 0.f);
        }
    }
    __syncthreads();

    int tx = t & 15, ty = t >> 4;
    ull acc[8][2];
    #pragma unroll
    for (int i = 0; i < 8; i++) { acc[i][0] = 0ull; acc[i][1] = 0ull; }

    #pragma unroll 16
    for (int kk = 0; kk < 64; kk++) {
        float4 a0 = *reinterpret_cast<const float4*>(&As[kk * 128 + ty * 8]);
        float4 a1 = *reinterpret_cast<const float4*>(&As[kk * 128 + ty * 8 + 4]);
        float4 b0 = *reinterpret_cast<const float4*>(&Bs[kk * 64 + tx * 4]);
        ull rb0 = pack2(b0.x, b0.y), rb1 = pack2(b0.z, b0.w);
        float ra[8] = {a0.x, a0.y, a0.z, a0.w, a1.x, a1.y, a1.z, a1.w};
        #pragma unroll
        for (int i = 0; i < 8; i++) {
            ull ai = pack2(ra[i], ra[i]);
            fma2(acc[i][0], ai, rb0);
            fma2(acc[i][1], ai, rb1);
        }
    }

    float ob[4];
    #pragma unroll
    for (int j = 0; j < 4; j++) ob[j] = obias[tx * 4 + j];
    float ps[4] = {0, 0, 0, 0}, ps2[4] = {0, 0, 0, 0};
    #pragma unroll
    for (int i = 0; i < 8; i++) {
        float2 u0 = unpack2(acc[i][0]), u1 = unpack2(acc[i][1]);
        float v[4] = {u0.x, u0.y, u1.x, u1.y};
        #pragma unroll
        for (int j = 0; j < 4; j++) {
            v[j] = fmaxf(v[j] + ob[j], 0.f);
            ps[j] += v[j]; ps2[j] = fmaf(v[j], v[j], ps2[j]);
        }
        int rr = block_m + ty * 8 + i;
        *reinterpret_cast<float4*>(&H[(size_t)rr * 64 + tx * 4]) =
            make_float4(v[0], v[1], v[2], v[3]);
    }
    __syncthreads();
    #pragma unroll
    for (int j = 0; j < 4; j++) {
        As[ty * 64 + tx * 4 + j]        = ps[j];
        As[1024 + ty * 64 + tx * 4 + j] = ps2[j];
    }
    __syncthreads();
    if (t < 64) {
        float s = 0.f, s2 = 0.f;
        #pragma unroll
        for (int g = 0; g < 16; g++) { s += As[g * 64 + t]; s2 += As[1024 + g * 64 + t]; }
        atomicAdd(&g_sum[t],   (double)s);
        atomicAdd(&g_sumsq[t], (double)s2);
    }
}

// ---------------------------------------------------------------------------
template <int CH>
__global__ void stats_edges_kernel(const float* __restrict__ PQ,
                                   const int* __restrict__ IDXp,
                                   const float* __restrict__ bias) {
    constexpr int G = 256 / CH;
    int c = threadIdx.x % CH;
    int g = threadIdx.x / CH;
    int stride = gridDim.x * G;
    float bb = bias[c];
    float s = 0.f, s2 = 0.f;
    for (int node = blockIdx.x * G + g; node < NROW; node += stride) {
        float p = PQ[(size_t)node * (2 * CH) + c] + bb;
        int base = (node >> 10) << 10;
        const int* ix = IDXp + node * KNN;
        #pragma unroll 5
        for (int kk = 0; kk < KNN; kk++) {
            int j = base + ix[kk];
            float v = fmaxf(p + PQ[(size_t)j * (2 * CH) + CH + c], 0.f);
            s += v; s2 = fmaf(v, v, s2);
        }
    }
    __shared__ float sh[2][256];
    sh[0][threadIdx.x] = s; sh[1][threadIdx.x] = s2;
    __syncthreads();
    if (g == 0) {
        #pragma unroll
        for (int gg = 1; gg < G; gg++) { s += sh[0][gg * CH + c]; s2 += sh[1][gg * CH + c]; }
        atomicAdd(&g_sum[c],   (double)s);
        atomicAdd(&g_sumsq[c], (double)s2);
    }
}

// ---------------------------------------------------------------------------
__global__ void stats_minmax_edges_kernel(const float* __restrict__ PQ2,
                                          const int* __restrict__ IDXp,
                                          const float* __restrict__ bias,
                                          float* __restrict__ vmax,
                                          float* __restrict__ vmin) {
    int c = threadIdx.x & 127;
    int g = threadIdx.x >> 7;
    int stride = gridDim.x * 2;
    float bb = bias[c];
    float s = 0.f, s2 = 0.f;
    for (int node = blockIdx.x * 2 + g; node < NROW; node += stride) {
        float p = PQ2[(size_t)node * 256 + c] + bb;
        int base = (node >> 10) << 10;
        const int* ix = IDXp + node * KNN;
        float mx = -3.4e38f, mn = 3.4e38f;
        #pragma unroll 5
        for (int kk = 0; kk < KNN; kk++) {
            int j = base + ix[kk];
            float v = fmaxf(p + PQ2[(size_t)j * 256 + 128 + c], 0.f);
            s += v; s2 = fmaf(v, v, s2);
            mx = fmaxf(mx, v); mn = fminf(mn, v);
        }
        vmax[(size_t)node * 128 + c] = mx;
        vmin[(size_t)node * 128 + c] = mn;
    }
    __shared__ float sh[2][256];
    sh[0][threadIdx.x] = s; sh[1][threadIdx.x] = s2;
    __syncthreads();
    if (g == 0) {
        s  += sh[0][128 + c];
        s2 += sh[1][128 + c];
        atomicAdd(&g_sum[c],   (double)s);
        atomicAdd(&g_sumsq[c], (double)s2);
    }
}

__global__ void apply_minmax_kernel(const float* __restrict__ vmax,
                                    const float* __restrict__ vmin,
                                    float* __restrict__ hcat) {
    int i = blockIdx.x * 256 + threadIdx.x;
    int c = i & 127, bi = i >> 7;
    float s = g_sc[c], cc = g_cc[c];
    float v = (s >= 0.f) ? vmax[i] : vmin[i];
    hcat[(size_t)bi * 192 + 64 + c] = fmaf(s, v, cc);
}

// ---------------------------------------------------------------------------
template <int CH>
__global__ void finalize_kernel(const float* __restrict__ gam,
                                const float* __restrict__ bet, int E) {
    int c = threadIdx.x;
    if (c < CH) {
        double mu  = g_sum[c] / (double)E;
        double var = g_sumsq[c] / (double)E - mu * mu;
        float s = gam[c] * rsqrtf((float)var + 1e-5f);
        g_sc[c] = s;
        g_cc[c] = bet[c] - (float)mu * s;
    }
    g_sum[c] = 0.0; g_sumsq[c] = 0.0;
}

__global__ void fold_kernel(const float* __restrict__ gam, const float* __restrict__ bet,
                            const float* __restrict__ W, const float* __restrict__ bias,
                            int E, float* __restrict__ Wf, float* __restrict__ bf) {
    __shared__ float s_s[64], s_c[64];
    int t = threadIdx.x;
    if (t < 64) {
        double mu  = g_sum[t] / (double)E;
        double var = g_sumsq[t] / (double)E - mu * mu;
        float s = gam[t] * rsqrtf((float)var + 1e-5f);
        s_s[t] = s;
        s_c[t] = bet[t] - (float)mu * s;
        g_sum[t] = 0.0; g_sumsq[t] = 0.0;
    } else if (t < 128) {
        g_sum[t] = 0.0; g_sumsq[t] = 0.0;
    }
    __syncthreads();
    for (int e = t; e < 64 * 64; e += 256) Wf[e] = s_s[e >> 6] * W[e];
    if (t < 64) {
        float acc = bias[t];
        #pragma unroll 4
        for (int kk = 0; kk < 64; kk++) acc = fmaf(s_c[kk], W[kk * 64 + t], acc);
        bf[t] = acc;
    }
}

// ---------------------------------------------------------------------------
__global__ void maxagg1_kernel(const float* __restrict__ H, float* __restrict__ hcat,
                               float* __restrict__ x1, float* __restrict__ sq) {
    int bi = blockIdx.x;
    int c  = threadIdx.x;
    const float* h = H + (size_t)bi * (KNN * 64) + c;
    float s = g_sc[c], cc = g_cc[c];
    float m = -3.4e38f;
    #pragma unroll
    for (int kk = 0; kk < KNN; kk++) m = fmaxf(m, fmaf(s, h[kk * 64], cc));
    hcat[(size_t)bi * 192 + c] = m;
    x1[(size_t)bi * 64 + c]    = m;
    float q = m * m;
    #pragma unroll
    for (int o = 16; o; o >>= 1) q += __shfl_xor_sync(0xffffffffu, q, o);
    __shared__ float sh[2];
    if ((c & 31) == 0) sh[c >> 5] = q;
    __syncthreads();
    if (c == 0) sq[bi] = sh[0] + sh[1];
}

__global__ void apply_bn_kernel(const float* __restrict__ Y, float* __restrict__ out) {
    int i = blockIdx.x * 256 + threadIdx.x;
    int c = i & 127;
    out[i] = fmaf(g_sc[c], Y[i], g_cc[c]);
}

// ---------------------------------------------------------------------------
extern "C" void kernel_launch(void* const* d_in, const int* in_sizes, int n_in,
                              void* d_out, int out_size) {
    const float* x0    = (const float*)d_in[1];
    const float* c1w0  = (const float*)d_in[2];
    const float* c1b0  = (const float*)d_in[3];
    const float* c1g0  = (const float*)d_in[4];
    const float* c1be0 = (const float*)d_in[5];
    const float* c1w1  = (const float*)d_in[6];
    const float* c1b1  = (const float*)d_in[7];
    const float* c1g1  = (const float*)d_in[8];
    const float* c1be1 = (const float*)d_in[9];
    const float* c1w2  = (const float*)d_in[10];
    const float* c1b2  = (const float*)d_in[11];
    const float* c1g2  = (const float*)d_in[12];
    const float* c1be2 = (const float*)d_in[13];
    const float* c2w0  = (const float*)d_in[14];
    const float* c2b0  = (const float*)d_in[15];
    const float* c2g0  = (const float*)d_in[16];
    const float* c2be0 = (const float*)d_in[17];
    const float* lw    = (const float*)d_in[18];
    const float* lb    = (const float*)d_in[19];
    const float* lg    = (const float*)d_in[20];
    const float* lbe   = (const float*)d_in[21];
    float* out = (float*)d_out;

    void* sp = nullptr; cudaGetSymbolAddress(&sp, g_scratch);
    float* S = (float*)sp;
    void* ip = nullptr; cudaGetSymbolAddress(&ip, g_knn_idx);
    int* IDX = (int*)ip;

    float* D     = S + OFF_D;
    float* PQ    = S + OFF_PQ;
    float* PQ2   = S + OFF_PQ2;
    float* H1    = S + OFF_H1;
    float* H2    = S + OFF_H2;
    float* HCAT  = S + OFF_HCAT;
    float* X1    = S + OFF_X1;
    float* Y0    = S + OFF_Y0;
    float* SQ    = S + OFF_SQ;
    float* WCAT  = S + OFF_WCAT;
    float* WCAT2 = S + OFF_WCAT2;
    float* WF    = S + OFF_WF;
    float* BF    = S + OFF_BF;
    float* VMAX  = S + OFF_H1;
    float* VMIN  = S + OFF_H1 + (size_t)NROW * 128;

    cudaStream_t s2;
    cudaStreamCreateWithFlags(&s2, cudaStreamNonBlocking);
    cudaEvent_t evFork1, evJoin1, evFork2, evJoin2;
    cudaEventCreateWithFlags(&evFork1, cudaEventDisableTiming);
    cudaEventCreateWithFlags(&evJoin1, cudaEventDisableTiming);
    cudaEventCreateWithFlags(&evFork2, cudaEventDisableTiming);
    cudaEventCreateWithFlags(&evJoin2, cudaEventDisableTiming);

    prep_kernel<<<192 + NROW / 8, 256>>>(c1w0, WCAT, c2w0, WCAT2, x0, SQ);

    // ---- EdgeConv 1: fork PQ1 gemm || dist1->topk1 ----
    cudaEventRecord(evFork1, 0);
    cudaStreamWaitEvent(s2, evFork1, 0);
    gemm_nodes<64, 64, 4, 4, false, false><<<dim3(2, NROW / 64), 256, 0, s2>>>(x0, WCAT, nullptr, PQ, NROW, 128, 256);
    cudaEventRecord(evJoin1, s2);

    dist_kernel<256><<<dim3(36, 1, 8), 256>>>(x0, SQ, D);
    topk_kernel<<<NROW / 8, 256>>>(D, IDX);
    cudaStreamWaitEvent(0, evJoin1, 0);

    stats_edges_kernel<64><<<512, 256>>>(PQ, IDX, c1b0);
    fold_kernel<<<1, 256>>>(c1g0, c1be0, c1w1, c1b1, NEDGE, WF, BF);
    gemm_edge1<<<NEDGE / 128, 256>>>(PQ, IDX, c1b0, WF, BF, H1);
    fold_kernel<<<1, 256>>>(c1g1, c1be1, c1w2, c1b2, NEDGE, WF, BF);
    gemm_nodes<128, 64, 8, 4, true, true><<<dim3(1, NEDGE / 128), 256>>>(H1, WF, BF, H2, NEDGE, 64, 64);
    finalize_kernel<64><<<1, 128>>>(c1g2, c1be2, NEDGE);
    maxagg1_kernel<<<NROW, 64>>>(H2, HCAT, X1, SQ);

    // ---- EdgeConv 2: fork PQ2 gemm || dist2->topk2 ----
    cudaEventRecord(evFork2, 0);
    cudaStreamWaitEvent(s2, evFork2, 0);
    gemm_nodes<64, 128, 4, 8, false, false><<<dim3(2, NROW / 64), 256, 0, s2>>>(X1, WCAT2, nullptr, PQ2, NROW, 256, 64);
    cudaEventRecord(evJoin2, s2);

    dist_kernel<64><<<dim3(36, 1, 8), 256>>>(X1, SQ, D);
    topk_kernel<<<NROW / 8, 256>>>(D, IDX);
    cudaStreamWaitEvent(0, evJoin2, 0);

    stats_minmax_edges_kernel<<<512, 256>>>(PQ2, IDX, c2b0, VMAX, VMIN);
    finalize_kernel<128><<<1, 128>>>(c2g0, c2be0, NEDGE);
    apply_minmax_kernel<<<NROW * 128 / 256, 256>>>(VMAX, VMIN, HCAT);

    // ---- Final Linear + BN ----
    gemm_nodes<64, 64, 4, 4, true, true><<<dim3(2, NROW / 64), 256>>>(HCAT, lw, lb, Y0, NROW, 128, 192);
    finalize_kernel<128><<<1, 128>>>(lg, lbe, NROW);
    apply_bn_kernel<<<NROW * 128 / 256, 256>>>(Y0, out);

    cudaEventDestroy(evFork1); cudaEventDestroy(evJoin1);
    cudaEventDestroy(evFork2); cudaEventDestroy(evJoin2);
    cudaStreamDestroy(s2);
}